// round 9
// baseline (speedup 1.0000x reference)
#include <cuda_runtime.h>
#include <cuda_fp16.h>
#include <cstdint>

// Problem constants
#define Bc 4
#define Tc 2048
#define Vc 512
#define Cc 512
#define Hc 4
#define Dc 128
#define NBc 128
#define MROWS (Bc*Tc)    // 8192
#define NCH 32
#define CHL 64

// fp32 scratch
__device__ float g_q[MROWS*Cc];
__device__ float g_k[MROWS*Cc];
__device__ float g_stA[(size_t)16*NCH*Dc*Dc];   // A^T per chunk

// fp16 split scratch (A-operands: hi/lo ; B-operands: single)
__device__ __half g_xh[MROWS*Cc],  g_xl[MROWS*Cc];
__device__ __half g_rh[MROWS*Cc],  g_rl[MROWS*Cc];
__device__ __half g_qnh[MROWS*Cc], g_qnl[MROWS*Cc];
__device__ __half g_knh[MROWS*Cc], g_knl[MROWS*Cc];
__device__ __half g_vsh[MROWS*Cc], g_vsl[MROWS*Cc];
__device__ __half g_wqTh[Cc*Vc];
__device__ __half g_wkTh[Cc*Vc];
__device__ __half g_vwTh[Cc*Vc];
__device__ __half g_owh[Vc*Cc];
__device__ __half g_sTh[(size_t)16*NCH*Dc*Dc];  // T^T single fp16 [bh][c][e][d]

// ===========================================================================
// Helpers
// ===========================================================================
__device__ __forceinline__ uint32_t smem_u32(const void* p) {
    uint32_t a;
    asm("{ .reg .u64 t; cvta.to.shared.u64 t, %1; cvt.u32.u64 %0, t; }"
        : "=r"(a) : "l"(p));
    return a;
}
__device__ __forceinline__ void ldm_x4(uint32_t* r, uint32_t addr) {
    asm volatile("ldmatrix.sync.aligned.m8n8.x4.shared.b16 {%0,%1,%2,%3}, [%4];"
                 : "=r"(r[0]), "=r"(r[1]), "=r"(r[2]), "=r"(r[3]) : "r"(addr));
}
__device__ __forceinline__ void mma_f16(float* c, const uint32_t* a,
                                        const uint32_t* b) {
    asm volatile(
        "mma.sync.aligned.m16n8k16.row.col.f32.f16.f16.f32 "
        "{%0,%1,%2,%3}, {%4,%5,%6,%7}, {%8,%9}, {%0,%1,%2,%3};"
        : "+f"(c[0]), "+f"(c[1]), "+f"(c[2]), "+f"(c[3])
        : "r"(a[0]), "r"(a[1]), "r"(a[2]), "r"(a[3]), "r"(b[0]), "r"(b[1]));
}
__device__ __forceinline__ void cp16(uint32_t dst, const void* src) {
    asm volatile("cp.async.cg.shared.global [%0], [%1], 16;"
                 :: "r"(dst), "l"(src));
}
__device__ __forceinline__ void cp_commit() {
    asm volatile("cp.async.commit_group;");
}
template <int N>
__device__ __forceinline__ void cp_wait() {
    asm volatile("cp.async.wait_group %0;" :: "n"(N));
}
__device__ __forceinline__ void split2(float v, __half& h, __half& l) {
    h = __float2half_rn(v);
    l = __float2half_rn(v - __half2float(h));
}

// ===========================================================================
// 2-pass split-fp16 warp-MMA GEMM (ROUND-7 CONFIG: K-slab 64, 2-stage).
// C[128,128] = A[M,512]@B[N,512]^T. A split hi/lo, B single.
// ===========================================================================
#define GSLAB 18432                 // 128 rows * 144B
#define GBUF  (3 * GSLAB)           // 55296 (A_h, A_l, B)
#define GS_BYTES (2 * GBUF)         // 110592

__device__ __forceinline__ void gemm_mma_tile(
    const __half* __restrict__ Ah, const __half* __restrict__ Al,
    const __half* __restrict__ Bh,
    float* __restrict__ Cp, __half* __restrict__ Oh, __half* __restrict__ Ol,
    float alpha, int tm, int tn)
{
    extern __shared__ __align__(16) char smc[];
    const int tid = threadIdx.x, lane = tid & 31, wid = tid >> 5;
    const int wm = wid >> 2, wn = wid & 3;
    const uint32_t sb = smem_u32(smc);

    float acc[4][4][4];
#pragma unroll
    for (int i = 0; i < 4; i++)
#pragma unroll
        for (int j = 0; j < 4; j++)
#pragma unroll
            for (int q = 0; q < 4; q++) acc[i][j][q] = 0.f;

    const __half* bases[3];
    bases[0] = Ah + ((size_t)tm * 128) * 512;
    bases[1] = Al + ((size_t)tm * 128) * 512;
    bases[2] = Bh + ((size_t)tn * 128) * 512;

    auto issue = [&](int c, int buf) {
        const uint32_t bb = sb + buf * GBUF;
#pragma unroll
        for (int s = 0; s < 3; s++) {
            const __half* src = bases[s] + c * 64;
#pragma unroll
            for (int i = 0; i < 4; i++) {
                const int idx = tid + 256 * i;
                const int row = idx >> 3, q = idx & 7;
                cp16(bb + s * GSLAB + row * 144 + q * 16,
                     src + (size_t)row * 512 + q * 8);
            }
        }
        cp_commit();
    };

    issue(0, 0);
    issue(1, 1);

    const uint32_t a_lrow = wm * 64 + (lane & 15);
    const uint32_t a_koff = (lane >> 4) * 8;
    const uint32_t b_lrow = wn * 32 + (lane & 7) + ((lane >> 4) << 3);
    const uint32_t b_koff = ((lane >> 3) & 1) * 8;

    for (int c = 0; c < 8; c++) {
        if (c == 7) cp_wait<0>(); else cp_wait<1>();
        __syncthreads();
        const uint32_t bb = sb + (c & 1) * GBUF;

#pragma unroll
        for (int ks = 0; ks < 4; ks++) {
            const int k0 = ks * 16;
            uint32_t bh[8];
#pragma unroll
            for (int nf = 0; nf < 2; nf++) {
                const uint32_t boff =
                    (b_lrow + nf * 16) * 144 + (k0 + b_koff) * 2;
                ldm_x4(bh + nf * 4, bb + 2 * GSLAB + boff);
            }
#pragma unroll
            for (int mi = 0; mi < 4; mi++) {
                const uint32_t aoff =
                    (a_lrow + mi * 16) * 144 + (k0 + a_koff) * 2;
                uint32_t ah[4], al[4];
                ldm_x4(ah, bb + 0 * GSLAB + aoff);
                ldm_x4(al, bb + 1 * GSLAB + aoff);
#pragma unroll
                for (int ni = 0; ni < 4; ni++) {
                    mma_f16(acc[mi][ni], ah, bh + ni * 2);
                    mma_f16(acc[mi][ni], al, bh + ni * 2);
                }
            }
        }
        __syncthreads();
        if (c + 2 < 8) issue(c + 2, c & 1);
    }

    const int qr = lane >> 2, qc = lane & 3;
#pragma unroll
    for (int mi = 0; mi < 4; mi++) {
#pragma unroll
        for (int ni = 0; ni < 4; ni++) {
            const int m = tm * 128 + wm * 64 + mi * 16 + qr;
            const int n = tn * 128 + wn * 32 + ni * 8 + qc * 2;
            float o0 = acc[mi][ni][0] * alpha, o1 = acc[mi][ni][1] * alpha;
            float o2 = acc[mi][ni][2] * alpha, o3 = acc[mi][ni][3] * alpha;
            if (Cp) {
                float2 v0, v1;
                v0.x = o0; v0.y = o1; v1.x = o2; v1.y = o3;
                *(float2*)(Cp + (size_t)m * 512 + n)       = v0;
                *(float2*)(Cp + (size_t)(m + 8) * 512 + n) = v1;
            } else {
                __half h0, l0, h1, l1, h2, l2, h3, l3;
                split2(o0, h0, l0); split2(o1, h1, l1);
                split2(o2, h2, l2); split2(o3, h3, l3);
                __half2 p;
                p.x = h0; p.y = h1;
                *(__half2*)(Oh + (size_t)m * 512 + n) = p;
                p.x = l0; p.y = l1;
                *(__half2*)(Ol + (size_t)m * 512 + n) = p;
                p.x = h2; p.y = h3;
                *(__half2*)(Oh + (size_t)(m + 8) * 512 + n) = p;
                p.x = l2; p.y = l3;
                *(__half2*)(Ol + (size_t)(m + 8) * 512 + n) = p;
            }
        }
    }
}

__global__ void __launch_bounds__(256) k_gemm_proj()
{
    if (blockIdx.z == 0)
        gemm_mma_tile(g_xh, g_xl, g_wqTh, g_q, nullptr, nullptr, 1.f,
                      blockIdx.y, blockIdx.x);
    else if (blockIdx.z == 1)
        gemm_mma_tile(g_xh, g_xl, g_wkTh, g_k, nullptr, nullptr, 1.f,
                      blockIdx.y, blockIdx.x);
    else
        gemm_mma_tile(g_xh, g_xl, g_vwTh, nullptr, g_vsh, g_vsl, 1.f,
                      blockIdx.y, blockIdx.x);
}

__global__ void __launch_bounds__(256) k_gemm_out(float* __restrict__ out,
                                                  const float* __restrict__ os)
{
    gemm_mma_tile(g_rh, g_rl, g_owh, out, nullptr, nullptr, __ldg(os),
                  blockIdx.y, blockIdx.x);
}

// ===========================================================================
// k_prep: fused independent prep work, 256 threads/block.
//  blocks [0, 4096)        : split x -> g_xh/g_xl
//  blocks [4096, 4608)     : transpose wq/wk -> single fp16 (256 tiles each)
//  blocks [4608, 4640)     : weights GEMMs -> g_vwTh (vc@basis^T), g_owh
// ===========================================================================
#define PREP_SPLIT_BLKS 4096
#define PREP_TR_BLKS    512
#define PREP_W_BLKS     32

__global__ void __launch_bounds__(256) k_prep(
    const float* __restrict__ x, const float* __restrict__ wq,
    const float* __restrict__ wk, const float* __restrict__ basis,
    const float* __restrict__ vc, const float* __restrict__ oc)
{
    __shared__ float shmem[8 * 132 * 2];   // max of transpose(32*33) / weights(2*8*132)
    const int blk = blockIdx.x;
    const int tid = threadIdx.x;

    if (blk < PREP_SPLIT_BLKS) {
        // ---- split x ----
        const int i = blk * 256 + tid;
        float4 v = ((const float4*)x)[i];
        __half h0, h1, h2, h3, l0, l1, l2, l3;
        split2(v.x, h0, l0); split2(v.y, h1, l1);
        split2(v.z, h2, l2); split2(v.w, h3, l3);
        __half2 p;
        p.x = h0; p.y = h1; ((__half2*)g_xh)[2 * i]     = p;
        p.x = h2; p.y = h3; ((__half2*)g_xh)[2 * i + 1] = p;
        p.x = l0; p.y = l1; ((__half2*)g_xl)[2 * i]     = p;
        p.x = l2; p.y = l3; ((__half2*)g_xl)[2 * i + 1] = p;
        return;
    }

    if (blk < PREP_SPLIT_BLKS + PREP_TR_BLKS) {
        // ---- transpose wq/wk tile 32x32 -> fp16 ----
        float (*t)[33] = (float(*)[33])shmem;
        const int tb = blk - PREP_SPLIT_BLKS;
        const int z = tb >> 8;                 // 0: wq, 1: wk
        const int tile = tb & 255;
        const int bx = tile & 15, by = tile >> 4;
        const float* in = z ? wk : wq;
        __half* oh = z ? g_wkTh : g_wqTh;
        const int i = tid & 31, ty = tid >> 5;     // 32 cols x 8 rows
#pragma unroll
        for (int r = 0; r < 4; r++) {
            const int j = ty + 8 * r;
            t[j][i] = in[(size_t)(by * 32 + j) * 512 + bx * 32 + i];
        }
        __syncthreads();
#pragma unroll
        for (int r = 0; r < 4; r++) {
            const int a = ty + 8 * r;
            // out[bx*32+a][by*32+i] = in[by*32+i][bx*32+a]
            oh[(size_t)(bx * 32 + a) * 512 + by * 32 + i] =
                __float2half_rn(t[i][a]);
        }
        return;
    }

    // ---- weights GEMMs ----
    {
        float (*As)[132] = (float(*)[132])shmem;
        float (*Bs)[132] = (float(*)[132])(shmem + 8 * 132);
        const int wb = blk - PREP_SPLIT_BLKS - PREP_TR_BLKS;
        const int z = wb >> 4;                 // 0: vwT, 1: ow
        const int bx = wb & 3, by = (wb >> 2) & 3;
        const float* A = z ? basis : vc;
        const float* B = z ? oc : basis;
        __half* Oh = z ? g_owh : g_vwTh;
        const int tx = tid & 15, ty = tid >> 4;

        float acc[8][8];
#pragma unroll
        for (int i = 0; i < 8; i++)
#pragma unroll
            for (int j = 0; j < 8; j++) acc[i][j] = 0.f;

        const float* Ab = A + (size_t)(by * 128) * NBc;

        for (int k0 = 0; k0 < NBc; k0 += 8) {
            {
                const int ar = tid >> 1, ac = (tid & 1) * 4;
                float4 v = *(const float4*)(Ab + (size_t)ar * NBc + k0 + ac);
                As[ac + 0][ar] = v.x; As[ac + 1][ar] = v.y;
                As[ac + 2][ar] = v.z; As[ac + 3][ar] = v.w;
            }
            {
                const int br = tid >> 1, bc = (tid & 1) * 4;
                float4 v = *(const float4*)(B + (size_t)(bx * 128 + br) * NBc + k0 + bc);
                Bs[bc + 0][br] = v.x; Bs[bc + 1][br] = v.y;
                Bs[bc + 2][br] = v.z; Bs[bc + 3][br] = v.w;
            }
            __syncthreads();

#pragma unroll
            for (int kk = 0; kk < 8; kk++) {
                float a[8], bf[8];
                *(float4*)(a)     = *(const float4*)&As[kk][ty * 8];
                *(float4*)(a + 4) = *(const float4*)&As[kk][ty * 8 + 4];
                *(float4*)(bf)     = *(const float4*)&Bs[kk][tx * 8];
                *(float4*)(bf + 4) = *(const float4*)&Bs[kk][tx * 8 + 4];
#pragma unroll
                for (int i = 0; i < 8; i++)
#pragma unroll
                    for (int j = 0; j < 8; j++) acc[i][j] += a[i] * bf[j];
            }
            __syncthreads();
        }

#pragma unroll
        for (int i = 0; i < 8; i++) {
            const size_t rowb =
                (size_t)(by * 128 + ty * 8 + i) * 512 + bx * 128 + tx * 8;
#pragma unroll
            for (int j = 0; j < 8; j += 2) {
                __half2 p;
                p.x = __float2half_rn(acc[i][j]);
                p.y = __float2half_rn(acc[i][j + 1]);
                *(__half2*)(Oh + rowb + j) = p;
            }
        }
    }
}

// L2-normalize rows of g_q/g_k, write fp16 splits
__global__ void __launch_bounds__(256) k_norm()
{
    const int row = blockIdx.x;
    const float* q = g_q + (size_t)row * Cc;
    const float* k = g_k + (size_t)row * Cc;
    const int t = threadIdx.x;
    float q0 = q[t], q1 = q[t + 256];
    float k0 = k[t], k1 = k[t + 256];
    float sq = q0 * q0 + q1 * q1;
    float sk = k0 * k0 + k1 * k1;
#pragma unroll
    for (int off = 16; off; off >>= 1) {
        sq += __shfl_xor_sync(0xffffffffu, sq, off);
        sk += __shfl_xor_sync(0xffffffffu, sk, off);
    }
    __shared__ float rq[8], rk[8];
    __shared__ float inv[2];
    const int w = t >> 5, l = t & 31;
    if (l == 0) { rq[w] = sq; rk[w] = sk; }
    __syncthreads();
    if (t == 0) {
        float a = 0.f, cc = 0.f;
#pragma unroll
        for (int i = 0; i < 8; i++) { a += rq[i]; cc += rk[i]; }
        inv[0] = 1.f / fmaxf(sqrtf(a), 1e-12f);
        inv[1] = 1.f / fmaxf(sqrtf(cc), 1e-12f);
    }
    __syncthreads();
    const float iq = inv[0], ik = inv[1];
    __half h, lo;
    const size_t b = (size_t)row * Cc;
    split2(q0 * iq, h, lo); g_qnh[b + t] = h;       g_qnl[b + t] = lo;
    split2(q1 * iq, h, lo); g_qnh[b + t + 256] = h; g_qnl[b + t + 256] = lo;
    split2(k0 * ik, h, lo); g_knh[b + t] = h;       g_knl[b + t] = lo;
    split2(k1 * ik, h, lo); g_knh[b + t + 256] = h; g_knl[b + t + 256] = lo;
}

// ===========================================================================
// Phase A (MMA): A^T_c[e][d] = sum_j V[j][e] * (d^j K[j][d])
// ===========================================================================
#define ST_K  0
#define ST_VH 18432
#define ST_VL 36864
#define STATE_SMEM 55296

__global__ void __launch_bounds__(256) k_state(const float* __restrict__ dlog)
{
    extern __shared__ __align__(16) char sm[];
    const int c = blockIdx.x + 1, h = blockIdx.y, b = blockIdx.z;
    const int tid = threadIdx.x, lane = tid & 31, wid = tid >> 5;
    const float dec = 1.f / (1.f + expf(-dlog[h]));
    const float l2d = log2f(dec);
    const size_t gb = ((size_t)b * Tc + c * CHL) * Cc + h * Dc;

#pragma unroll
    for (int i = 0; i < 32; i++) {
        const int idx = tid + 256 * i;
        const int d = idx & 127, j = idx >> 7;
        const float kv = __half2float(g_knh[gb + (size_t)j * Cc + d]) +
                         __half2float(g_knl[gb + (size_t)j * Cc + d]);
        *(__half*)(sm + ST_K + d * 144 + j * 2) =
            __float2half_rn(kv * exp2f(l2d * (float)j));
        *(__half*)(sm + ST_VH + d * 144 + j * 2) =
            g_vsh[gb + (size_t)j * Cc + d];
        *(__half*)(sm + ST_VL + d * 144 + j * 2) =
            g_vsl[gb + (size_t)j * Cc + d];
    }
    __syncthreads();

    const int wm = wid >> 2, wn = wid & 3;
    const uint32_t sb = smem_u32(sm);
    const uint32_t a_lrow = wm * 64 + (lane & 15);
    const uint32_t a_koff = (lane >> 4) * 8;
    const uint32_t b_lrow = wn * 32 + (lane & 7) + ((lane >> 4) << 3);
    const uint32_t b_koff = ((lane >> 3) & 1) * 8;

    float acc[4][4][4];
#pragma unroll
    for (int i = 0; i < 4; i++)
#pragma unroll
        for (int j = 0; j < 4; j++)
#pragma unroll
            for (int q = 0; q < 4; q++) acc[i][j][q] = 0.f;

#pragma unroll
    for (int ks = 0; ks < 4; ks++) {
        const int k0 = ks * 16;
        uint32_t kh[8];
#pragma unroll
        for (int nf = 0; nf < 2; nf++) {
            const uint32_t boff = (b_lrow + nf * 16) * 144 + (k0 + b_koff) * 2;
            ldm_x4(kh + nf * 4, sb + ST_K + boff);
        }
#pragma unroll
        for (int mi = 0; mi < 4; mi++) {
            uint32_t vh[4], vl[4];
            const uint32_t aoff = (a_lrow + mi * 16) * 144 + (k0 + a_koff) * 2;
            ldm_x4(vh, sb + ST_VH + aoff);
            ldm_x4(vl, sb + ST_VL + aoff);
#pragma unroll
            for (int ni = 0; ni < 4; ni++) {
                mma_f16(acc[mi][ni], vh, kh + ni * 2);
                mma_f16(acc[mi][ni], vl, kh + ni * 2);
            }
        }
    }

    float* dst = g_stA + ((size_t)(b * Hc + h) * NCH + c) * (Dc * Dc);
    const int qr = lane >> 2, qc = lane & 3;
#pragma unroll
    for (int mi = 0; mi < 4; mi++) {
#pragma unroll
        for (int ni = 0; ni < 4; ni++) {
            const int m = wm * 64 + mi * 16 + qr;
            const int n = wn * 32 + ni * 8 + qc * 2;
            float2 v0, v1;
            v0.x = acc[mi][ni][0]; v0.y = acc[mi][ni][1];
            v1.x = acc[mi][ni][2]; v1.y = acc[mi][ni][3];
            *(float2*)(dst + (size_t)m * Dc + n)       = v0;
            *(float2*)(dst + (size_t)(m + 8) * Dc + n) = v1;
        }
    }
}

// ===========================================================================
// Phase B: backward scan on A^T, writes single-fp16 T^T.
// ===========================================================================
__global__ void __launch_bounds__(256) k_scan(const float* __restrict__ dlog)
{
    const int bh = blockIdx.x;
    const int h = bh & (Hc - 1);
    const int idx4 = blockIdx.y * 256 + threadIdx.x;   // 0..4095
    const float dec = 1.f / (1.f + expf(-dlog[h]));
    const float dL = exp2f(log2f(dec) * (float)CHL);

    float4 run = make_float4(0.f, 0.f, 0.f, 0.f);
    for (int c = NCH - 2; c >= 0; c--) {
        const float4* A =
            (const float4*)(g_stA + ((size_t)bh * NCH + c + 1) * (Dc * Dc));
        float4 a = A[idx4];
        run.x = a.x + dL * run.x;
        run.y = a.y + dL * run.y;
        run.z = a.z + dL * run.z;
        run.w = a.w + dL * run.w;
        const size_t o = ((size_t)bh * NCH + c) * (Dc * Dc) + (size_t)idx4 * 4;
        __half2 p;
        p.x = __float2half_rn(run.x); p.y = __float2half_rn(run.y);
        *(__half2*)(g_sTh + o) = p;
        p.x = __float2half_rn(run.z); p.y = __float2half_rn(run.w);
        *(__half2*)(g_sTh + o + 2) = p;
    }
}

// ===========================================================================
// Phase C (MMA): intra masked attention + inter Q@T^T. S single fp16.
// ===========================================================================
#define CQ_H 0
#define CQ_L 17408
#define CK   34816
#define CV   52224
#define CS   70656
#define CT   79872
#define CATTN_SMEM 114688

__global__ void __launch_bounds__(256) k_cattn(const float* __restrict__ dlog)
{
    extern __shared__ __align__(16) char sm[];
    const int c = blockIdx.x, h = blockIdx.y, b = blockIdx.z;
    const int tid = threadIdx.x, lane = tid & 31, wid = tid >> 5;
    const int wm = wid >> 2, wn = wid & 3;
    const float dec = 1.f / (1.f + expf(-dlog[h]));
    const float l2d = log2f(dec);
    const size_t gb = ((size_t)b * Tc + c * CHL) * Cc + h * Dc;
    const uint32_t sb = smem_u32(sm);

    // Prefetch full T^T (single fp16) with cp.async
    if (c < NCH - 1) {
        const __half* Th = g_sTh + ((size_t)(b * Hc + h) * NCH + c) * (Dc * Dc);
#pragma unroll
        for (int i = 0; i < 8; i++) {
            const int idx = tid + 256 * i;           // 0..2047
            const int e = idx >> 4, q = idx & 15;
            cp16(sb + CT + e * 272 + q * 16, Th + (size_t)e * 128 + q * 8);
        }
    }
    cp_commit();

    // Q hi/lo, K single tiles 64x128 pitch 272B
    {
        const uint4* s0 = (const uint4*)(g_qnh + gb);
        const uint4* s1 = (const uint4*)(g_qnl + gb);
        const uint4* s2 = (const uint4*)(g_knh + gb);
#pragma unroll
        for (int i = 0; i < 4; i++) {
            const int idx = tid + 256 * i;
            const int row = idx >> 4, q = idx & 15;
            const size_t so = (size_t)row * 64 + q;
            const uint32_t doff = row * 272 + q * 16;
            *(uint4*)(sm + CQ_H + doff) = s0[so];
            *(uint4*)(sm + CQ_L + doff) = s1[so];
            *(uint4*)(sm + CK   + doff) = s2[so];
        }
    }
    // Transposed V (single): VT[d][j] pitch 144B
#pragma unroll
    for (int i = 0; i < 32; i++) {
        const int idx = tid + 256 * i;
        const int d = idx & 127, j = idx >> 7;
        *(__half*)(sm + CV + d * 144 + j * 2) = g_vsh[gb + (size_t)j * Cc + d];
    }
    __syncthreads();

    const uint32_t a_koff = (lane >> 4) * 8;
    const uint32_t b_koff = ((lane >> 3) & 1) * 8;
    const uint32_t aQ_row = wm * 32 + (lane & 15);
    const uint32_t bS_row = wn * 16 + (lane & 7) + ((lane >> 4) << 3);
    const uint32_t bO_row = wn * 32 + (lane & 7) + ((lane >> 4) << 3);
    const int qr = lane >> 2, qc = lane & 3;

    // ---- intra: S = Q K^T (Q hi/lo x K single) ----
    float accS[2][2][4];
#pragma unroll
    for (int i = 0; i < 2; i++)
#pragma unroll
        for (int j = 0; j < 2; j++)
#pragma unroll
            for (int q = 0; q < 4; q++) accS[i][j][q] = 0.f;

#pragma unroll
    for (int ks = 0; ks < 8; ks++) {
        const int k0 = ks * 16;
        uint32_t kh[4];
        const uint32_t boff = bS_row * 272 + (k0 + b_koff) * 2;
        ldm_x4(kh, sb + CK + boff);
#pragma unroll
        for (int mi = 0; mi < 2; mi++) {
            uint32_t qh[4], ql[4];
            const uint32_t aoff = (aQ_row + mi * 16) * 272 + (k0 + a_koff) * 2;
            ldm_x4(qh, sb + CQ_H + aoff);
            ldm_x4(ql, sb + CQ_L + aoff);
#pragma unroll
            for (int ni = 0; ni < 2; ni++) {
                mma_f16(accS[mi][ni], qh, kh + ni * 2);
                mma_f16(accS[mi][ni], ql, kh + ni * 2);
            }
        }
    }

    // mask + store S (single fp16)
#pragma unroll
    for (int mi = 0; mi < 2; mi++) {
#pragma unroll
        for (int ni = 0; ni < 2; ni++) {
#pragma unroll
            for (int q = 0; q < 4; q++) {
                const int il = wm * 32 + mi * 16 + qr + (q >> 1) * 8;
                const int jl = wn * 16 + ni * 8 + qc * 2 + (q & 1);
                float s = 0.f;
                if (jl > il)
                    s = accS[mi][ni][q] * exp2f(l2d * (float)(jl - il - 1));
                *(__half*)(sm + CS + il * 144 + jl * 2) = __float2half_rn(s);
            }
        }
    }
    cp_wait<0>();
    __syncthreads();

    // ---- O accumulators ----
    float acc[2][4][4], accI[2][4][4];
#pragma unroll
    for (int i = 0; i < 2; i++)
#pragma unroll
        for (int j = 0; j < 4; j++)
#pragma unroll
            for (int q = 0; q < 4; q++) { acc[i][j][q] = 0.f; accI[i][j][q] = 0.f; }

    // intra SV: S single x V single (1 pass), K=64
#pragma unroll
    for (int ks = 0; ks < 4; ks++) {
        const int k0 = ks * 16;
        uint32_t vh[8];
#pragma unroll
        for (int nf = 0; nf < 2; nf++) {
            const uint32_t boff = (bO_row + nf * 16) * 144 + (k0 + b_koff) * 2;
            ldm_x4(vh + nf * 4, sb + CV + boff);
        }
#pragma unroll
        for (int mi = 0; mi < 2; mi++) {
            uint32_t sh[4];
            const uint32_t aoff = (aQ_row + mi * 16) * 144 + (k0 + a_koff) * 2;
            ldm_x4(sh, sb + CS + aoff);
#pragma unroll
            for (int ni = 0; ni < 4; ni++)
                mma_f16(acc[mi][ni], sh, vh + ni * 2);
        }
    }

    // inter: O_i += Q @ T^T (Q hi/lo x T single), K=128
    if (c < NCH - 1) {
#pragma unroll
        for (int ks = 0; ks < 8; ks++) {
            const int k0 = ks * 16;
            uint32_t th[8];
#pragma unroll
            for (int nf = 0; nf < 2; nf++) {
                const uint32_t boff =
                    (bO_row + nf * 16) * 272 + (k0 + b_koff) * 2;
                ldm_x4(th + nf * 4, sb + CT + boff);
            }
#pragma unroll
            for (int mi = 0; mi < 2; mi++) {
                uint32_t qh[4], ql[4];
                const uint32_t aoff =
                    (aQ_row + mi * 16) * 272 + (k0 + a_koff) * 2;
                ldm_x4(qh, sb + CQ_H + aoff);
                ldm_x4(ql, sb + CQ_L + aoff);
#pragma unroll
                for (int ni = 0; ni < 4; ni++) {
                    mma_f16(accI[mi][ni], qh, th + ni * 2);
                    mma_f16(accI[mi][ni], ql, th + ni * 2);
                }
            }
        }
    }

    // epilogue: O = acc + f(row) * accI -> fp16 split write g_rh/g_rl
#pragma unroll
    for (int mi = 0; mi < 2; mi++) {
        const int r0 = wm * 32 + mi * 16 + qr;
        const float f0 = exp2f(l2d * (float)(63 - r0));
        const float f1 = exp2f(l2d * (float)(63 - (r0 + 8)));
#pragma unroll
        for (int ni = 0; ni < 4; ni++) {
            const int col = wn * 32 + ni * 8 + qc * 2;
            const size_t a0 = gb + (size_t)r0 * Cc + col;
            const size_t a1 = gb + (size_t)(r0 + 8) * Cc + col;
            float o0 = acc[mi][ni][0] + f0 * accI[mi][ni][0];
            float o1 = acc[mi][ni][1] + f0 * accI[mi][ni][1];
            float o2 = acc[mi][ni][2] + f1 * accI[mi][ni][2];
            float o3 = acc[mi][ni][3] + f1 * accI[mi][ni][3];
            __half h0, l0, h1, l1, h2, l2, h3, l3;
            split2(o0, h0, l0); split2(o1, h1, l1);
            split2(o2, h2, l2); split2(o3, h3, l3);
            __half2 p;
            p.x = h0; p.y = h1; *(__half2*)(g_rh + a0) = p;
            p.x = l0; p.y = l1; *(__half2*)(g_rl + a0) = p;
            p.x = h2; p.y = h3; *(__half2*)(g_rh + a1) = p;
            p.x = l2; p.y = l3; *(__half2*)(g_rl + a1) = p;
        }
    }
}

extern "C" void kernel_launch(void* const* d_in, const int* in_sizes, int n_in,
                              void* d_out, int out_size)
{
    const float* x     = (const float*)d_in[0];
    const float* basis = (const float*)d_in[1];
    const float* wq    = (const float*)d_in[2];
    const float* wk    = (const float*)d_in[3];
    const float* vc    = (const float*)d_in[4];
    const float* oc    = (const float*)d_in[5];
    const float* dlog  = (const float*)d_in[6];
    const float* oscal = (const float*)d_in[7];
    float* out = (float*)d_out;

    (void)in_sizes; (void)n_in; (void)out_size;

    cudaFuncSetAttribute(k_state, cudaFuncAttributeMaxDynamicSharedMemorySize,
                         STATE_SMEM);
    cudaFuncSetAttribute(k_cattn, cudaFuncAttributeMaxDynamicSharedMemorySize,
                         CATTN_SMEM);
    cudaFuncSetAttribute(k_gemm_proj, cudaFuncAttributeMaxDynamicSharedMemorySize,
                         GS_BYTES);
    cudaFuncSetAttribute(k_gemm_out, cudaFuncAttributeMaxDynamicSharedMemorySize,
                         GS_BYTES);

    k_prep<<<PREP_SPLIT_BLKS + PREP_TR_BLKS + PREP_W_BLKS, 256>>>(
        x, wq, wk, basis, vc, oc);

    k_gemm_proj<<<dim3(Cc / 128, MROWS / 128, 3), 256, GS_BYTES>>>();
    k_norm<<<MROWS, 256>>>();

    k_state<<<dim3(NCH - 1, Hc, Bc), 256, STATE_SMEM>>>(dlog);
    k_scan<<<dim3(16, 16), 256>>>(dlog);
    k_cattn<<<dim3(NCH, Hc, Bc), 256, CATTN_SMEM>>>(dlog);

    k_gemm_out<<<dim3(Vc / 128, MROWS / 128), 256, GS_BYTES>>>(out, oscal);
}

// round 10
// speedup vs baseline: 1.0471x; 1.0471x over previous
#include <cuda_runtime.h>
#include <cuda_fp16.h>
#include <cstdint>

// Problem constants
#define Bc 4
#define Tc 2048
#define Vc 512
#define Cc 512
#define Hc 4
#define Dc 128
#define NBc 128
#define MROWS (Bc*Tc)    // 8192
#define NCH 32
#define CHL 64

// fp32 scratch
__device__ float g_q[MROWS*Cc];
__device__ float g_k[MROWS*Cc];
__device__ float g_stA[(size_t)16*NCH*Dc*Dc];   // A^T per chunk

// fp16 split scratch (A-operands: hi/lo ; B-operands: single)
__device__ __half g_xh[MROWS*Cc],  g_xl[MROWS*Cc];
__device__ __half g_rh[MROWS*Cc],  g_rl[MROWS*Cc];
__device__ __half g_qnh[MROWS*Cc], g_qnl[MROWS*Cc];
__device__ __half g_knh[MROWS*Cc], g_knl[MROWS*Cc];
__device__ __half g_vsh[MROWS*Cc], g_vsl[MROWS*Cc];
__device__ __half g_wqTh[Cc*Vc];
__device__ __half g_wkTh[Cc*Vc];
__device__ __half g_vwTh[Cc*Vc];
__device__ __half g_owh[Vc*Cc];
__device__ __half g_sTh[(size_t)16*NCH*Dc*Dc];  // T^T single fp16 [bh][c][e][d]

// ===========================================================================
// Helpers
// ===========================================================================
__device__ __forceinline__ uint32_t smem_u32(const void* p) {
    uint32_t a;
    asm("{ .reg .u64 t; cvta.to.shared.u64 t, %1; cvt.u32.u64 %0, t; }"
        : "=r"(a) : "l"(p));
    return a;
}
__device__ __forceinline__ void ldm_x4(uint32_t* r, uint32_t addr) {
    asm volatile("ldmatrix.sync.aligned.m8n8.x4.shared.b16 {%0,%1,%2,%3}, [%4];"
                 : "=r"(r[0]), "=r"(r[1]), "=r"(r[2]), "=r"(r[3]) : "r"(addr));
}
__device__ __forceinline__ void mma_f16(float* c, const uint32_t* a,
                                        const uint32_t* b) {
    asm volatile(
        "mma.sync.aligned.m16n8k16.row.col.f32.f16.f16.f32 "
        "{%0,%1,%2,%3}, {%4,%5,%6,%7}, {%8,%9}, {%0,%1,%2,%3};"
        : "+f"(c[0]), "+f"(c[1]), "+f"(c[2]), "+f"(c[3])
        : "r"(a[0]), "r"(a[1]), "r"(a[2]), "r"(a[3]), "r"(b[0]), "r"(b[1]));
}
__device__ __forceinline__ void cp16(uint32_t dst, const void* src) {
    asm volatile("cp.async.cg.shared.global [%0], [%1], 16;"
                 :: "r"(dst), "l"(src));
}
__device__ __forceinline__ void cp_commit() {
    asm volatile("cp.async.commit_group;");
}
template <int N>
__device__ __forceinline__ void cp_wait() {
    asm volatile("cp.async.wait_group %0;" :: "n"(N));
}
__device__ __forceinline__ void split2(float v, __half& h, __half& l) {
    h = __float2half_rn(v);
    l = __float2half_rn(v - __half2float(h));
}

// ===========================================================================
// 2-pass split-fp16 warp-MMA GEMM (round-7 config: K-slab 64, 2-stage).
// C[128,128] = A[M,512]@B[N,512]^T. A split hi/lo, B single.
// ===========================================================================
#define GSLAB 18432                 // 128 rows * 144B
#define GBUF  (3 * GSLAB)           // 55296 (A_h, A_l, B)
#define GS_BYTES (2 * GBUF)         // 110592

__device__ __forceinline__ void gemm_mma_tile(
    const __half* __restrict__ Ah, const __half* __restrict__ Al,
    const __half* __restrict__ Bh,
    float* __restrict__ Cp, __half* __restrict__ Oh, __half* __restrict__ Ol,
    float alpha, int tm, int tn)
{
    extern __shared__ __align__(16) char smc[];
    const int tid = threadIdx.x, lane = tid & 31, wid = tid >> 5;
    const int wm = wid >> 2, wn = wid & 3;
    const uint32_t sb = smem_u32(smc);

    float acc[4][4][4];
#pragma unroll
    for (int i = 0; i < 4; i++)
#pragma unroll
        for (int j = 0; j < 4; j++)
#pragma unroll
            for (int q = 0; q < 4; q++) acc[i][j][q] = 0.f;

    const __half* bases[3];
    bases[0] = Ah + ((size_t)tm * 128) * 512;
    bases[1] = Al + ((size_t)tm * 128) * 512;
    bases[2] = Bh + ((size_t)tn * 128) * 512;

    auto issue = [&](int c, int buf) {
        const uint32_t bb = sb + buf * GBUF;
#pragma unroll
        for (int s = 0; s < 3; s++) {
            const __half* src = bases[s] + c * 64;
#pragma unroll
            for (int i = 0; i < 4; i++) {
                const int idx = tid + 256 * i;
                const int row = idx >> 3, q = idx & 7;
                cp16(bb + s * GSLAB + row * 144 + q * 16,
                     src + (size_t)row * 512 + q * 8);
            }
        }
        cp_commit();
    };

    issue(0, 0);
    issue(1, 1);

    const uint32_t a_lrow = wm * 64 + (lane & 15);
    const uint32_t a_koff = (lane >> 4) * 8;
    const uint32_t b_lrow = wn * 32 + (lane & 7) + ((lane >> 4) << 3);
    const uint32_t b_koff = ((lane >> 3) & 1) * 8;

    for (int c = 0; c < 8; c++) {
        if (c == 7) cp_wait<0>(); else cp_wait<1>();
        __syncthreads();
        const uint32_t bb = sb + (c & 1) * GBUF;

#pragma unroll
        for (int ks = 0; ks < 4; ks++) {
            const int k0 = ks * 16;
            uint32_t bh[8];
#pragma unroll
            for (int nf = 0; nf < 2; nf++) {
                const uint32_t boff =
                    (b_lrow + nf * 16) * 144 + (k0 + b_koff) * 2;
                ldm_x4(bh + nf * 4, bb + 2 * GSLAB + boff);
            }
#pragma unroll
            for (int mi = 0; mi < 4; mi++) {
                const uint32_t aoff =
                    (a_lrow + mi * 16) * 144 + (k0 + a_koff) * 2;
                uint32_t ah[4], al[4];
                ldm_x4(ah, bb + 0 * GSLAB + aoff);
                ldm_x4(al, bb + 1 * GSLAB + aoff);
#pragma unroll
                for (int ni = 0; ni < 4; ni++) {
                    mma_f16(acc[mi][ni], ah, bh + ni * 2);
                    mma_f16(acc[mi][ni], al, bh + ni * 2);
                }
            }
        }
        __syncthreads();
        if (c + 2 < 8) issue(c + 2, c & 1);
    }

    const int qr = lane >> 2, qc = lane & 3;
#pragma unroll
    for (int mi = 0; mi < 4; mi++) {
#pragma unroll
        for (int ni = 0; ni < 4; ni++) {
            const int m = tm * 128 + wm * 64 + mi * 16 + qr;
            const int n = tn * 128 + wn * 32 + ni * 8 + qc * 2;
            float o0 = acc[mi][ni][0] * alpha, o1 = acc[mi][ni][1] * alpha;
            float o2 = acc[mi][ni][2] * alpha, o3 = acc[mi][ni][3] * alpha;
            if (Cp) {
                float2 v0, v1;
                v0.x = o0; v0.y = o1; v1.x = o2; v1.y = o3;
                *(float2*)(Cp + (size_t)m * 512 + n)       = v0;
                *(float2*)(Cp + (size_t)(m + 8) * 512 + n) = v1;
            } else {
                __half h0, l0, h1, l1, h2, l2, h3, l3;
                split2(o0, h0, l0); split2(o1, h1, l1);
                split2(o2, h2, l2); split2(o3, h3, l3);
                __half2 p;
                p.x = h0; p.y = h1;
                *(__half2*)(Oh + (size_t)m * 512 + n) = p;
                p.x = l0; p.y = l1;
                *(__half2*)(Ol + (size_t)m * 512 + n) = p;
                p.x = h2; p.y = h3;
                *(__half2*)(Oh + (size_t)(m + 8) * 512 + n) = p;
                p.x = l2; p.y = l3;
                *(__half2*)(Ol + (size_t)(m + 8) * 512 + n) = p;
            }
        }
    }
}

__global__ void __launch_bounds__(256) k_gemm_proj()
{
    if (blockIdx.z == 0)
        gemm_mma_tile(g_xh, g_xl, g_wqTh, g_q, nullptr, nullptr, 1.f,
                      blockIdx.y, blockIdx.x);
    else if (blockIdx.z == 1)
        gemm_mma_tile(g_xh, g_xl, g_wkTh, g_k, nullptr, nullptr, 1.f,
                      blockIdx.y, blockIdx.x);
    else
        gemm_mma_tile(g_xh, g_xl, g_vwTh, nullptr, g_vsh, g_vsl, 1.f,
                      blockIdx.y, blockIdx.x);
}

__global__ void __launch_bounds__(256) k_gemm_out(float* __restrict__ out,
                                                  const float* __restrict__ os)
{
    gemm_mma_tile(g_rh, g_rl, g_owh, out, nullptr, nullptr, __ldg(os),
                  blockIdx.y, blockIdx.x);
}

// ===========================================================================
// Split x -> fp16 hi/lo
// ===========================================================================
__global__ void __launch_bounds__(256) k_split(const float* __restrict__ in)
{
    int i = blockIdx.x * 256 + threadIdx.x;
    float4 v = ((const float4*)in)[i];
    __half h0, h1, h2, h3, l0, l1, l2, l3;
    split2(v.x, h0, l0); split2(v.y, h1, l1);
    split2(v.z, h2, l2); split2(v.w, h3, l3);
    __half2 p;
    p.x = h0; p.y = h1; ((__half2*)g_xh)[2 * i]     = p;
    p.x = h2; p.y = h3; ((__half2*)g_xh)[2 * i + 1] = p;
    p.x = l0; p.y = l1; ((__half2*)g_xl)[2 * i]     = p;
    p.x = l2; p.y = l3; ((__half2*)g_xl)[2 * i + 1] = p;
}

// Transpose 512x512 weights -> single fp16 (wq, wk)
__global__ void __launch_bounds__(1024) k_splitT(const float* __restrict__ wq,
                                                 const float* __restrict__ wk)
{
    __shared__ float t[32][33];
    const float* in = (blockIdx.z == 0) ? wq : wk;
    __half* oh = (blockIdx.z == 0) ? g_wqTh : g_wkTh;
    const int x = blockIdx.x * 32 + threadIdx.x;
    const int y = blockIdx.y * 32 + threadIdx.y;
    t[threadIdx.y][threadIdx.x] = in[y * 512 + x];
    __syncthreads();
    const float v = t[threadIdx.x][threadIdx.y];
    const int ox = blockIdx.y * 32 + threadIdx.x;
    const int oy = blockIdx.x * 32 + threadIdx.y;
    oh[oy * 512 + ox] = __float2half_rn(v);
}

// ===========================================================================
// k_weights: z=0: vwT[c][v] = vc @ basis^T ; z=1: ow[v][c] = basis @ oc^T
// ===========================================================================
__global__ void __launch_bounds__(256) k_weights(
    const float* __restrict__ basis, const float* __restrict__ vc,
    const float* __restrict__ oc)
{
    __shared__ float As[8][132];
    __shared__ float Bs[8][132];
    const int z = blockIdx.z;
    const float* A = z ? basis : vc;
    const float* B = z ? oc : basis;
    __half* Oh = z ? g_owh : g_vwTh;
    const int bx = blockIdx.x, by = blockIdx.y;
    const int tid = threadIdx.x;
    const int tx = tid & 15, ty = tid >> 4;

    float acc[8][8];
#pragma unroll
    for (int i = 0; i < 8; i++)
#pragma unroll
        for (int j = 0; j < 8; j++) acc[i][j] = 0.f;

    const float* Ab = A + (size_t)(by * 128) * NBc;

    for (int k0 = 0; k0 < NBc; k0 += 8) {
        {
            const int ar = tid >> 1, ac = (tid & 1) * 4;
            float4 v = *(const float4*)(Ab + (size_t)ar * NBc + k0 + ac);
            As[ac + 0][ar] = v.x; As[ac + 1][ar] = v.y;
            As[ac + 2][ar] = v.z; As[ac + 3][ar] = v.w;
        }
        {
            const int br = tid >> 1, bc = (tid & 1) * 4;
            float4 v = *(const float4*)(B + (size_t)(bx * 128 + br) * NBc + k0 + bc);
            Bs[bc + 0][br] = v.x; Bs[bc + 1][br] = v.y;
            Bs[bc + 2][br] = v.z; Bs[bc + 3][br] = v.w;
        }
        __syncthreads();

#pragma unroll
        for (int kk = 0; kk < 8; kk++) {
            float a[8], bf[8];
            *(float4*)(a)     = *(const float4*)&As[kk][ty * 8];
            *(float4*)(a + 4) = *(const float4*)&As[kk][ty * 8 + 4];
            *(float4*)(bf)     = *(const float4*)&Bs[kk][tx * 8];
            *(float4*)(bf + 4) = *(const float4*)&Bs[kk][tx * 8 + 4];
#pragma unroll
            for (int i = 0; i < 8; i++)
#pragma unroll
                for (int j = 0; j < 8; j++) acc[i][j] += a[i] * bf[j];
        }
        __syncthreads();
    }

#pragma unroll
    for (int i = 0; i < 8; i++) {
        const size_t rowb = (size_t)(by * 128 + ty * 8 + i) * 512 + bx * 128 + tx * 8;
#pragma unroll
        for (int j = 0; j < 8; j += 2) {
            __half2 p;
            p.x = __float2half_rn(acc[i][j]);
            p.y = __float2half_rn(acc[i][j + 1]);
            *(__half2*)(Oh + rowb + j) = p;
        }
    }
}

// L2-normalize rows of g_q/g_k, write fp16 splits
__global__ void __launch_bounds__(256) k_norm()
{
    const int row = blockIdx.x;
    const float* q = g_q + (size_t)row * Cc;
    const float* k = g_k + (size_t)row * Cc;
    const int t = threadIdx.x;
    float q0 = q[t], q1 = q[t + 256];
    float k0 = k[t], k1 = k[t + 256];
    float sq = q0 * q0 + q1 * q1;
    float sk = k0 * k0 + k1 * k1;
#pragma unroll
    for (int off = 16; off; off >>= 1) {
        sq += __shfl_xor_sync(0xffffffffu, sq, off);
        sk += __shfl_xor_sync(0xffffffffu, sk, off);
    }
    __shared__ float rq[8], rk[8];
    __shared__ float inv[2];
    const int w = t >> 5, l = t & 31;
    if (l == 0) { rq[w] = sq; rk[w] = sk; }
    __syncthreads();
    if (t == 0) {
        float a = 0.f, cc = 0.f;
#pragma unroll
        for (int i = 0; i < 8; i++) { a += rq[i]; cc += rk[i]; }
        inv[0] = 1.f / fmaxf(sqrtf(a), 1e-12f);
        inv[1] = 1.f / fmaxf(sqrtf(cc), 1e-12f);
    }
    __syncthreads();
    const float iq = inv[0], ik = inv[1];
    __half h, lo;
    const size_t b = (size_t)row * Cc;
    split2(q0 * iq, h, lo); g_qnh[b + t] = h;       g_qnl[b + t] = lo;
    split2(q1 * iq, h, lo); g_qnh[b + t + 256] = h; g_qnl[b + t + 256] = lo;
    split2(k0 * ik, h, lo); g_knh[b + t] = h;       g_knl[b + t] = lo;
    split2(k1 * ik, h, lo); g_knh[b + t + 256] = h; g_knl[b + t + 256] = lo;
}

// ===========================================================================
// Phase A (MMA): A^T_c[e][d] = sum_j V[j][e] * (d^j K[j][d])
// Vectorized transpose staging: thread = (j-pair, 8 d); uint4 loads,
// conflict-free half2 smem stores.
// ===========================================================================
#define ST_K  0
#define ST_VH 18432
#define ST_VL 36864
#define STATE_SMEM 55296

__global__ void __launch_bounds__(256) k_state(const float* __restrict__ dlog)
{
    extern __shared__ __align__(16) char sm[];
    const int c = blockIdx.x + 1, h = blockIdx.y, b = blockIdx.z;
    const int tid = threadIdx.x, lane = tid & 31, wid = tid >> 5;
    const float dec = 1.f / (1.f + expf(-dlog[h]));
    const float l2d = log2f(dec);
    const size_t gb = ((size_t)b * Tc + c * CHL) * Cc + h * Dc;

#pragma unroll
    for (int it = 0; it < 2; it++) {
        const int idx = tid + 256 * it;          // 0..511
        const int jp = idx & 31;                 // j-pair 0..31
        const int d0 = (idx >> 5) * 8;           // 0..120
        const int j0 = jp * 2;
        const size_t r0 = gb + (size_t)j0 * Cc + d0;
        const size_t r1 = r0 + Cc;
        uint4 kh0 = *(const uint4*)(g_knh + r0);
        uint4 kl0 = *(const uint4*)(g_knl + r0);
        uint4 kh1 = *(const uint4*)(g_knh + r1);
        uint4 kl1 = *(const uint4*)(g_knl + r1);
        uint4 vh0 = *(const uint4*)(g_vsh + r0);
        uint4 vh1 = *(const uint4*)(g_vsh + r1);
        uint4 vl0 = *(const uint4*)(g_vsl + r0);
        uint4 vl1 = *(const uint4*)(g_vsl + r1);
        const __half* pkh0 = (const __half*)&kh0;
        const __half* pkl0 = (const __half*)&kl0;
        const __half* pkh1 = (const __half*)&kh1;
        const __half* pkl1 = (const __half*)&kl1;
        const __half* pvh0 = (const __half*)&vh0;
        const __half* pvh1 = (const __half*)&vh1;
        const __half* pvl0 = (const __half*)&vl0;
        const __half* pvl1 = (const __half*)&vl1;
        const float e0 = exp2f(l2d * (float)j0);
        const float e1 = e0 * dec;
#pragma unroll
        for (int u = 0; u < 8; u++) {
            const uint32_t off = (d0 + u) * 144 + jp * 4;
            const float k0v = __half2float(pkh0[u]) + __half2float(pkl0[u]);
            const float k1v = __half2float(pkh1[u]) + __half2float(pkl1[u]);
            __half2 p;
            p.x = __float2half_rn(k0v * e0);
            p.y = __float2half_rn(k1v * e1);
            *(__half2*)(sm + ST_K + off) = p;
            p.x = pvh0[u]; p.y = pvh1[u];
            *(__half2*)(sm + ST_VH + off) = p;
            p.x = pvl0[u]; p.y = pvl1[u];
            *(__half2*)(sm + ST_VL + off) = p;
        }
    }
    __syncthreads();

    const int wm = wid >> 2, wn = wid & 3;
    const uint32_t sb = smem_u32(sm);
    const uint32_t a_lrow = wm * 64 + (lane & 15);
    const uint32_t a_koff = (lane >> 4) * 8;
    const uint32_t b_lrow = wn * 32 + (lane & 7) + ((lane >> 4) << 3);
    const uint32_t b_koff = ((lane >> 3) & 1) * 8;

    float acc[4][4][4];
#pragma unroll
    for (int i = 0; i < 4; i++)
#pragma unroll
        for (int j = 0; j < 4; j++)
#pragma unroll
            for (int q = 0; q < 4; q++) acc[i][j][q] = 0.f;

#pragma unroll
    for (int ks = 0; ks < 4; ks++) {
        const int k0 = ks * 16;
        uint32_t kh[8];
#pragma unroll
        for (int nf = 0; nf < 2; nf++) {
            const uint32_t boff = (b_lrow + nf * 16) * 144 + (k0 + b_koff) * 2;
            ldm_x4(kh + nf * 4, sb + ST_K + boff);
        }
#pragma unroll
        for (int mi = 0; mi < 4; mi++) {
            uint32_t vh[4], vl[4];
            const uint32_t aoff = (a_lrow + mi * 16) * 144 + (k0 + a_koff) * 2;
            ldm_x4(vh, sb + ST_VH + aoff);
            ldm_x4(vl, sb + ST_VL + aoff);
#pragma unroll
            for (int ni = 0; ni < 4; ni++) {
                mma_f16(acc[mi][ni], vh, kh + ni * 2);
                mma_f16(acc[mi][ni], vl, kh + ni * 2);
            }
        }
    }

    float* dst = g_stA + ((size_t)(b * Hc + h) * NCH + c) * (Dc * Dc);
    const int qr = lane >> 2, qc = lane & 3;
#pragma unroll
    for (int mi = 0; mi < 4; mi++) {
#pragma unroll
        for (int ni = 0; ni < 4; ni++) {
            const int m = wm * 64 + mi * 16 + qr;
            const int n = wn * 32 + ni * 8 + qc * 2;
            float2 v0, v1;
            v0.x = acc[mi][ni][0]; v0.y = acc[mi][ni][1];
            v1.x = acc[mi][ni][2]; v1.y = acc[mi][ni][3];
            *(float2*)(dst + (size_t)m * Dc + n)       = v0;
            *(float2*)(dst + (size_t)(m + 8) * Dc + n) = v1;
        }
    }
}

// ===========================================================================
// Phase B: backward scan on A^T, writes single-fp16 T^T.
// ===========================================================================
__global__ void __launch_bounds__(256) k_scan(const float* __restrict__ dlog)
{
    const int bh = blockIdx.x;
    const int h = bh & (Hc - 1);
    const int idx4 = blockIdx.y * 256 + threadIdx.x;   // 0..4095
    const float dec = 1.f / (1.f + expf(-dlog[h]));
    const float dL = exp2f(log2f(dec) * (float)CHL);

    float4 run = make_float4(0.f, 0.f, 0.f, 0.f);
    for (int c = NCH - 2; c >= 0; c--) {
        const float4* A =
            (const float4*)(g_stA + ((size_t)bh * NCH + c + 1) * (Dc * Dc));
        float4 a = A[idx4];
        run.x = a.x + dL * run.x;
        run.y = a.y + dL * run.y;
        run.z = a.z + dL * run.z;
        run.w = a.w + dL * run.w;
        const size_t o = ((size_t)bh * NCH + c) * (Dc * Dc) + (size_t)idx4 * 4;
        __half2 p;
        p.x = __float2half_rn(run.x); p.y = __float2half_rn(run.y);
        *(__half2*)(g_sTh + o) = p;
        p.x = __float2half_rn(run.z); p.y = __float2half_rn(run.w);
        *(__half2*)(g_sTh + o + 2) = p;
    }
}

// ===========================================================================
// Phase C (MMA): round-7 version (S split hi/lo) + vectorized V staging.
// ===========================================================================
#define CQ_H 0
#define CQ_L 17408
#define CK   34816
#define CV   52224
#define CS_H 70656
#define CS_L 79872
#define CT   89088
#define CATTN_SMEM 123904

__global__ void __launch_bounds__(256) k_cattn(const float* __restrict__ dlog)
{
    extern __shared__ __align__(16) char sm[];
    const int c = blockIdx.x, h = blockIdx.y, b = blockIdx.z;
    const int tid = threadIdx.x, lane = tid & 31, wid = tid >> 5;
    const int wm = wid >> 2, wn = wid & 3;
    const float dec = 1.f / (1.f + expf(-dlog[h]));
    const float l2d = log2f(dec);
    const size_t gb = ((size_t)b * Tc + c * CHL) * Cc + h * Dc;
    const uint32_t sb = smem_u32(sm);

    // Prefetch full T^T (single fp16) with cp.async
    if (c < NCH - 1) {
        const __half* Th = g_sTh + ((size_t)(b * Hc + h) * NCH + c) * (Dc * Dc);
#pragma unroll
        for (int i = 0; i < 8; i++) {
            const int idx = tid + 256 * i;           // 0..2047
            const int e = idx >> 4, q = idx & 15;
            cp16(sb + CT + e * 272 + q * 16, Th + (size_t)e * 128 + q * 8);
        }
    }
    cp_commit();

    // Q hi/lo, K single tiles 64x128 pitch 272B
    {
        const uint4* s0 = (const uint4*)(g_qnh + gb);
        const uint4* s1 = (const uint4*)(g_qnl + gb);
        const uint4* s2 = (const uint4*)(g_knh + gb);
#pragma unroll
        for (int i = 0; i < 4; i++) {
            const int idx = tid + 256 * i;
            const int row = idx >> 4, q = idx & 15;
            const size_t so = (size_t)row * 64 + q;
            const uint32_t doff = row * 272 + q * 16;
            *(uint4*)(sm + CQ_H + doff) = s0[so];
            *(uint4*)(sm + CQ_L + doff) = s1[so];
            *(uint4*)(sm + CK   + doff) = s2[so];
        }
    }
    // Transposed V (single): VT[d][j] pitch 144B — vectorized staging
#pragma unroll
    for (int it = 0; it < 2; it++) {
        const int idx = tid + 256 * it;
        const int jp = idx & 31;
        const int d0 = (idx >> 5) * 8;
        const int j0 = jp * 2;
        const size_t r0 = gb + (size_t)j0 * Cc + d0;
        uint4 a0 = *(const uint4*)(g_vsh + r0);
        uint4 a1 = *(const uint4*)(g_vsh + r0 + Cc);
        const __half* p0 = (const __half*)&a0;
        const __half* p1 = (const __half*)&a1;
#pragma unroll
        for (int u = 0; u < 8; u++) {
            __half2 p; p.x = p0[u]; p.y = p1[u];
            *(__half2*)(sm + CV + (d0 + u) * 144 + jp * 4) = p;
        }
    }
    __syncthreads();

    const uint32_t a_koff = (lane >> 4) * 8;
    const uint32_t b_koff = ((lane >> 3) & 1) * 8;
    const uint32_t aQ_row = wm * 32 + (lane & 15);
    const uint32_t bS_row = wn * 16 + (lane & 7) + ((lane >> 4) << 3);
    const uint32_t bO_row = wn * 32 + (lane & 7) + ((lane >> 4) << 3);
    const int qr = lane >> 2, qc = lane & 3;

    // ---- intra: S = Q K^T (Q hi/lo x K single) ----
    float accS[2][2][4];
#pragma unroll
    for (int i = 0; i < 2; i++)
#pragma unroll
        for (int j = 0; j < 2; j++)
#pragma unroll
            for (int q = 0; q < 4; q++) accS[i][j][q] = 0.f;

#pragma unroll
    for (int ks = 0; ks < 8; ks++) {
        const int k0 = ks * 16;
        uint32_t kh[4];
        const uint32_t boff = bS_row * 272 + (k0 + b_koff) * 2;
        ldm_x4(kh, sb + CK + boff);
#pragma unroll
        for (int mi = 0; mi < 2; mi++) {
            uint32_t qh[4], ql[4];
            const uint32_t aoff = (aQ_row + mi * 16) * 272 + (k0 + a_koff) * 2;
            ldm_x4(qh, sb + CQ_H + aoff);
            ldm_x4(ql, sb + CQ_L + aoff);
#pragma unroll
            for (int ni = 0; ni < 2; ni++) {
                mma_f16(accS[mi][ni], qh, kh + ni * 2);
                mma_f16(accS[mi][ni], ql, kh + ni * 2);
            }
        }
    }

    // mask + split-store S (fp16 hi/lo)
#pragma unroll
    for (int mi = 0; mi < 2; mi++) {
#pragma unroll
        for (int ni = 0; ni < 2; ni++) {
#pragma unroll
            for (int q = 0; q < 4; q++) {
                const int il = wm * 32 + mi * 16 + qr + (q >> 1) * 8;
                const int jl = wn * 16 + ni * 8 + qc * 2 + (q & 1);
                float s = 0.f;
                if (jl > il)
                    s = accS[mi][ni][q] * exp2f(l2d * (float)(jl - il - 1));
                __half hh, ll;
                split2(s, hh, ll);
                *(__half*)(sm + CS_H + il * 144 + jl * 2) = hh;
                *(__half*)(sm + CS_L + il * 144 + jl * 2) = ll;
            }
        }
    }
    cp_wait<0>();
    __syncthreads();

    // ---- O accumulators ----
    float acc[2][4][4], accI[2][4][4];
#pragma unroll
    for (int i = 0; i < 2; i++)
#pragma unroll
        for (int j = 0; j < 4; j++)
#pragma unroll
            for (int q = 0; q < 4; q++) { acc[i][j][q] = 0.f; accI[i][j][q] = 0.f; }

    // intra SV: S hi/lo x V single, K=64
#pragma unroll
    for (int ks = 0; ks < 4; ks++) {
        const int k0 = ks * 16;
        uint32_t vh[8];
#pragma unroll
        for (int nf = 0; nf < 2; nf++) {
            const uint32_t boff = (bO_row + nf * 16) * 144 + (k0 + b_koff) * 2;
            ldm_x4(vh + nf * 4, sb + CV + boff);
        }
#pragma unroll
        for (int mi = 0; mi < 2; mi++) {
            uint32_t sh[4], sl[4];
            const uint32_t aoff = (aQ_row + mi * 16) * 144 + (k0 + a_koff) * 2;
            ldm_x4(sh, sb + CS_H + aoff);
            ldm_x4(sl, sb + CS_L + aoff);
#pragma unroll
            for (int ni = 0; ni < 4; ni++) {
                mma_f16(acc[mi][ni], sh, vh + ni * 2);
                mma_f16(acc[mi][ni], sl, vh + ni * 2);
            }
        }
    }

    // inter: O_i += Q @ T^T (Q hi/lo x T single), K=128
    if (c < NCH - 1) {
#pragma unroll
        for (int ks = 0; ks < 8; ks++) {
            const int k0 = ks * 16;
            uint32_t th[8];
#pragma unroll
            for (int nf = 0; nf < 2; nf++) {
                const uint32_t boff =
                    (bO_row + nf * 16) * 272 + (k0 + b_koff) * 2;
                ldm_x4(th + nf * 4, sb + CT + boff);
            }
#pragma unroll
            for (int mi = 0; mi < 2; mi++) {
                uint32_t qh[4], ql[4];
                const uint32_t aoff =
                    (aQ_row + mi * 16) * 272 + (k0 + a_koff) * 2;
                ldm_x4(qh, sb + CQ_H + aoff);
                ldm_x4(ql, sb + CQ_L + aoff);
#pragma unroll
                for (int ni = 0; ni < 4; ni++) {
                    mma_f16(accI[mi][ni], qh, th + ni * 2);
                    mma_f16(accI[mi][ni], ql, th + ni * 2);
                }
            }
        }
    }

    // epilogue: O = acc + f(row) * accI -> fp16 split write g_rh/g_rl
#pragma unroll
    for (int mi = 0; mi < 2; mi++) {
        const int r0 = wm * 32 + mi * 16 + qr;
        const float f0 = exp2f(l2d * (float)(63 - r0));
        const float f1 = exp2f(l2d * (float)(63 - (r0 + 8)));
#pragma unroll
        for (int ni = 0; ni < 4; ni++) {
            const int col = wn * 32 + ni * 8 + qc * 2;
            const size_t a0 = gb + (size_t)r0 * Cc + col;
            const size_t a1 = gb + (size_t)(r0 + 8) * Cc + col;
            float o0 = acc[mi][ni][0] + f0 * accI[mi][ni][0];
            float o1 = acc[mi][ni][1] + f0 * accI[mi][ni][1];
            float o2 = acc[mi][ni][2] + f1 * accI[mi][ni][2];
            float o3 = acc[mi][ni][3] + f1 * accI[mi][ni][3];
            __half h0, l0, h1, l1, h2, l2, h3, l3;
            split2(o0, h0, l0); split2(o1, h1, l1);
            split2(o2, h2, l2); split2(o3, h3, l3);
            __half2 p;
            p.x = h0; p.y = h1; *(__half2*)(g_rh + a0) = p;
            p.x = l0; p.y = l1; *(__half2*)(g_rl + a0) = p;
            p.x = h2; p.y = h3; *(__half2*)(g_rh + a1) = p;
            p.x = l2; p.y = l3; *(__half2*)(g_rl + a1) = p;
        }
    }
}

extern "C" void kernel_launch(void* const* d_in, const int* in_sizes, int n_in,
                              void* d_out, int out_size)
{
    const float* x     = (const float*)d_in[0];
    const float* basis = (const float*)d_in[1];
    const float* wq    = (const float*)d_in[2];
    const float* wk    = (const float*)d_in[3];
    const float* vc    = (const float*)d_in[4];
    const float* oc    = (const float*)d_in[5];
    const float* dlog  = (const float*)d_in[6];
    const float* oscal = (const float*)d_in[7];
    float* out = (float*)d_out;

    (void)in_sizes; (void)n_in; (void)out_size;

    cudaFuncSetAttribute(k_state, cudaFuncAttributeMaxDynamicSharedMemorySize,
                         STATE_SMEM);
    cudaFuncSetAttribute(k_cattn, cudaFuncAttributeMaxDynamicSharedMemorySize,
                         CATTN_SMEM);
    cudaFuncSetAttribute(k_gemm_proj, cudaFuncAttributeMaxDynamicSharedMemorySize,
                         GS_BYTES);
    cudaFuncSetAttribute(k_gemm_out, cudaFuncAttributeMaxDynamicSharedMemorySize,
                         GS_BYTES);

    k_weights<<<dim3(4, 4, 2), 256>>>(basis, vc, oc);
    k_split<<<MROWS * Cc / 4 / 256, 256>>>(x);
    k_splitT<<<dim3(16, 16, 2), dim3(32, 32)>>>(wq, wk);

    k_gemm_proj<<<dim3(Cc / 128, MROWS / 128, 3), 256, GS_BYTES>>>();
    k_norm<<<MROWS, 256>>>();

    k_state<<<dim3(NCH - 1, Hc, Bc), 256, STATE_SMEM>>>(dlog);
    k_scan<<<dim3(16, 16), 256>>>(dlog);
    k_cattn<<<dim3(NCH, Hc, Bc), 256, CATTN_SMEM>>>(dlog);

    k_gemm_out<<<dim3(Vc / 128, MROWS / 128), 256, GS_BYTES>>>(out, oscal);
}

// round 12
// speedup vs baseline: 1.1767x; 1.1238x over previous
#include <cuda_runtime.h>
#include <cuda_fp16.h>
#include <cstdint>

// Problem constants
#define Bc 4
#define Tc 2048
#define Vc 512
#define Cc 512
#define Hc 4
#define Dc 128
#define NBc 128
#define MROWS (Bc*Tc)    // 8192
#define NCH 32
#define CHL 64

// fp32 scratch
__device__ float g_q[MROWS*Cc];
__device__ float g_k[MROWS*Cc];
__device__ float g_stA[(size_t)16*NCH*Dc*Dc];   // A^T per chunk

// fp16 scratch
__device__ __half g_xh[MROWS*Cc],  g_xl[MROWS*Cc];
__device__ __half g_rh[MROWS*Cc];                // r single fp16
__device__ __half g_qnh[MROWS*Cc];               // q single fp16
__device__ __half g_knh[MROWS*Cc], g_knl[MROWS*Cc];
__device__ __half g_vsh[MROWS*Cc], g_vsl[MROWS*Cc];
__device__ __half g_wqTh[Cc*Vc];
__device__ __half g_wkTh[Cc*Vc];
__device__ __half g_vwTh[Cc*Vc];
__device__ __half g_owh[Vc*Cc];
__device__ __half g_sTh[(size_t)16*NCH*Dc*Dc];  // T^T single fp16 [bh][c][e][d]

// ===========================================================================
// Helpers
// ===========================================================================
__device__ __forceinline__ uint32_t smem_u32(const void* p) {
    uint32_t a;
    asm("{ .reg .u64 t; cvta.to.shared.u64 t, %1; cvt.u32.u64 %0, t; }"
        : "=r"(a) : "l"(p));
    return a;
}
__device__ __forceinline__ void ldm_x4(uint32_t* r, uint32_t addr) {
    asm volatile("ldmatrix.sync.aligned.m8n8.x4.shared.b16 {%0,%1,%2,%3}, [%4];"
                 : "=r"(r[0]), "=r"(r[1]), "=r"(r[2]), "=r"(r[3]) : "r"(addr));
}
__device__ __forceinline__ void mma_f16(float* c, const uint32_t* a,
                                        const uint32_t* b) {
    asm volatile(
        "mma.sync.aligned.m16n8k16.row.col.f32.f16.f16.f32 "
        "{%0,%1,%2,%3}, {%4,%5,%6,%7}, {%8,%9}, {%0,%1,%2,%3};"
        : "+f"(c[0]), "+f"(c[1]), "+f"(c[2]), "+f"(c[3])
        : "r"(a[0]), "r"(a[1]), "r"(a[2]), "r"(a[3]), "r"(b[0]), "r"(b[1]));
}
__device__ __forceinline__ void cp16(uint32_t dst, const void* src) {
    asm volatile("cp.async.cg.shared.global [%0], [%1], 16;"
                 :: "r"(dst), "l"(src));
}
__device__ __forceinline__ void cp_commit() {
    asm volatile("cp.async.commit_group;");
}
template <int N>
__device__ __forceinline__ void cp_wait() {
    asm volatile("cp.async.wait_group %0;" :: "n"(N));
}
__device__ __forceinline__ void split2(float v, __half& h, __half& l) {
    h = __float2half_rn(v);
    l = __float2half_rn(v - __half2float(h));
}

// ===========================================================================
// Split-fp16 warp-MMA GEMM (round-7 config: K-slab 64, 2-stage).
// C[128,128] = A[M,512]@B[N,512]^T. SPLITA: A hi/lo 2-pass, else single 1-pass.
// ===========================================================================
#define GSLAB 18432                 // 128 rows * 144B
#define GBUF  (3 * GSLAB)           // 55296 (A_h, A_l, B)
#define GS_BYTES (2 * GBUF)         // 110592

template <bool SPLITA>
__device__ __forceinline__ void gemm_mma_tile(
    const __half* __restrict__ Ah, const __half* __restrict__ Al,
    const __half* __restrict__ Bh,
    float* __restrict__ Cp, __half* __restrict__ Oh, __half* __restrict__ Ol,
    float alpha, int tm, int tn)
{
    extern __shared__ __align__(16) char smc[];
    const int tid = threadIdx.x, lane = tid & 31, wid = tid >> 5;
    const int wm = wid >> 2, wn = wid & 3;
    const uint32_t sb = smem_u32(smc);

    float acc[4][4][4];
#pragma unroll
    for (int i = 0; i < 4; i++)
#pragma unroll
        for (int j = 0; j < 4; j++)
#pragma unroll
            for (int q = 0; q < 4; q++) acc[i][j][q] = 0.f;

    const __half* bases[3];
    bases[0] = Ah + ((size_t)tm * 128) * 512;
    bases[1] = SPLITA ? (Al + ((size_t)tm * 128) * 512) : nullptr;
    bases[2] = Bh + ((size_t)tn * 128) * 512;

    auto issue = [&](int c, int buf) {
        const uint32_t bb = sb + buf * GBUF;
#pragma unroll
        for (int s = 0; s < 3; s++) {
            if (!SPLITA && s == 1) continue;
            const __half* src = bases[s] + c * 64;
#pragma unroll
            for (int i = 0; i < 4; i++) {
                const int idx = tid + 256 * i;
                const int row = idx >> 3, q = idx & 7;
                cp16(bb + s * GSLAB + row * 144 + q * 16,
                     src + (size_t)row * 512 + q * 8);
            }
        }
        cp_commit();
    };

    issue(0, 0);
    issue(1, 1);

    const uint32_t a_lrow = wm * 64 + (lane & 15);
    const uint32_t a_koff = (lane >> 4) * 8;
    const uint32_t b_lrow = wn * 32 + (lane & 7) + ((lane >> 4) << 3);
    const uint32_t b_koff = ((lane >> 3) & 1) * 8;

    for (int c = 0; c < 8; c++) {
        if (c == 7) cp_wait<0>(); else cp_wait<1>();
        __syncthreads();
        const uint32_t bb = sb + (c & 1) * GBUF;

#pragma unroll
        for (int ks = 0; ks < 4; ks++) {
            const int k0 = ks * 16;
            uint32_t bh[8];
#pragma unroll
            for (int nf = 0; nf < 2; nf++) {
                const uint32_t boff =
                    (b_lrow + nf * 16) * 144 + (k0 + b_koff) * 2;
                ldm_x4(bh + nf * 4, bb + 2 * GSLAB + boff);
            }
#pragma unroll
            for (int mi = 0; mi < 4; mi++) {
                const uint32_t aoff =
                    (a_lrow + mi * 16) * 144 + (k0 + a_koff) * 2;
                uint32_t ah[4];
                ldm_x4(ah, bb + 0 * GSLAB + aoff);
#pragma unroll
                for (int ni = 0; ni < 4; ni++)
                    mma_f16(acc[mi][ni], ah, bh + ni * 2);
                if (SPLITA) {
                    uint32_t al[4];
                    ldm_x4(al, bb + 1 * GSLAB + aoff);
#pragma unroll
                    for (int ni = 0; ni < 4; ni++)
                        mma_f16(acc[mi][ni], al, bh + ni * 2);
                }
            }
        }
        __syncthreads();
        if (c + 2 < 8) issue(c + 2, c & 1);
    }

    const int qr = lane >> 2, qc = lane & 3;
#pragma unroll
    for (int mi = 0; mi < 4; mi++) {
#pragma unroll
        for (int ni = 0; ni < 4; ni++) {
            const int m = tm * 128 + wm * 64 + mi * 16 + qr;
            const int n = tn * 128 + wn * 32 + ni * 8 + qc * 2;
            float o0 = acc[mi][ni][0] * alpha, o1 = acc[mi][ni][1] * alpha;
            float o2 = acc[mi][ni][2] * alpha, o3 = acc[mi][ni][3] * alpha;
            if (Cp) {
                float2 v0, v1;
                v0.x = o0; v0.y = o1; v1.x = o2; v1.y = o3;
                *(float2*)(Cp + (size_t)m * 512 + n)       = v0;
                *(float2*)(Cp + (size_t)(m + 8) * 512 + n) = v1;
            } else {
                __half h0, l0, h1, l1, h2, l2, h3, l3;
                split2(o0, h0, l0); split2(o1, h1, l1);
                split2(o2, h2, l2); split2(o3, h3, l3);
                __half2 p;
                p.x = h0; p.y = h1;
                *(__half2*)(Oh + (size_t)m * 512 + n) = p;
                p.x = l0; p.y = l1;
                *(__half2*)(Ol + (size_t)m * 512 + n) = p;
                p.x = h2; p.y = h3;
                *(__half2*)(Oh + (size_t)(m + 8) * 512 + n) = p;
                p.x = l2; p.y = l3;
                *(__half2*)(Ol + (size_t)(m + 8) * 512 + n) = p;
            }
        }
    }
}

__global__ void __launch_bounds__(256) k_gemm_proj()
{
    if (blockIdx.z == 0)
        gemm_mma_tile<true>(g_xh, g_xl, g_wqTh, g_q, nullptr, nullptr, 1.f,
                            blockIdx.y, blockIdx.x);
    else if (blockIdx.z == 1)
        gemm_mma_tile<true>(g_xh, g_xl, g_wkTh, g_k, nullptr, nullptr, 1.f,
                            blockIdx.y, blockIdx.x);
    else
        gemm_mma_tile<true>(g_xh, g_xl, g_vwTh, nullptr, g_vsh, g_vsl, 1.f,
                            blockIdx.y, blockIdx.x);
}

__global__ void __launch_bounds__(256) k_gemm_out(float* __restrict__ out,
                                                  const float* __restrict__ os)
{
    gemm_mma_tile<false>(g_rh, nullptr, g_owh, out, nullptr, nullptr,
                         __ldg(os), blockIdx.y, blockIdx.x);
}

// ===========================================================================
// Split x -> fp16 hi/lo
// ===========================================================================
__global__ void __launch_bounds__(256) k_split(const float* __restrict__ in)
{
    int i = blockIdx.x * 256 + threadIdx.x;
    float4 v = ((const float4*)in)[i];
    __half h0, h1, h2, h3, l0, l1, l2, l3;
    split2(v.x, h0, l0); split2(v.y, h1, l1);
    split2(v.z, h2, l2); split2(v.w, h3, l3);
    __half2 p;
    p.x = h0; p.y = h1; ((__half2*)g_xh)[2 * i]     = p;
    p.x = h2; p.y = h3; ((__half2*)g_xh)[2 * i + 1] = p;
    p.x = l0; p.y = l1; ((__half2*)g_xl)[2 * i]     = p;
    p.x = l2; p.y = l3; ((__half2*)g_xl)[2 * i + 1] = p;
}

// Transpose 512x512 weights -> single fp16 (wq, wk)
__global__ void __launch_bounds__(1024) k_splitT(const float* __restrict__ wq,
                                                 const float* __restrict__ wk)
{
    __shared__ float t[32][33];
    const float* in = (blockIdx.z == 0) ? wq : wk;
    __half* oh = (blockIdx.z == 0) ? g_wqTh : g_wkTh;
    const int x = blockIdx.x * 32 + threadIdx.x;
    const int y = blockIdx.y * 32 + threadIdx.y;
    t[threadIdx.y][threadIdx.x] = in[y * 512 + x];
    __syncthreads();
    const float v = t[threadIdx.x][threadIdx.y];
    const int ox = blockIdx.y * 32 + threadIdx.x;
    const int oy = blockIdx.x * 32 + threadIdx.y;
    oh[oy * 512 + ox] = __float2half_rn(v);
}

// ===========================================================================
// k_weights: z=0: vwT[c][v] = vc @ basis^T ; z=1: ow[v][c] = basis @ oc^T
// ===========================================================================
__global__ void __launch_bounds__(256) k_weights(
    const float* __restrict__ basis, const float* __restrict__ vc,
    const float* __restrict__ oc)
{
    __shared__ float As[8][132];
    __shared__ float Bs[8][132];
    const int z = blockIdx.z;
    const float* A = z ? basis : vc;
    const float* B = z ? oc : basis;
    __half* Oh = z ? g_owh : g_vwTh;
    const int bx = blockIdx.x, by = blockIdx.y;
    const int tid = threadIdx.x;
    const int tx = tid & 15, ty = tid >> 4;

    float acc[8][8];
#pragma unroll
    for (int i = 0; i < 8; i++)
#pragma unroll
        for (int j = 0; j < 8; j++) acc[i][j] = 0.f;

    const float* Ab = A + (size_t)(by * 128) * NBc;

    for (int k0 = 0; k0 < NBc; k0 += 8) {
        {
            const int ar = tid >> 1, ac = (tid & 1) * 4;
            float4 v = *(const float4*)(Ab + (size_t)ar * NBc + k0 + ac);
            As[ac + 0][ar] = v.x; As[ac + 1][ar] = v.y;
            As[ac + 2][ar] = v.z; As[ac + 3][ar] = v.w;
        }
        {
            const int br = tid >> 1, bc = (tid & 1) * 4;
            float4 v = *(const float4*)(B + (size_t)(bx * 128 + br) * NBc + k0 + bc);
            Bs[bc + 0][br] = v.x; Bs[bc + 1][br] = v.y;
            Bs[bc + 2][br] = v.z; Bs[bc + 3][br] = v.w;
        }
        __syncthreads();

#pragma unroll
        for (int kk = 0; kk < 8; kk++) {
            float a[8], bf[8];
            *(float4*)(a)     = *(const float4*)&As[kk][ty * 8];
            *(float4*)(a + 4) = *(const float4*)&As[kk][ty * 8 + 4];
            *(float4*)(bf)     = *(const float4*)&Bs[kk][tx * 8];
            *(float4*)(bf + 4) = *(const float4*)&Bs[kk][tx * 8 + 4];
#pragma unroll
            for (int i = 0; i < 8; i++)
#pragma unroll
                for (int j = 0; j < 8; j++) acc[i][j] += a[i] * bf[j];
        }
        __syncthreads();
    }

#pragma unroll
    for (int i = 0; i < 8; i++) {
        const size_t rowb = (size_t)(by * 128 + ty * 8 + i) * 512 + bx * 128 + tx * 8;
#pragma unroll
        for (int j = 0; j < 8; j += 2) {
            __half2 p;
            p.x = __float2half_rn(acc[i][j]);
            p.y = __float2half_rn(acc[i][j + 1]);
            *(__half2*)(Oh + rowb + j) = p;
        }
    }
}

// L2-normalize rows of g_q/g_k; q -> single fp16, k -> fp16 hi/lo
__global__ void __launch_bounds__(256) k_norm()
{
    const int row = blockIdx.x;
    const float* q = g_q + (size_t)row * Cc;
    const float* k = g_k + (size_t)row * Cc;
    const int t = threadIdx.x;
    float q0 = q[t], q1 = q[t + 256];
    float k0 = k[t], k1 = k[t + 256];
    float sq = q0 * q0 + q1 * q1;
    float sk = k0 * k0 + k1 * k1;
#pragma unroll
    for (int off = 16; off; off >>= 1) {
        sq += __shfl_xor_sync(0xffffffffu, sq, off);
        sk += __shfl_xor_sync(0xffffffffu, sk, off);
    }
    __shared__ float rq[8], rk[8];
    __shared__ float inv[2];
    const int w = t >> 5, l = t & 31;
    if (l == 0) { rq[w] = sq; rk[w] = sk; }
    __syncthreads();
    if (t == 0) {
        float a = 0.f, cc = 0.f;
#pragma unroll
        for (int i = 0; i < 8; i++) { a += rq[i]; cc += rk[i]; }
        inv[0] = 1.f / fmaxf(sqrtf(a), 1e-12f);
        inv[1] = 1.f / fmaxf(sqrtf(cc), 1e-12f);
    }
    __syncthreads();
    const float iq = inv[0], ik = inv[1];
    __half h, lo;
    const size_t b = (size_t)row * Cc;
    g_qnh[b + t]       = __float2half_rn(q0 * iq);
    g_qnh[b + t + 256] = __float2half_rn(q1 * iq);
    split2(k0 * ik, h, lo); g_knh[b + t] = h;       g_knl[b + t] = lo;
    split2(k1 * ik, h, lo); g_knh[b + t + 256] = h; g_knl[b + t + 256] = lo;
}

// ===========================================================================
// Phase A (MMA): A^T_c[e][d] = sum_j V[j][e] * (d^j K[j][d])
// Vectorized transpose staging.
// ===========================================================================
#define ST_K  0
#define ST_VH 18432
#define ST_VL 36864
#define STATE_SMEM 55296

__global__ void __launch_bounds__(256) k_state(const float* __restrict__ dlog)
{
    extern __shared__ __align__(16) char sm[];
    const int c = blockIdx.x + 1, h = blockIdx.y, b = blockIdx.z;
    const int tid = threadIdx.x, lane = tid & 31, wid = tid >> 5;
    const float dec = 1.f / (1.f + expf(-dlog[h]));
    const float l2d = log2f(dec);
    const size_t gb = ((size_t)b * Tc + c * CHL) * Cc + h * Dc;

#pragma unroll
    for (int it = 0; it < 2; it++) {
        const int idx = tid + 256 * it;          // 0..511
        const int jp = idx & 31;                 // j-pair 0..31
        const int d0 = (idx >> 5) * 8;           // 0..120
        const int j0 = jp * 2;
        const size_t r0 = gb + (size_t)j0 * Cc + d0;
        const size_t r1 = r0 + Cc;
        uint4 kh0 = *(const uint4*)(g_knh + r0);
        uint4 kl0 = *(const uint4*)(g_knl + r0);
        uint4 kh1 = *(const uint4*)(g_knh + r1);
        uint4 kl1 = *(const uint4*)(g_knl + r1);
        uint4 vh0 = *(const uint4*)(g_vsh + r0);
        uint4 vh1 = *(const uint4*)(g_vsh + r1);
        uint4 vl0 = *(const uint4*)(g_vsl + r0);
        uint4 vl1 = *(const uint4*)(g_vsl + r1);
        const __half* pkh0 = (const __half*)&kh0;
        const __half* pkl0 = (const __half*)&kl0;
        const __half* pkh1 = (const __half*)&kh1;
        const __half* pkl1 = (const __half*)&kl1;
        const __half* pvh0 = (const __half*)&vh0;
        const __half* pvh1 = (const __half*)&vh1;
        const __half* pvl0 = (const __half*)&vl0;
        const __half* pvl1 = (const __half*)&vl1;
        const float e0 = exp2f(l2d * (float)j0);
        const float e1 = e0 * dec;
#pragma unroll
        for (int u = 0; u < 8; u++) {
            const uint32_t off = (d0 + u) * 144 + jp * 4;
            const float k0v = __half2float(pkh0[u]) + __half2float(pkl0[u]);
            const float k1v = __half2float(pkh1[u]) + __half2float(pkl1[u]);
            __half2 p;
            p.x = __float2half_rn(k0v * e0);
            p.y = __float2half_rn(k1v * e1);
            *(__half2*)(sm + ST_K + off) = p;
            p.x = pvh0[u]; p.y = pvh1[u];
            *(__half2*)(sm + ST_VH + off) = p;
            p.x = pvl0[u]; p.y = pvl1[u];
            *(__half2*)(sm + ST_VL + off) = p;
        }
    }
    __syncthreads();

    const int wm = wid >> 2, wn = wid & 3;
    const uint32_t sb = smem_u32(sm);
    const uint32_t a_lrow = wm * 64 + (lane & 15);
    const uint32_t a_koff = (lane >> 4) * 8;
    const uint32_t b_lrow = wn * 32 + (lane & 7) + ((lane >> 4) << 3);
    const uint32_t b_koff = ((lane >> 3) & 1) * 8;

    float acc[4][4][4];
#pragma unroll
    for (int i = 0; i < 4; i++)
#pragma unroll
        for (int j = 0; j < 4; j++)
#pragma unroll
            for (int q = 0; q < 4; q++) acc[i][j][q] = 0.f;

#pragma unroll
    for (int ks = 0; ks < 4; ks++) {
        const int k0 = ks * 16;
        uint32_t kh[8];
#pragma unroll
        for (int nf = 0; nf < 2; nf++) {
            const uint32_t boff = (b_lrow + nf * 16) * 144 + (k0 + b_koff) * 2;
            ldm_x4(kh + nf * 4, sb + ST_K + boff);
        }
#pragma unroll
        for (int mi = 0; mi < 4; mi++) {
            uint32_t vh[4], vl[4];
            const uint32_t aoff = (a_lrow + mi * 16) * 144 + (k0 + a_koff) * 2;
            ldm_x4(vh, sb + ST_VH + aoff);
            ldm_x4(vl, sb + ST_VL + aoff);
#pragma unroll
            for (int ni = 0; ni < 4; ni++) {
                mma_f16(acc[mi][ni], vh, kh + ni * 2);
                mma_f16(acc[mi][ni], vl, kh + ni * 2);
            }
        }
    }

    float* dst = g_stA + ((size_t)(b * Hc + h) * NCH + c) * (Dc * Dc);
    const int qr = lane >> 2, qc = lane & 3;
#pragma unroll
    for (int mi = 0; mi < 4; mi++) {
#pragma unroll
        for (int ni = 0; ni < 4; ni++) {
            const int m = wm * 64 + mi * 16 + qr;
            const int n = wn * 32 + ni * 8 + qc * 2;
            float2 v0, v1;
            v0.x = acc[mi][ni][0]; v0.y = acc[mi][ni][1];
            v1.x = acc[mi][ni][2]; v1.y = acc[mi][ni][3];
            *(float2*)(dst + (size_t)m * Dc + n)       = v0;
            *(float2*)(dst + (size_t)(m + 8) * Dc + n) = v1;
        }
    }
}

// ===========================================================================
// Phase B: backward scan on A^T, writes single-fp16 T^T.
// ===========================================================================
__global__ void __launch_bounds__(256) k_scan(const float* __restrict__ dlog)
{
    const int bh = blockIdx.x;
    const int h = bh & (Hc - 1);
    const int idx4 = blockIdx.y * 256 + threadIdx.x;   // 0..4095
    const float dec = 1.f / (1.f + expf(-dlog[h]));
    const float dL = exp2f(log2f(dec) * (float)CHL);

    float4 run = make_float4(0.f, 0.f, 0.f, 0.f);
    for (int c = NCH - 2; c >= 0; c--) {
        const float4* A =
            (const float4*)(g_stA + ((size_t)bh * NCH + c + 1) * (Dc * Dc));
        float4 a = A[idx4];
        run.x = a.x + dL * run.x;
        run.y = a.y + dL * run.y;
        run.z = a.z + dL * run.z;
        run.w = a.w + dL * run.w;
        const size_t o = ((size_t)bh * NCH + c) * (Dc * Dc) + (size_t)idx4 * 4;
        __half2 p;
        p.x = __float2half_rn(run.x); p.y = __float2half_rn(run.y);
        *(__half2*)(g_sTh + o) = p;
        p.x = __float2half_rn(run.z); p.y = __float2half_rn(run.w);
        *(__half2*)(g_sTh + o + 2) = p;
    }
}

// ===========================================================================
// Phase C (MMA): all-single operands, 1-pass MMAs. FIXED smem layout:
// CQ 64x272=17408 | CK 64x272=17408 | CV 128x144=18432 | CS 64x144=9216
// | CT 128x272=34816  => total 97280, 2 CTAs/SM.
// ===========================================================================
#define CQ   0
#define CK   17408
#define CV   34816
#define CS   53248
#define CT   62464
#define CATTN_SMEM 97280

__global__ void __launch_bounds__(256) k_cattn(const float* __restrict__ dlog)
{
    extern __shared__ __align__(16) char sm[];
    const int c = blockIdx.x, h = blockIdx.y, b = blockIdx.z;
    const int tid = threadIdx.x, lane = tid & 31, wid = tid >> 5;
    const int wm = wid >> 2, wn = wid & 3;
    const float dec = 1.f / (1.f + expf(-dlog[h]));
    const float l2d = log2f(dec);
    const size_t gb = ((size_t)b * Tc + c * CHL) * Cc + h * Dc;
    const uint32_t sb = smem_u32(sm);

    // Prefetch full T^T (single fp16) with cp.async
    if (c < NCH - 1) {
        const __half* Th = g_sTh + ((size_t)(b * Hc + h) * NCH + c) * (Dc * Dc);
#pragma unroll
        for (int i = 0; i < 8; i++) {
            const int idx = tid + 256 * i;           // 0..2047
            const int e = idx >> 4, q = idx & 15;
            cp16(sb + CT + e * 272 + q * 16, Th + (size_t)e * 128 + q * 8);
        }
    }
    cp_commit();

    // Q single, K single tiles 64x128 pitch 272B
    {
        const uint4* s0 = (const uint4*)(g_qnh + gb);
        const uint4* s2 = (const uint4*)(g_knh + gb);
#pragma unroll
        for (int i = 0; i < 4; i++) {
            const int idx = tid + 256 * i;
            const int row = idx >> 4, q = idx & 15;
            const size_t so = (size_t)row * 64 + q;
            const uint32_t doff = row * 272 + q * 16;
            *(uint4*)(sm + CQ + doff) = s0[so];
            *(uint4*)(sm + CK + doff) = s2[so];
        }
    }
    // Transposed V (single): VT[d][j] pitch 144B — vectorized staging
#pragma unroll
    for (int it = 0; it < 2; it++) {
        const int idx = tid + 256 * it;
        const int jp = idx & 31;
        const int d0 = (idx >> 5) * 8;
        const int j0 = jp * 2;
        const size_t r0 = gb + (size_t)j0 * Cc + d0;
        uint4 a0 = *(const uint4*)(g_vsh + r0);
        uint4 a1 = *(const uint4*)(g_vsh + r0 + Cc);
        const __half* p0 = (const __half*)&a0;
        const __half* p1 = (const __half*)&a1;
#pragma unroll
        for (int u = 0; u < 8; u++) {
            __half2 p; p.x = p0[u]; p.y = p1[u];
            *(__half2*)(sm + CV + (d0 + u) * 144 + jp * 4) = p;
        }
    }
    __syncthreads();

    const uint32_t a_koff = (lane >> 4) * 8;
    const uint32_t b_koff = ((lane >> 3) & 1) * 8;
    const uint32_t aQ_row = wm * 32 + (lane & 15);
    const uint32_t bS_row = wn * 16 + (lane & 7) + ((lane >> 4) << 3);
    const uint32_t bO_row = wn * 32 + (lane & 7) + ((lane >> 4) << 3);
    const int qr = lane >> 2, qc = lane & 3;

    // ---- intra: S = Q K^T (1 pass) ----
    float accS[2][2][4];
#pragma unroll
    for (int i = 0; i < 2; i++)
#pragma unroll
        for (int j = 0; j < 2; j++)
#pragma unroll
            for (int q = 0; q < 4; q++) accS[i][j][q] = 0.f;

#pragma unroll
    for (int ks = 0; ks < 8; ks++) {
        const int k0 = ks * 16;
        uint32_t kh[4];
        const uint32_t boff = bS_row * 272 + (k0 + b_koff) * 2;
        ldm_x4(kh, sb + CK + boff);
#pragma unroll
        for (int mi = 0; mi < 2; mi++) {
            uint32_t qh[4];
            const uint32_t aoff = (aQ_row + mi * 16) * 272 + (k0 + a_koff) * 2;
            ldm_x4(qh, sb + CQ + aoff);
#pragma unroll
            for (int ni = 0; ni < 2; ni++)
                mma_f16(accS[mi][ni], qh, kh + ni * 2);
        }
    }

    // mask + store S (single fp16)
#pragma unroll
    for (int mi = 0; mi < 2; mi++) {
#pragma unroll
        for (int ni = 0; ni < 2; ni++) {
#pragma unroll
            for (int q = 0; q < 4; q++) {
                const int il = wm * 32 + mi * 16 + qr + (q >> 1) * 8;
                const int jl = wn * 16 + ni * 8 + qc * 2 + (q & 1);
                float s = 0.f;
                if (jl > il)
                    s = accS[mi][ni][q] * exp2f(l2d * (float)(jl - il - 1));
                *(__half*)(sm + CS + il * 144 + jl * 2) = __float2half_rn(s);
            }
        }
    }
    cp_wait<0>();
    __syncthreads();

    // ---- O accumulators ----
    float acc[2][4][4], accI[2][4][4];
#pragma unroll
    for (int i = 0; i < 2; i++)
#pragma unroll
        for (int j = 0; j < 4; j++)
#pragma unroll
            for (int q = 0; q < 4; q++) { acc[i][j][q] = 0.f; accI[i][j][q] = 0.f; }

    // intra SV: single x single (1 pass), K=64
#pragma unroll
    for (int ks = 0; ks < 4; ks++) {
        const int k0 = ks * 16;
        uint32_t vh[8];
#pragma unroll
        for (int nf = 0; nf < 2; nf++) {
            const uint32_t boff = (bO_row + nf * 16) * 144 + (k0 + b_koff) * 2;
            ldm_x4(vh + nf * 4, sb + CV + boff);
        }
#pragma unroll
        for (int mi = 0; mi < 2; mi++) {
            uint32_t sh[4];
            const uint32_t aoff = (aQ_row + mi * 16) * 144 + (k0 + a_koff) * 2;
            ldm_x4(sh, sb + CS + aoff);
#pragma unroll
            for (int ni = 0; ni < 4; ni++)
                mma_f16(acc[mi][ni], sh, vh + ni * 2);
        }
    }

    // inter: O_i += Q @ T^T (single x single), K=128
    if (c < NCH - 1) {
#pragma unroll
        for (int ks = 0; ks < 8; ks++) {
            const int k0 = ks * 16;
            uint32_t th[8];
#pragma unroll
            for (int nf = 0; nf < 2; nf++) {
                const uint32_t boff =
                    (bO_row + nf * 16) * 272 + (k0 + b_koff) * 2;
                ldm_x4(th + nf * 4, sb + CT + boff);
            }
#pragma unroll
            for (int mi = 0; mi < 2; mi++) {
                uint32_t qh[4];
                const uint32_t aoff =
                    (aQ_row + mi * 16) * 272 + (k0 + a_koff) * 2;
                ldm_x4(qh, sb + CQ + aoff);
#pragma unroll
                for (int ni = 0; ni < 4; ni++)
                    mma_f16(accI[mi][ni], qh, th + ni * 2);
            }
        }
    }

    // epilogue: O = acc + f(row) * accI -> single fp16 write g_rh
#pragma unroll
    for (int mi = 0; mi < 2; mi++) {
        const int r0 = wm * 32 + mi * 16 + qr;
        const float f0 = exp2f(l2d * (float)(63 - r0));
        const float f1 = exp2f(l2d * (float)(63 - (r0 + 8)));
#pragma unroll
        for (int ni = 0; ni < 4; ni++) {
            const int col = wn * 32 + ni * 8 + qc * 2;
            const size_t a0 = gb + (size_t)r0 * Cc + col;
            const size_t a1 = gb + (size_t)(r0 + 8) * Cc + col;
            __half2 p;
            p.x = __float2half_rn(acc[mi][ni][0] + f0 * accI[mi][ni][0]);
            p.y = __float2half_rn(acc[mi][ni][1] + f0 * accI[mi][ni][1]);
            *(__half2*)(g_rh + a0) = p;
            p.x = __float2half_rn(acc[mi][ni][2] + f1 * accI[mi][ni][2]);
            p.y = __float2half_rn(acc[mi][ni][3] + f1 * accI[mi][ni][3]);
            *(__half2*)(g_rh + a1) = p;
        }
    }
}

extern "C" void kernel_launch(void* const* d_in, const int* in_sizes, int n_in,
                              void* d_out, int out_size)
{
    const float* x     = (const float*)d_in[0];
    const float* basis = (const float*)d_in[1];
    const float* wq    = (const float*)d_in[2];
    const float* wk    = (const float*)d_in[3];
    const float* vc    = (const float*)d_in[4];
    const float* oc    = (const float*)d_in[5];
    const float* dlog  = (const float*)d_in[6];
    const float* oscal = (const float*)d_in[7];
    float* out = (float*)d_out;

    (void)in_sizes; (void)n_in; (void)out_size;

    cudaFuncSetAttribute(k_state, cudaFuncAttributeMaxDynamicSharedMemorySize,
                         STATE_SMEM);
    cudaFuncSetAttribute(k_cattn, cudaFuncAttributeMaxDynamicSharedMemorySize,
                         CATTN_SMEM);
    cudaFuncSetAttribute(k_gemm_proj, cudaFuncAttributeMaxDynamicSharedMemorySize,
                         GS_BYTES);
    cudaFuncSetAttribute(k_gemm_out, cudaFuncAttributeMaxDynamicSharedMemorySize,
                         GS_BYTES);

    k_weights<<<dim3(4, 4, 2), 256>>>(basis, vc, oc);
    k_split<<<MROWS * Cc / 4 / 256, 256>>>(x);
    k_splitT<<<dim3(16, 16, 2), dim3(32, 32)>>>(wq, wk);

    k_gemm_proj<<<dim3(Cc / 128, MROWS / 128, 3), 256, GS_BYTES>>>();
    k_norm<<<MROWS, 256>>>();

    k_state<<<dim3(NCH - 1, Hc, Bc), 256, STATE_SMEM>>>(dlog);
    k_scan<<<dim3(16, 16), 256>>>(dlog);
    k_cattn<<<dim3(NCH, Hc, Bc), 256, CATTN_SMEM>>>(dlog);

    k_gemm_out<<<dim3(Vc / 128, MROWS / 128), 256, GS_BYTES>>>(out, oscal);
}

// round 13
// speedup vs baseline: 1.3866x; 1.1784x over previous
#include <cuda_runtime.h>
#include <cuda_fp16.h>
#include <cstdint>

// Problem constants
#define Bc 4
#define Tc 2048
#define Vc 512
#define Cc 512
#define Hc 4
#define Dc 128
#define NBc 128
#define MROWS (Bc*Tc)    // 8192
#define NCH 32
#define CHL 64

// fp32 scratch
__device__ float g_q[MROWS*Cc];
__device__ float g_k[MROWS*Cc];
__device__ float g_stA[(size_t)16*NCH*Dc*Dc];   // A^T per chunk

// fp16 scratch
__device__ __half g_xh[MROWS*Cc];                // x single fp16
__device__ __half g_rh[MROWS*Cc];                // r single fp16
__device__ __half g_qnh[MROWS*Cc];               // q single fp16
__device__ __half g_knh[MROWS*Cc], g_knl[MROWS*Cc];
__device__ __half g_vsh[MROWS*Cc], g_vsl[MROWS*Cc];
__device__ __half g_wqTh[Cc*Vc];
__device__ __half g_wkTh[Cc*Vc];
__device__ __half g_vwTh[Cc*Vc];
__device__ __half g_owh[Vc*Cc];
__device__ __half g_sTh[(size_t)16*NCH*Dc*Dc];  // T^T single fp16 [bh][c][e][d]

// ===========================================================================
// Helpers
// ===========================================================================
__device__ __forceinline__ uint32_t smem_u32(const void* p) {
    uint32_t a;
    asm("{ .reg .u64 t; cvta.to.shared.u64 t, %1; cvt.u32.u64 %0, t; }"
        : "=r"(a) : "l"(p));
    return a;
}
__device__ __forceinline__ void ldm_x4(uint32_t* r, uint32_t addr) {
    asm volatile("ldmatrix.sync.aligned.m8n8.x4.shared.b16 {%0,%1,%2,%3}, [%4];"
                 : "=r"(r[0]), "=r"(r[1]), "=r"(r[2]), "=r"(r[3]) : "r"(addr));
}
__device__ __forceinline__ void mma_f16(float* c, const uint32_t* a,
                                        const uint32_t* b) {
    asm volatile(
        "mma.sync.aligned.m16n8k16.row.col.f32.f16.f16.f32 "
        "{%0,%1,%2,%3}, {%4,%5,%6,%7}, {%8,%9}, {%0,%1,%2,%3};"
        : "+f"(c[0]), "+f"(c[1]), "+f"(c[2]), "+f"(c[3])
        : "r"(a[0]), "r"(a[1]), "r"(a[2]), "r"(a[3]), "r"(b[0]), "r"(b[1]));
}
__device__ __forceinline__ void cp16(uint32_t dst, const void* src) {
    asm volatile("cp.async.cg.shared.global [%0], [%1], 16;"
                 :: "r"(dst), "l"(src));
}
__device__ __forceinline__ void cp_commit() {
    asm volatile("cp.async.commit_group;");
}
template <int N>
__device__ __forceinline__ void cp_wait() {
    asm volatile("cp.async.wait_group %0;" :: "n"(N));
}
__device__ __forceinline__ void split2(float v, __half& h, __half& l) {
    h = __float2half_rn(v);
    l = __float2half_rn(v - __half2float(h));
}

// ===========================================================================
// 1-pass single-fp16 warp-MMA GEMM (K-slab 64, 2-stage double buffer).
// C[128,128] = A[M,512]@B[N,512]^T. A single, B single.
// ===========================================================================
#define GSLAB 18432                 // 128 rows * 144B
#define GBUF  (2 * GSLAB)           // 36864 (A, B)
#define GS_BYTES (2 * GBUF)         // 73728

__device__ __forceinline__ void gemm_mma_tile(
    const __half* __restrict__ Ah, const __half* __restrict__ Bh,
    float* __restrict__ Cp, __half* __restrict__ Oh, __half* __restrict__ Ol,
    float alpha, int tm, int tn)
{
    extern __shared__ __align__(16) char smc[];
    const int tid = threadIdx.x, lane = tid & 31, wid = tid >> 5;
    const int wm = wid >> 2, wn = wid & 3;
    const uint32_t sb = smem_u32(smc);

    float acc[4][4][4];
#pragma unroll
    for (int i = 0; i < 4; i++)
#pragma unroll
        for (int j = 0; j < 4; j++)
#pragma unroll
            for (int q = 0; q < 4; q++) acc[i][j][q] = 0.f;

    const __half* bases[2];
    bases[0] = Ah + ((size_t)tm * 128) * 512;
    bases[1] = Bh + ((size_t)tn * 128) * 512;

    auto issue = [&](int c, int buf) {
        const uint32_t bb = sb + buf * GBUF;
#pragma unroll
        for (int s = 0; s < 2; s++) {
            const __half* src = bases[s] + c * 64;
#pragma unroll
            for (int i = 0; i < 4; i++) {
                const int idx = tid + 256 * i;
                const int row = idx >> 3, q = idx & 7;
                cp16(bb + s * GSLAB + row * 144 + q * 16,
                     src + (size_t)row * 512 + q * 8);
            }
        }
        cp_commit();
    };

    issue(0, 0);
    issue(1, 1);

    const uint32_t a_lrow = wm * 64 + (lane & 15);
    const uint32_t a_koff = (lane >> 4) * 8;
    const uint32_t b_lrow = wn * 32 + (lane & 7) + ((lane >> 4) << 3);
    const uint32_t b_koff = ((lane >> 3) & 1) * 8;

    for (int c = 0; c < 8; c++) {
        if (c == 7) cp_wait<0>(); else cp_wait<1>();
        __syncthreads();
        const uint32_t bb = sb + (c & 1) * GBUF;

#pragma unroll
        for (int ks = 0; ks < 4; ks++) {
            const int k0 = ks * 16;
            uint32_t bh[8];
#pragma unroll
            for (int nf = 0; nf < 2; nf++) {
                const uint32_t boff =
                    (b_lrow + nf * 16) * 144 + (k0 + b_koff) * 2;
                ldm_x4(bh + nf * 4, bb + GSLAB + boff);
            }
#pragma unroll
            for (int mi = 0; mi < 4; mi++) {
                const uint32_t aoff =
                    (a_lrow + mi * 16) * 144 + (k0 + a_koff) * 2;
                uint32_t ah[4];
                ldm_x4(ah, bb + aoff);
#pragma unroll
                for (int ni = 0; ni < 4; ni++)
                    mma_f16(acc[mi][ni], ah, bh + ni * 2);
            }
        }
        __syncthreads();
        if (c + 2 < 8) issue(c + 2, c & 1);
    }

    const int qr = lane >> 2, qc = lane & 3;
#pragma unroll
    for (int mi = 0; mi < 4; mi++) {
#pragma unroll
        for (int ni = 0; ni < 4; ni++) {
            const int m = tm * 128 + wm * 64 + mi * 16 + qr;
            const int n = tn * 128 + wn * 32 + ni * 8 + qc * 2;
            float o0 = acc[mi][ni][0] * alpha, o1 = acc[mi][ni][1] * alpha;
            float o2 = acc[mi][ni][2] * alpha, o3 = acc[mi][ni][3] * alpha;
            if (Cp) {
                float2 v0, v1;
                v0.x = o0; v0.y = o1; v1.x = o2; v1.y = o3;
                *(float2*)(Cp + (size_t)m * 512 + n)       = v0;
                *(float2*)(Cp + (size_t)(m + 8) * 512 + n) = v1;
            } else {
                __half h0, l0, h1, l1, h2, l2, h3, l3;
                split2(o0, h0, l0); split2(o1, h1, l1);
                split2(o2, h2, l2); split2(o3, h3, l3);
                __half2 p;
                p.x = h0; p.y = h1;
                *(__half2*)(Oh + (size_t)m * 512 + n) = p;
                p.x = l0; p.y = l1;
                *(__half2*)(Ol + (size_t)m * 512 + n) = p;
                p.x = h2; p.y = h3;
                *(__half2*)(Oh + (size_t)(m + 8) * 512 + n) = p;
                p.x = l2; p.y = l3;
                *(__half2*)(Ol + (size_t)(m + 8) * 512 + n) = p;
            }
        }
    }
}

__global__ void __launch_bounds__(256) k_gemm_proj()
{
    if (blockIdx.z == 0)
        gemm_mma_tile(g_xh, g_wqTh, g_q, nullptr, nullptr, 1.f,
                      blockIdx.y, blockIdx.x);
    else if (blockIdx.z == 1)
        gemm_mma_tile(g_xh, g_wkTh, g_k, nullptr, nullptr, 1.f,
                      blockIdx.y, blockIdx.x);
    else
        gemm_mma_tile(g_xh, g_vwTh, nullptr, g_vsh, g_vsl, 1.f,
                      blockIdx.y, blockIdx.x);
}

__global__ void __launch_bounds__(256) k_gemm_out(float* __restrict__ out,
                                                  const float* __restrict__ os)
{
    gemm_mma_tile(g_rh, g_owh, out, nullptr, nullptr, __ldg(os),
                  blockIdx.y, blockIdx.x);
}

// ===========================================================================
// x -> single fp16
// ===========================================================================
__global__ void __launch_bounds__(256) k_split(const float* __restrict__ in)
{
    int i = blockIdx.x * 256 + threadIdx.x;
    float4 v = ((const float4*)in)[i];
    __half2 p;
    p.x = __float2half_rn(v.x); p.y = __float2half_rn(v.y);
    ((__half2*)g_xh)[2 * i]     = p;
    p.x = __float2half_rn(v.z); p.y = __float2half_rn(v.w);
    ((__half2*)g_xh)[2 * i + 1] = p;
}

// Transpose 512x512 weights -> single fp16 (wq, wk)
__global__ void __launch_bounds__(1024) k_splitT(const float* __restrict__ wq,
                                                 const float* __restrict__ wk)
{
    __shared__ float t[32][33];
    const float* in = (blockIdx.z == 0) ? wq : wk;
    __half* oh = (blockIdx.z == 0) ? g_wqTh : g_wkTh;
    const int x = blockIdx.x * 32 + threadIdx.x;
    const int y = blockIdx.y * 32 + threadIdx.y;
    t[threadIdx.y][threadIdx.x] = in[y * 512 + x];
    __syncthreads();
    const float v = t[threadIdx.x][threadIdx.y];
    const int ox = blockIdx.y * 32 + threadIdx.x;
    const int oy = blockIdx.x * 32 + threadIdx.y;
    oh[oy * 512 + ox] = __float2half_rn(v);
}

// ===========================================================================
// k_weights: z=0: vwT[c][v] = vc @ basis^T ; z=1: ow[v][c] = basis @ oc^T
// ===========================================================================
__global__ void __launch_bounds__(256) k_weights(
    const float* __restrict__ basis, const float* __restrict__ vc,
    const float* __restrict__ oc)
{
    __shared__ float As[8][132];
    __shared__ float Bs[8][132];
    const int z = blockIdx.z;
    const float* A = z ? basis : vc;
    const float* B = z ? oc : basis;
    __half* Oh = z ? g_owh : g_vwTh;
    const int bx = blockIdx.x, by = blockIdx.y;
    const int tid = threadIdx.x;
    const int tx = tid & 15, ty = tid >> 4;

    float acc[8][8];
#pragma unroll
    for (int i = 0; i < 8; i++)
#pragma unroll
        for (int j = 0; j < 8; j++) acc[i][j] = 0.f;

    const float* Ab = A + (size_t)(by * 128) * NBc;

    for (int k0 = 0; k0 < NBc; k0 += 8) {
        {
            const int ar = tid >> 1, ac = (tid & 1) * 4;
            float4 v = *(const float4*)(Ab + (size_t)ar * NBc + k0 + ac);
            As[ac + 0][ar] = v.x; As[ac + 1][ar] = v.y;
            As[ac + 2][ar] = v.z; As[ac + 3][ar] = v.w;
        }
        {
            const int br = tid >> 1, bc = (tid & 1) * 4;
            float4 v = *(const float4*)(B + (size_t)(bx * 128 + br) * NBc + k0 + bc);
            Bs[bc + 0][br] = v.x; Bs[bc + 1][br] = v.y;
            Bs[bc + 2][br] = v.z; Bs[bc + 3][br] = v.w;
        }
        __syncthreads();

#pragma unroll
        for (int kk = 0; kk < 8; kk++) {
            float a[8], bf[8];
            *(float4*)(a)     = *(const float4*)&As[kk][ty * 8];
            *(float4*)(a + 4) = *(const float4*)&As[kk][ty * 8 + 4];
            *(float4*)(bf)     = *(const float4*)&Bs[kk][tx * 8];
            *(float4*)(bf + 4) = *(const float4*)&Bs[kk][tx * 8 + 4];
#pragma unroll
            for (int i = 0; i < 8; i++)
#pragma unroll
                for (int j = 0; j < 8; j++) acc[i][j] += a[i] * bf[j];
        }
        __syncthreads();
    }

#pragma unroll
    for (int i = 0; i < 8; i++) {
        const size_t rowb = (size_t)(by * 128 + ty * 8 + i) * 512 + bx * 128 + tx * 8;
#pragma unroll
        for (int j = 0; j < 8; j += 2) {
            __half2 p;
            p.x = __float2half_rn(acc[i][j]);
            p.y = __float2half_rn(acc[i][j + 1]);
            *(__half2*)(Oh + rowb + j) = p;
        }
    }
}

// L2-normalize rows of g_q/g_k; q -> single fp16, k -> fp16 hi/lo
__global__ void __launch_bounds__(256) k_norm()
{
    const int row = blockIdx.x;
    const float* q = g_q + (size_t)row * Cc;
    const float* k = g_k + (size_t)row * Cc;
    const int t = threadIdx.x;
    float q0 = q[t], q1 = q[t + 256];
    float k0 = k[t], k1 = k[t + 256];
    float sq = q0 * q0 + q1 * q1;
    float sk = k0 * k0 + k1 * k1;
#pragma unroll
    for (int off = 16; off; off >>= 1) {
        sq += __shfl_xor_sync(0xffffffffu, sq, off);
        sk += __shfl_xor_sync(0xffffffffu, sk, off);
    }
    __shared__ float rq[8], rk[8];
    __shared__ float inv[2];
    const int w = t >> 5, l = t & 31;
    if (l == 0) { rq[w] = sq; rk[w] = sk; }
    __syncthreads();
    if (t == 0) {
        float a = 0.f, cc = 0.f;
#pragma unroll
        for (int i = 0; i < 8; i++) { a += rq[i]; cc += rk[i]; }
        inv[0] = 1.f / fmaxf(sqrtf(a), 1e-12f);
        inv[1] = 1.f / fmaxf(sqrtf(cc), 1e-12f);
    }
    __syncthreads();
    const float iq = inv[0], ik = inv[1];
    __half h, lo;
    const size_t b = (size_t)row * Cc;
    g_qnh[b + t]       = __float2half_rn(q0 * iq);
    g_qnh[b + t + 256] = __float2half_rn(q1 * iq);
    split2(k0 * ik, h, lo); g_knh[b + t] = h;       g_knl[b + t] = lo;
    split2(k1 * ik, h, lo); g_knh[b + t + 256] = h; g_knl[b + t + 256] = lo;
}

// ===========================================================================
// Phase A (MMA): A^T_c[e][d] = sum_j V[j][e] * (d^j K[j][d])
// ===========================================================================
#define ST_K  0
#define ST_VH 18432
#define ST_VL 36864
#define STATE_SMEM 55296

__global__ void __launch_bounds__(256) k_state(const float* __restrict__ dlog)
{
    extern __shared__ __align__(16) char sm[];
    const int c = blockIdx.x + 1, h = blockIdx.y, b = blockIdx.z;
    const int tid = threadIdx.x, lane = tid & 31, wid = tid >> 5;
    const float dec = 1.f / (1.f + expf(-dlog[h]));
    const float l2d = log2f(dec);
    const size_t gb = ((size_t)b * Tc + c * CHL) * Cc + h * Dc;

#pragma unroll
    for (int it = 0; it < 2; it++) {
        const int idx = tid + 256 * it;          // 0..511
        const int jp = idx & 31;                 // j-pair 0..31
        const int d0 = (idx >> 5) * 8;           // 0..120
        const int j0 = jp * 2;
        const size_t r0 = gb + (size_t)j0 * Cc + d0;
        const size_t r1 = r0 + Cc;
        uint4 kh0 = *(const uint4*)(g_knh + r0);
        uint4 kl0 = *(const uint4*)(g_knl + r0);
        uint4 kh1 = *(const uint4*)(g_knh + r1);
        uint4 kl1 = *(const uint4*)(g_knl + r1);
        uint4 vh0 = *(const uint4*)(g_vsh + r0);
        uint4 vh1 = *(const uint4*)(g_vsh + r1);
        uint4 vl0 = *(const uint4*)(g_vsl + r0);
        uint4 vl1 = *(const uint4*)(g_vsl + r1);
        const __half* pkh0 = (const __half*)&kh0;
        const __half* pkl0 = (const __half*)&kl0;
        const __half* pkh1 = (const __half*)&kh1;
        const __half* pkl1 = (const __half*)&kl1;
        const __half* pvh0 = (const __half*)&vh0;
        const __half* pvh1 = (const __half*)&vh1;
        const __half* pvl0 = (const __half*)&vl0;
        const __half* pvl1 = (const __half*)&vl1;
        const float e0 = exp2f(l2d * (float)j0);
        const float e1 = e0 * dec;
#pragma unroll
        for (int u = 0; u < 8; u++) {
            const uint32_t off = (d0 + u) * 144 + jp * 4;
            const float k0v = __half2float(pkh0[u]) + __half2float(pkl0[u]);
            const float k1v = __half2float(pkh1[u]) + __half2float(pkl1[u]);
            __half2 p;
            p.x = __float2half_rn(k0v * e0);
            p.y = __float2half_rn(k1v * e1);
            *(__half2*)(sm + ST_K + off) = p;
            p.x = pvh0[u]; p.y = pvh1[u];
            *(__half2*)(sm + ST_VH + off) = p;
            p.x = pvl0[u]; p.y = pvl1[u];
            *(__half2*)(sm + ST_VL + off) = p;
        }
    }
    __syncthreads();

    const int wm = wid >> 2, wn = wid & 3;
    const uint32_t sb = smem_u32(sm);
    const uint32_t a_lrow = wm * 64 + (lane & 15);
    const uint32_t a_koff = (lane >> 4) * 8;
    const uint32_t b_lrow = wn * 32 + (lane & 7) + ((lane >> 4) << 3);
    const uint32_t b_koff = ((lane >> 3) & 1) * 8;

    float acc[4][4][4];
#pragma unroll
    for (int i = 0; i < 4; i++)
#pragma unroll
        for (int j = 0; j < 4; j++)
#pragma unroll
            for (int q = 0; q < 4; q++) acc[i][j][q] = 0.f;

#pragma unroll
    for (int ks = 0; ks < 4; ks++) {
        const int k0 = ks * 16;
        uint32_t kh[8];
#pragma unroll
        for (int nf = 0; nf < 2; nf++) {
            const uint32_t boff = (b_lrow + nf * 16) * 144 + (k0 + b_koff) * 2;
            ldm_x4(kh + nf * 4, sb + ST_K + boff);
        }
#pragma unroll
        for (int mi = 0; mi < 4; mi++) {
            uint32_t vh[4], vl[4];
            const uint32_t aoff = (a_lrow + mi * 16) * 144 + (k0 + a_koff) * 2;
            ldm_x4(vh, sb + ST_VH + aoff);
            ldm_x4(vl, sb + ST_VL + aoff);
#pragma unroll
            for (int ni = 0; ni < 4; ni++) {
                mma_f16(acc[mi][ni], vh, kh + ni * 2);
                mma_f16(acc[mi][ni], vl, kh + ni * 2);
            }
        }
    }

    float* dst = g_stA + ((size_t)(b * Hc + h) * NCH + c) * (Dc * Dc);
    const int qr = lane >> 2, qc = lane & 3;
#pragma unroll
    for (int mi = 0; mi < 4; mi++) {
#pragma unroll
        for (int ni = 0; ni < 4; ni++) {
            const int m = wm * 64 + mi * 16 + qr;
            const int n = wn * 32 + ni * 8 + qc * 2;
            float2 v0, v1;
            v0.x = acc[mi][ni][0]; v0.y = acc[mi][ni][1];
            v1.x = acc[mi][ni][2]; v1.y = acc[mi][ni][3];
            *(float2*)(dst + (size_t)m * Dc + n)       = v0;
            *(float2*)(dst + (size_t)(m + 8) * Dc + n) = v1;
        }
    }
}

// ===========================================================================
// Phase B: backward scan on A^T, writes single-fp16 T^T.
// ===========================================================================
__global__ void __launch_bounds__(256) k_scan(const float* __restrict__ dlog)
{
    const int bh = blockIdx.x;
    const int h = bh & (Hc - 1);
    const int idx4 = blockIdx.y * 256 + threadIdx.x;   // 0..4095
    const float dec = 1.f / (1.f + expf(-dlog[h]));
    const float dL = exp2f(log2f(dec) * (float)CHL);

    float4 run = make_float4(0.f, 0.f, 0.f, 0.f);
    for (int c = NCH - 2; c >= 0; c--) {
        const float4* A =
            (const float4*)(g_stA + ((size_t)bh * NCH + c + 1) * (Dc * Dc));
        float4 a = A[idx4];
        run.x = a.x + dL * run.x;
        run.y = a.y + dL * run.y;
        run.z = a.z + dL * run.z;
        run.w = a.w + dL * run.w;
        const size_t o = ((size_t)bh * NCH + c) * (Dc * Dc) + (size_t)idx4 * 4;
        __half2 p;
        p.x = __float2half_rn(run.x); p.y = __float2half_rn(run.y);
        *(__half2*)(g_sTh + o) = p;
        p.x = __float2half_rn(run.z); p.y = __float2half_rn(run.w);
        *(__half2*)(g_sTh + o + 2) = p;
    }
}

// ===========================================================================
// Phase C (MMA): all-single operands, 1-pass MMAs.
// CQ 17408 | CK 17408 | CV 18432 | CS 9216 | CT 34816 => 97280, 2 CTAs/SM.
// ===========================================================================
#define CQ   0
#define CK   17408
#define CV   34816
#define CS   53248
#define CT   62464
#define CATTN_SMEM 97280

__global__ void __launch_bounds__(256) k_cattn(const float* __restrict__ dlog)
{
    extern __shared__ __align__(16) char sm[];
    const int c = blockIdx.x, h = blockIdx.y, b = blockIdx.z;
    const int tid = threadIdx.x, lane = tid & 31, wid = tid >> 5;
    const int wm = wid >> 2, wn = wid & 3;
    const float dec = 1.f / (1.f + expf(-dlog[h]));
    const float l2d = log2f(dec);
    const size_t gb = ((size_t)b * Tc + c * CHL) * Cc + h * Dc;
    const uint32_t sb = smem_u32(sm);

    // Prefetch full T^T (single fp16) with cp.async
    if (c < NCH - 1) {
        const __half* Th = g_sTh + ((size_t)(b * Hc + h) * NCH + c) * (Dc * Dc);
#pragma unroll
        for (int i = 0; i < 8; i++) {
            const int idx = tid + 256 * i;           // 0..2047
            const int e = idx >> 4, q = idx & 15;
            cp16(sb + CT + e * 272 + q * 16, Th + (size_t)e * 128 + q * 8);
        }
    }
    cp_commit();

    // Q single, K single tiles 64x128 pitch 272B
    {
        const uint4* s0 = (const uint4*)(g_qnh + gb);
        const uint4* s2 = (const uint4*)(g_knh + gb);
#pragma unroll
        for (int i = 0; i < 4; i++) {
            const int idx = tid + 256 * i;
            const int row = idx >> 4, q = idx & 15;
            const size_t so = (size_t)row * 64 + q;
            const uint32_t doff = row * 272 + q * 16;
            *(uint4*)(sm + CQ + doff) = s0[so];
            *(uint4*)(sm + CK + doff) = s2[so];
        }
    }
    // Transposed V (single): VT[d][j] pitch 144B — vectorized staging
#pragma unroll
    for (int it = 0; it < 2; it++) {
        const int idx = tid + 256 * it;
        const int jp = idx & 31;
        const int d0 = (idx >> 5) * 8;
        const int j0 = jp * 2;
        const size_t r0 = gb + (size_t)j0 * Cc + d0;
        uint4 a0 = *(const uint4*)(g_vsh + r0);
        uint4 a1 = *(const uint4*)(g_vsh + r0 + Cc);
        const __half* p0 = (const __half*)&a0;
        const __half* p1 = (const __half*)&a1;
#pragma unroll
        for (int u = 0; u < 8; u++) {
            __half2 p; p.x = p0[u]; p.y = p1[u];
            *(__half2*)(sm + CV + (d0 + u) * 144 + jp * 4) = p;
        }
    }
    __syncthreads();

    const uint32_t a_koff = (lane >> 4) * 8;
    const uint32_t b_koff = ((lane >> 3) & 1) * 8;
    const uint32_t aQ_row = wm * 32 + (lane & 15);
    const uint32_t bS_row = wn * 16 + (lane & 7) + ((lane >> 4) << 3);
    const uint32_t bO_row = wn * 32 + (lane & 7) + ((lane >> 4) << 3);
    const int qr = lane >> 2, qc = lane & 3;

    // ---- intra: S = Q K^T (1 pass) ----
    float accS[2][2][4];
#pragma unroll
    for (int i = 0; i < 2; i++)
#pragma unroll
        for (int j = 0; j < 2; j++)
#pragma unroll
            for (int q = 0; q < 4; q++) accS[i][j][q] = 0.f;

#pragma unroll
    for (int ks = 0; ks < 8; ks++) {
        const int k0 = ks * 16;
        uint32_t kh[4];
        const uint32_t boff = bS_row * 272 + (k0 + b_koff) * 2;
        ldm_x4(kh, sb + CK + boff);
#pragma unroll
        for (int mi = 0; mi < 2; mi++) {
            uint32_t qh[4];
            const uint32_t aoff = (aQ_row + mi * 16) * 272 + (k0 + a_koff) * 2;
            ldm_x4(qh, sb + CQ + aoff);
#pragma unroll
            for (int ni = 0; ni < 2; ni++)
                mma_f16(accS[mi][ni], qh, kh + ni * 2);
        }
    }

    // mask + store S (single fp16)
#pragma unroll
    for (int mi = 0; mi < 2; mi++) {
#pragma unroll
        for (int ni = 0; ni < 2; ni++) {
#pragma unroll
            for (int q = 0; q < 4; q++) {
                const int il = wm * 32 + mi * 16 + qr + (q >> 1) * 8;
                const int jl = wn * 16 + ni * 8 + qc * 2 + (q & 1);
                float s = 0.f;
                if (jl > il)
                    s = accS[mi][ni][q] * exp2f(l2d * (float)(jl - il - 1));
                *(__half*)(sm + CS + il * 144 + jl * 2) = __float2half_rn(s);
            }
        }
    }
    cp_wait<0>();
    __syncthreads();

    // ---- O accumulators ----
    float acc[2][4][4], accI[2][4][4];
#pragma unroll
    for (int i = 0; i < 2; i++)
#pragma unroll
        for (int j = 0; j < 4; j++)
#pragma unroll
            for (int q = 0; q < 4; q++) { acc[i][j][q] = 0.f; accI[i][j][q] = 0.f; }

    // intra SV: single x single (1 pass), K=64
#pragma unroll
    for (int ks = 0; ks < 4; ks++) {
        const int k0 = ks * 16;
        uint32_t vh[8];
#pragma unroll
        for (int nf = 0; nf < 2; nf++) {
            const uint32_t boff = (bO_row + nf * 16) * 144 + (k0 + b_koff) * 2;
            ldm_x4(vh + nf * 4, sb + CV + boff);
        }
#pragma unroll
        for (int mi = 0; mi < 2; mi++) {
            uint32_t sh[4];
            const uint32_t aoff = (aQ_row + mi * 16) * 144 + (k0 + a_koff) * 2;
            ldm_x4(sh, sb + CS + aoff);
#pragma unroll
            for (int ni = 0; ni < 4; ni++)
                mma_f16(acc[mi][ni], sh, vh + ni * 2);
        }
    }

    // inter: O_i += Q @ T^T (single x single), K=128
    if (c < NCH - 1) {
#pragma unroll
        for (int ks = 0; ks < 8; ks++) {
            const int k0 = ks * 16;
            uint32_t th[8];
#pragma unroll
            for (int nf = 0; nf < 2; nf++) {
                const uint32_t boff =
                    (bO_row + nf * 16) * 272 + (k0 + b_koff) * 2;
                ldm_x4(th + nf * 4, sb + CT + boff);
            }
#pragma unroll
            for (int mi = 0; mi < 2; mi++) {
                uint32_t qh[4];
                const uint32_t aoff =
                    (aQ_row + mi * 16) * 272 + (k0 + a_koff) * 2;
                ldm_x4(qh, sb + CQ + aoff);
#pragma unroll
                for (int ni = 0; ni < 4; ni++)
                    mma_f16(accI[mi][ni], qh, th + ni * 2);
            }
        }
    }

    // epilogue: O = acc + f(row) * accI -> single fp16 write g_rh
#pragma unroll
    for (int mi = 0; mi < 2; mi++) {
        const int r0 = wm * 32 + mi * 16 + qr;
        const float f0 = exp2f(l2d * (float)(63 - r0));
        const float f1 = exp2f(l2d * (float)(63 - (r0 + 8)));
#pragma unroll
        for (int ni = 0; ni < 4; ni++) {
            const int col = wn * 32 + ni * 8 + qc * 2;
            const size_t a0 = gb + (size_t)r0 * Cc + col;
            const size_t a1 = gb + (size_t)(r0 + 8) * Cc + col;
            __half2 p;
            p.x = __float2half_rn(acc[mi][ni][0] + f0 * accI[mi][ni][0]);
            p.y = __float2half_rn(acc[mi][ni][1] + f0 * accI[mi][ni][1]);
            *(__half2*)(g_rh + a0) = p;
            p.x = __float2half_rn(acc[mi][ni][2] + f1 * accI[mi][ni][2]);
            p.y = __float2half_rn(acc[mi][ni][3] + f1 * accI[mi][ni][3]);
            *(__half2*)(g_rh + a1) = p;
        }
    }
}

extern "C" void kernel_launch(void* const* d_in, const int* in_sizes, int n_in,
                              void* d_out, int out_size)
{
    const float* x     = (const float*)d_in[0];
    const float* basis = (const float*)d_in[1];
    const float* wq    = (const float*)d_in[2];
    const float* wk    = (const float*)d_in[3];
    const float* vc    = (const float*)d_in[4];
    const float* oc    = (const float*)d_in[5];
    const float* dlog  = (const float*)d_in[6];
    const float* oscal = (const float*)d_in[7];
    float* out = (float*)d_out;

    (void)in_sizes; (void)n_in; (void)out_size;

    cudaFuncSetAttribute(k_state, cudaFuncAttributeMaxDynamicSharedMemorySize,
                         STATE_SMEM);
    cudaFuncSetAttribute(k_cattn, cudaFuncAttributeMaxDynamicSharedMemorySize,
                         CATTN_SMEM);
    cudaFuncSetAttribute(k_gemm_proj, cudaFuncAttributeMaxDynamicSharedMemorySize,
                         GS_BYTES);
    cudaFuncSetAttribute(k_gemm_out, cudaFuncAttributeMaxDynamicSharedMemorySize,
                         GS_BYTES);

    k_weights<<<dim3(4, 4, 2), 256>>>(basis, vc, oc);
    k_split<<<MROWS * Cc / 4 / 256, 256>>>(x);
    k_splitT<<<dim3(16, 16, 2), dim3(32, 32)>>>(wq, wk);

    k_gemm_proj<<<dim3(Cc / 128, MROWS / 128, 3), 256, GS_BYTES>>>();
    k_norm<<<MROWS, 256>>>();

    k_state<<<dim3(NCH - 1, Hc, Bc), 256, STATE_SMEM>>>(dlog);
    k_scan<<<dim3(16, 16), 256>>>(dlog);
    k_cattn<<<dim3(NCH, Hc, Bc), 256, CATTN_SMEM>>>(dlog);

    k_gemm_out<<<dim3(Vc / 128, MROWS / 128), 256, GS_BYTES>>>(out, oscal);
}

// round 14
// speedup vs baseline: 1.4787x; 1.0665x over previous
#include <cuda_runtime.h>
#include <cuda_fp16.h>
#include <cstdint>

// Problem constants
#define Bc 4
#define Tc 2048
#define Vc 512
#define Cc 512
#define Hc 4
#define Dc 128
#define NBc 128
#define MROWS (Bc*Tc)    // 8192
#define NCH 32
#define CHL 64

// fp32 scratch
__device__ float g_q[MROWS*Cc];
__device__ float g_k[MROWS*Cc];
__device__ float g_stA[(size_t)16*NCH*Dc*Dc];   // A^T per chunk

// fp16 scratch
__device__ __half g_xh[MROWS*Cc];                // x single fp16
__device__ __half g_rh[MROWS*Cc];                // r single fp16
__device__ __half g_qnh[MROWS*Cc];               // q single fp16
__device__ __half g_knh[MROWS*Cc], g_knl[MROWS*Cc];
__device__ __half g_vsh[MROWS*Cc], g_vsl[MROWS*Cc];
__device__ __half g_wqTh[Cc*Vc];
__device__ __half g_wkTh[Cc*Vc];
__device__ __half g_vwTh[Cc*Vc];
__device__ __half g_owh[Vc*Cc];
__device__ __half g_sTh[(size_t)16*NCH*Dc*Dc];  // T^T single fp16 [bh][c][e][d]

// ===========================================================================
// Helpers
// ===========================================================================
__device__ __forceinline__ uint32_t smem_u32(const void* p) {
    uint32_t a;
    asm("{ .reg .u64 t; cvta.to.shared.u64 t, %1; cvt.u32.u64 %0, t; }"
        : "=r"(a) : "l"(p));
    return a;
}
__device__ __forceinline__ void ldm_x4(uint32_t* r, uint32_t addr) {
    asm volatile("ldmatrix.sync.aligned.m8n8.x4.shared.b16 {%0,%1,%2,%3}, [%4];"
                 : "=r"(r[0]), "=r"(r[1]), "=r"(r[2]), "=r"(r[3]) : "r"(addr));
}
__device__ __forceinline__ void mma_f16(float* c, const uint32_t* a,
                                        const uint32_t* b) {
    asm volatile(
        "mma.sync.aligned.m16n8k16.row.col.f32.f16.f16.f32 "
        "{%0,%1,%2,%3}, {%4,%5,%6,%7}, {%8,%9}, {%0,%1,%2,%3};"
        : "+f"(c[0]), "+f"(c[1]), "+f"(c[2]), "+f"(c[3])
        : "r"(a[0]), "r"(a[1]), "r"(a[2]), "r"(a[3]), "r"(b[0]), "r"(b[1]));
}
__device__ __forceinline__ void cp16(uint32_t dst, const void* src) {
    asm volatile("cp.async.cg.shared.global [%0], [%1], 16;"
                 :: "r"(dst), "l"(src));
}
__device__ __forceinline__ void cp_commit() {
    asm volatile("cp.async.commit_group;");
}
template <int N>
__device__ __forceinline__ void cp_wait() {
    asm volatile("cp.async.wait_group %0;" :: "n"(N));
}
__device__ __forceinline__ void split2(float v, __half& h, __half& l) {
    h = __float2half_rn(v);
    l = __float2half_rn(v - __half2float(h));
}

// ===========================================================================
// 1-pass single-fp16 warp-MMA GEMM. K-slab 64, 3-STAGE pipeline, ONE sync
// per iteration (8 barriers total). C[128,128] = A[M,512]@B[N,512]^T.
// ===========================================================================
#define GSLAB 18432                 // 128 rows * 144B
#define GBUF  (2 * GSLAB)           // 36864 (A, B)
#define GS_BYTES (3 * GBUF)         // 110592 (3 stages)

__device__ __forceinline__ void gemm_mma_tile(
    const __half* __restrict__ Ah, const __half* __restrict__ Bh,
    float* __restrict__ Cp, __half* __restrict__ Oh, __half* __restrict__ Ol,
    float alpha, int tm, int tn)
{
    extern __shared__ __align__(16) char smc[];
    const int tid = threadIdx.x, lane = tid & 31, wid = tid >> 5;
    const int wm = wid >> 2, wn = wid & 3;
    const uint32_t sb = smem_u32(smc);

    float acc[4][4][4];
#pragma unroll
    for (int i = 0; i < 4; i++)
#pragma unroll
        for (int j = 0; j < 4; j++)
#pragma unroll
            for (int q = 0; q < 4; q++) acc[i][j][q] = 0.f;

    const __half* bases[2];
    bases[0] = Ah + ((size_t)tm * 128) * 512;
    bases[1] = Bh + ((size_t)tn * 128) * 512;

    auto issue = [&](int c, int stage) {
        const uint32_t bb = sb + stage * GBUF;
#pragma unroll
        for (int s = 0; s < 2; s++) {
            const __half* src = bases[s] + c * 64;
#pragma unroll
            for (int i = 0; i < 4; i++) {
                const int idx = tid + 256 * i;
                const int row = idx >> 3, q = idx & 7;
                cp16(bb + s * GSLAB + row * 144 + q * 16,
                     src + (size_t)row * 512 + q * 8);
            }
        }
        cp_commit();
    };

    issue(0, 0);
    issue(1, 1);

    const uint32_t a_lrow = wm * 64 + (lane & 15);
    const uint32_t a_koff = (lane >> 4) * 8;
    const uint32_t b_lrow = wn * 32 + (lane & 7) + ((lane >> 4) << 3);
    const uint32_t b_koff = ((lane >> 3) & 1) * 8;

    int stage = 0;
    for (int c = 0; c < 8; c++) {
        if (c == 7) cp_wait<0>(); else cp_wait<1>();
        __syncthreads();
        const uint32_t bb = sb + stage * GBUF;

#pragma unroll
        for (int ks = 0; ks < 4; ks++) {
            const int k0 = ks * 16;
            uint32_t bh[8];
#pragma unroll
            for (int nf = 0; nf < 2; nf++) {
                const uint32_t boff =
                    (b_lrow + nf * 16) * 144 + (k0 + b_koff) * 2;
                ldm_x4(bh + nf * 4, bb + GSLAB + boff);
            }
#pragma unroll
            for (int mi = 0; mi < 4; mi++) {
                const uint32_t aoff =
                    (a_lrow + mi * 16) * 144 + (k0 + a_koff) * 2;
                uint32_t ah[4];
                ldm_x4(ah, bb + aoff);
#pragma unroll
                for (int ni = 0; ni < 4; ni++)
                    mma_f16(acc[mi][ni], ah, bh + ni * 2);
            }
        }
        // Write stage (c+2)%3 == (c-1)%3: its reads (iter c-1) completed
        // before this iteration's __syncthreads, so one barrier suffices.
        if (c + 2 < 8) issue(c + 2, (c + 2) % 3);
        stage = (stage + 1) % 3;
    }

    const int qr = lane >> 2, qc = lane & 3;
#pragma unroll
    for (int mi = 0; mi < 4; mi++) {
#pragma unroll
        for (int ni = 0; ni < 4; ni++) {
            const int m = tm * 128 + wm * 64 + mi * 16 + qr;
            const int n = tn * 128 + wn * 32 + ni * 8 + qc * 2;
            float o0 = acc[mi][ni][0] * alpha, o1 = acc[mi][ni][1] * alpha;
            float o2 = acc[mi][ni][2] * alpha, o3 = acc[mi][ni][3] * alpha;
            if (Cp) {
                float2 v0, v1;
                v0.x = o0; v0.y = o1; v1.x = o2; v1.y = o3;
                *(float2*)(Cp + (size_t)m * 512 + n)       = v0;
                *(float2*)(Cp + (size_t)(m + 8) * 512 + n) = v1;
            } else {
                __half h0, l0, h1, l1, h2, l2, h3, l3;
                split2(o0, h0, l0); split2(o1, h1, l1);
                split2(o2, h2, l2); split2(o3, h3, l3);
                __half2 p;
                p.x = h0; p.y = h1;
                *(__half2*)(Oh + (size_t)m * 512 + n) = p;
                p.x = l0; p.y = l1;
                *(__half2*)(Ol + (size_t)m * 512 + n) = p;
                p.x = h2; p.y = h3;
                *(__half2*)(Oh + (size_t)(m + 8) * 512 + n) = p;
                p.x = l2; p.y = l3;
                *(__half2*)(Ol + (size_t)(m + 8) * 512 + n) = p;
            }
        }
    }
}

__global__ void __launch_bounds__(256) k_gemm_proj()
{
    if (blockIdx.z == 0)
        gemm_mma_tile(g_xh, g_wqTh, g_q, nullptr, nullptr, 1.f,
                      blockIdx.y, blockIdx.x);
    else if (blockIdx.z == 1)
        gemm_mma_tile(g_xh, g_wkTh, g_k, nullptr, nullptr, 1.f,
                      blockIdx.y, blockIdx.x);
    else
        gemm_mma_tile(g_xh, g_vwTh, nullptr, g_vsh, g_vsl, 1.f,
                      blockIdx.y, blockIdx.x);
}

__global__ void __launch_bounds__(256) k_gemm_out(float* __restrict__ out,
                                                  const float* __restrict__ os)
{
    gemm_mma_tile(g_rh, g_owh, out, nullptr, nullptr, __ldg(os),
                  blockIdx.y, blockIdx.x);
}

// ===========================================================================
// k_prep: fused prep, LONG POLE (weights GEMMs) FIRST.
//  blocks [0, 32)       : weights GEMMs -> g_vwTh (vc@basis^T), g_owh
//  blocks [32, 544)     : transpose wq/wk -> single fp16
//  blocks [544, 4640)   : x -> single fp16
// ===========================================================================
#define PREP_W_BLKS   32
#define PREP_TR_BLKS  512
#define PREP_SPLIT_BLKS 4096
#define PREP_BLKS (PREP_W_BLKS + PREP_TR_BLKS + PREP_SPLIT_BLKS)

__global__ void __launch_bounds__(256) k_prep(
    const float* __restrict__ x, const float* __restrict__ wq,
    const float* __restrict__ wk, const float* __restrict__ basis,
    const float* __restrict__ vc, const float* __restrict__ oc)
{
    __shared__ __align__(16) float shmem[2 * 8 * 132];  // 8448B (>= 32*33*4)
    const int blk = blockIdx.x;
    const int tid = threadIdx.x;

    if (blk < PREP_W_BLKS) {
        // ---- weights GEMMs (scheduled first) ----
        float (*As)[132] = (float(*)[132])shmem;
        float (*Bs)[132] = (float(*)[132])(shmem + 8 * 132);
        const int z = blk >> 4;                 // 0: vwT, 1: ow
        const int bx = blk & 3, by = (blk >> 2) & 3;
        const float* A = z ? basis : vc;
        const float* B = z ? oc : basis;
        __half* Oh = z ? g_owh : g_vwTh;
        const int tx = tid & 15, ty = tid >> 4;

        float acc[8][8];
#pragma unroll
        for (int i = 0; i < 8; i++)
#pragma unroll
            for (int j = 0; j < 8; j++) acc[i][j] = 0.f;

        const float* Ab = A + (size_t)(by * 128) * NBc;

        for (int k0 = 0; k0 < NBc; k0 += 8) {
            {
                const int ar = tid >> 1, ac = (tid & 1) * 4;
                float4 v = *(const float4*)(Ab + (size_t)ar * NBc + k0 + ac);
                As[ac + 0][ar] = v.x; As[ac + 1][ar] = v.y;
                As[ac + 2][ar] = v.z; As[ac + 3][ar] = v.w;
            }
            {
                const int br = tid >> 1, bc = (tid & 1) * 4;
                float4 v = *(const float4*)(B + (size_t)(bx * 128 + br) * NBc + k0 + bc);
                Bs[bc + 0][br] = v.x; Bs[bc + 1][br] = v.y;
                Bs[bc + 2][br] = v.z; Bs[bc + 3][br] = v.w;
            }
            __syncthreads();

#pragma unroll
            for (int kk = 0; kk < 8; kk++) {
                float a[8], bf[8];
                *(float4*)(a)     = *(const float4*)&As[kk][ty * 8];
                *(float4*)(a + 4) = *(const float4*)&As[kk][ty * 8 + 4];
                *(float4*)(bf)     = *(const float4*)&Bs[kk][tx * 8];
                *(float4*)(bf + 4) = *(const float4*)&Bs[kk][tx * 8 + 4];
#pragma unroll
                for (int i = 0; i < 8; i++)
#pragma unroll
                    for (int j = 0; j < 8; j++) acc[i][j] += a[i] * bf[j];
            }
            __syncthreads();
        }

#pragma unroll
        for (int i = 0; i < 8; i++) {
            const size_t rowb =
                (size_t)(by * 128 + ty * 8 + i) * 512 + bx * 128 + tx * 8;
#pragma unroll
            for (int j = 0; j < 8; j += 2) {
                __half2 p;
                p.x = __float2half_rn(acc[i][j]);
                p.y = __float2half_rn(acc[i][j + 1]);
                *(__half2*)(Oh + rowb + j) = p;
            }
        }
        return;
    }

    if (blk < PREP_W_BLKS + PREP_TR_BLKS) {
        // ---- transpose wq/wk 32x32 tile -> fp16 ----
        float (*t)[33] = (float(*)[33])shmem;
        const int tb = blk - PREP_W_BLKS;
        const int z = tb >> 8;                 // 0: wq, 1: wk
        const int tile = tb & 255;
        const int bx = tile & 15, by = tile >> 4;
        const float* in = z ? wk : wq;
        __half* oh = z ? g_wkTh : g_wqTh;
        const int i = tid & 31, ty = tid >> 5;
#pragma unroll
        for (int r = 0; r < 4; r++) {
            const int j = ty + 8 * r;
            t[j][i] = in[(size_t)(by * 32 + j) * 512 + bx * 32 + i];
        }
        __syncthreads();
#pragma unroll
        for (int r = 0; r < 4; r++) {
            const int a = ty + 8 * r;
            oh[(size_t)(bx * 32 + a) * 512 + by * 32 + i] =
                __float2half_rn(t[i][a]);
        }
        return;
    }

    // ---- split x -> single fp16 ----
    {
        const int i = (blk - PREP_W_BLKS - PREP_TR_BLKS) * 256 + tid;
        float4 v = ((const float4*)x)[i];
        __half2 p;
        p.x = __float2half_rn(v.x); p.y = __float2half_rn(v.y);
        ((__half2*)g_xh)[2 * i]     = p;
        p.x = __float2half_rn(v.z); p.y = __float2half_rn(v.w);
        ((__half2*)g_xh)[2 * i + 1] = p;
    }
}

// L2-normalize rows of g_q/g_k; q -> single fp16, k -> fp16 hi/lo
__global__ void __launch_bounds__(256) k_norm()
{
    const int row = blockIdx.x;
    const float* q = g_q + (size_t)row * Cc;
    const float* k = g_k + (size_t)row * Cc;
    const int t = threadIdx.x;
    float q0 = q[t], q1 = q[t + 256];
    float k0 = k[t], k1 = k[t + 256];
    float sq = q0 * q0 + q1 * q1;
    float sk = k0 * k0 + k1 * k1;
#pragma unroll
    for (int off = 16; off; off >>= 1) {
        sq += __shfl_xor_sync(0xffffffffu, sq, off);
        sk += __shfl_xor_sync(0xffffffffu, sk, off);
    }
    __shared__ float rq[8], rk[8];
    __shared__ float inv[2];
    const int w = t >> 5, l = t & 31;
    if (l == 0) { rq[w] = sq; rk[w] = sk; }
    __syncthreads();
    if (t == 0) {
        float a = 0.f, cc = 0.f;
#pragma unroll
        for (int i = 0; i < 8; i++) { a += rq[i]; cc += rk[i]; }
        inv[0] = 1.f / fmaxf(sqrtf(a), 1e-12f);
        inv[1] = 1.f / fmaxf(sqrtf(cc), 1e-12f);
    }
    __syncthreads();
    const float iq = inv[0], ik = inv[1];
    __half h, lo;
    const size_t b = (size_t)row * Cc;
    g_qnh[b + t]       = __float2half_rn(q0 * iq);
    g_qnh[b + t + 256] = __float2half_rn(q1 * iq);
    split2(k0 * ik, h, lo); g_knh[b + t] = h;       g_knl[b + t] = lo;
    split2(k1 * ik, h, lo); g_knh[b + t + 256] = h; g_knl[b + t + 256] = lo;
}

// ===========================================================================
// Phase A (MMA): A^T_c[e][d] = sum_j V[j][e] * (d^j K[j][d])
// ===========================================================================
#define ST_K  0
#define ST_VH 18432
#define ST_VL 36864
#define STATE_SMEM 55296

__global__ void __launch_bounds__(256) k_state(const float* __restrict__ dlog)
{
    extern __shared__ __align__(16) char sm[];
    const int c = blockIdx.x + 1, h = blockIdx.y, b = blockIdx.z;
    const int tid = threadIdx.x, lane = tid & 31, wid = tid >> 5;
    const float dec = 1.f / (1.f + expf(-dlog[h]));
    const float l2d = log2f(dec);
    const size_t gb = ((size_t)b * Tc + c * CHL) * Cc + h * Dc;

#pragma unroll
    for (int it = 0; it < 2; it++) {
        const int idx = tid + 256 * it;          // 0..511
        const int jp = idx & 31;                 // j-pair 0..31
        const int d0 = (idx >> 5) * 8;           // 0..120
        const int j0 = jp * 2;
        const size_t r0 = gb + (size_t)j0 * Cc + d0;
        const size_t r1 = r0 + Cc;
        uint4 kh0 = *(const uint4*)(g_knh + r0);
        uint4 kl0 = *(const uint4*)(g_knl + r0);
        uint4 kh1 = *(const uint4*)(g_knh + r1);
        uint4 kl1 = *(const uint4*)(g_knl + r1);
        uint4 vh0 = *(const uint4*)(g_vsh + r0);
        uint4 vh1 = *(const uint4*)(g_vsh + r1);
        uint4 vl0 = *(const uint4*)(g_vsl + r0);
        uint4 vl1 = *(const uint4*)(g_vsl + r1);
        const __half* pkh0 = (const __half*)&kh0;
        const __half* pkl0 = (const __half*)&kl0;
        const __half* pkh1 = (const __half*)&kh1;
        const __half* pkl1 = (const __half*)&kl1;
        const __half* pvh0 = (const __half*)&vh0;
        const __half* pvh1 = (const __half*)&vh1;
        const __half* pvl0 = (const __half*)&vl0;
        const __half* pvl1 = (const __half*)&vl1;
        const float e0 = exp2f(l2d * (float)j0);
        const float e1 = e0 * dec;
#pragma unroll
        for (int u = 0; u < 8; u++) {
            const uint32_t off = (d0 + u) * 144 + jp * 4;
            const float k0v = __half2float(pkh0[u]) + __half2float(pkl0[u]);
            const float k1v = __half2float(pkh1[u]) + __half2float(pkl1[u]);
            __half2 p;
            p.x = __float2half_rn(k0v * e0);
            p.y = __float2half_rn(k1v * e1);
            *(__half2*)(sm + ST_K + off) = p;
            p.x = pvh0[u]; p.y = pvh1[u];
            *(__half2*)(sm + ST_VH + off) = p;
            p.x = pvl0[u]; p.y = pvl1[u];
            *(__half2*)(sm + ST_VL + off) = p;
        }
    }
    __syncthreads();

    const int wm = wid >> 2, wn = wid & 3;
    const uint32_t sb = smem_u32(sm);
    const uint32_t a_lrow = wm * 64 + (lane & 15);
    const uint32_t a_koff = (lane >> 4) * 8;
    const uint32_t b_lrow = wn * 32 + (lane & 7) + ((lane >> 4) << 3);
    const uint32_t b_koff = ((lane >> 3) & 1) * 8;

    float acc[4][4][4];
#pragma unroll
    for (int i = 0; i < 4; i++)
#pragma unroll
        for (int j = 0; j < 4; j++)
#pragma unroll
            for (int q = 0; q < 4; q++) acc[i][j][q] = 0.f;

#pragma unroll
    for (int ks = 0; ks < 4; ks++) {
        const int k0 = ks * 16;
        uint32_t kh[8];
#pragma unroll
        for (int nf = 0; nf < 2; nf++) {
            const uint32_t boff = (b_lrow + nf * 16) * 144 + (k0 + b_koff) * 2;
            ldm_x4(kh + nf * 4, sb + ST_K + boff);
        }
#pragma unroll
        for (int mi = 0; mi < 4; mi++) {
            uint32_t vh[4], vl[4];
            const uint32_t aoff = (a_lrow + mi * 16) * 144 + (k0 + a_koff) * 2;
            ldm_x4(vh, sb + ST_VH + aoff);
            ldm_x4(vl, sb + ST_VL + aoff);
#pragma unroll
            for (int ni = 0; ni < 4; ni++) {
                mma_f16(acc[mi][ni], vh, kh + ni * 2);
                mma_f16(acc[mi][ni], vl, kh + ni * 2);
            }
        }
    }

    float* dst = g_stA + ((size_t)(b * Hc + h) * NCH + c) * (Dc * Dc);
    const int qr = lane >> 2, qc = lane & 3;
#pragma unroll
    for (int mi = 0; mi < 4; mi++) {
#pragma unroll
        for (int ni = 0; ni < 4; ni++) {
            const int m = wm * 64 + mi * 16 + qr;
            const int n = wn * 32 + ni * 8 + qc * 2;
            float2 v0, v1;
            v0.x = acc[mi][ni][0]; v0.y = acc[mi][ni][1];
            v1.x = acc[mi][ni][2]; v1.y = acc[mi][ni][3];
            *(float2*)(dst + (size_t)m * Dc + n)       = v0;
            *(float2*)(dst + (size_t)(m + 8) * Dc + n) = v1;
        }
    }
}

// ===========================================================================
// Phase B: backward scan on A^T, writes single-fp16 T^T.
// ===========================================================================
__global__ void __launch_bounds__(256) k_scan(const float* __restrict__ dlog)
{
    const int bh = blockIdx.x;
    const int h = bh & (Hc - 1);
    const int idx4 = blockIdx.y * 256 + threadIdx.x;   // 0..4095
    const float dec = 1.f / (1.f + expf(-dlog[h]));
    const float dL = exp2f(log2f(dec) * (float)CHL);

    float4 run = make_float4(0.f, 0.f, 0.f, 0.f);
    for (int c = NCH - 2; c >= 0; c--) {
        const float4* A =
            (const float4*)(g_stA + ((size_t)bh * NCH + c + 1) * (Dc * Dc));
        float4 a = A[idx4];
        run.x = a.x + dL * run.x;
        run.y = a.y + dL * run.y;
        run.z = a.z + dL * run.z;
        run.w = a.w + dL * run.w;
        const size_t o = ((size_t)bh * NCH + c) * (Dc * Dc) + (size_t)idx4 * 4;
        __half2 p;
        p.x = __float2half_rn(run.x); p.y = __float2half_rn(run.y);
        *(__half2*)(g_sTh + o) = p;
        p.x = __float2half_rn(run.z); p.y = __float2half_rn(run.w);
        *(__half2*)(g_sTh + o + 2) = p;
    }
}

// ===========================================================================
// Phase C (MMA): all-single operands, 1-pass MMAs.
// CQ 17408 | CK 17408 | CV 18432 | CS 9216 | CT 34816 => 97280, 2 CTAs/SM.
// ===========================================================================
#define CQ   0
#define CK   17408
#define CV   34816
#define CS   53248
#define CT   62464
#define CATTN_SMEM 97280

__global__ void __launch_bounds__(256) k_cattn(const float* __restrict__ dlog)
{
    extern __shared__ __align__(16) char sm[];
    const int c = blockIdx.x, h = blockIdx.y, b = blockIdx.z;
    const int tid = threadIdx.x, lane = tid & 31, wid = tid >> 5;
    const int wm = wid >> 2, wn = wid & 3;
    const float dec = 1.f / (1.f + expf(-dlog[h]));
    const float l2d = log2f(dec);
    const size_t gb = ((size_t)b * Tc + c * CHL) * Cc + h * Dc;
    const uint32_t sb = smem_u32(sm);

    // Prefetch full T^T (single fp16) with cp.async
    if (c < NCH - 1) {
        const __half* Th = g_sTh + ((size_t)(b * Hc + h) * NCH + c) * (Dc * Dc);
#pragma unroll
        for (int i = 0; i < 8; i++) {
            const int idx = tid + 256 * i;           // 0..2047
            const int e = idx >> 4, q = idx & 15;
            cp16(sb + CT + e * 272 + q * 16, Th + (size_t)e * 128 + q * 8);
        }
    }
    cp_commit();

    // Q single, K single tiles 64x128 pitch 272B
    {
        const uint4* s0 = (const uint4*)(g_qnh + gb);
        const uint4* s2 = (const uint4*)(g_knh + gb);
#pragma unroll
        for (int i = 0; i < 4; i++) {
            const int idx = tid + 256 * i;
            const int row = idx >> 4, q = idx & 15;
            const size_t so = (size_t)row * 64 + q;
            const uint32_t doff = row * 272 + q * 16;
            *(uint4*)(sm + CQ + doff) = s0[so];
            *(uint4*)(sm + CK + doff) = s2[so];
        }
    }
    // Transposed V (single): VT[d][j] pitch 144B — vectorized staging
#pragma unroll
    for (int it = 0; it < 2; it++) {
        const int idx = tid + 256 * it;
        const int jp = idx & 31;
        const int d0 = (idx >> 5) * 8;
        const int j0 = jp * 2;
        const size_t r0 = gb + (size_t)j0 * Cc + d0;
        uint4 a0 = *(const uint4*)(g_vsh + r0);
        uint4 a1 = *(const uint4*)(g_vsh + r0 + Cc);
        const __half* p0 = (const __half*)&a0;
        const __half* p1 = (const __half*)&a1;
#pragma unroll
        for (int u = 0; u < 8; u++) {
            __half2 p; p.x = p0[u]; p.y = p1[u];
            *(__half2*)(sm + CV + (d0 + u) * 144 + jp * 4) = p;
        }
    }
    __syncthreads();

    const uint32_t a_koff = (lane >> 4) * 8;
    const uint32_t b_koff = ((lane >> 3) & 1) * 8;
    const uint32_t aQ_row = wm * 32 + (lane & 15);
    const uint32_t bS_row = wn * 16 + (lane & 7) + ((lane >> 4) << 3);
    const uint32_t bO_row = wn * 32 + (lane & 7) + ((lane >> 4) << 3);
    const int qr = lane >> 2, qc = lane & 3;

    // ---- intra: S = Q K^T (1 pass) ----
    float accS[2][2][4];
#pragma unroll
    for (int i = 0; i < 2; i++)
#pragma unroll
        for (int j = 0; j < 2; j++)
#pragma unroll
            for (int q = 0; q < 4; q++) accS[i][j][q] = 0.f;

#pragma unroll
    for (int ks = 0; ks < 8; ks++) {
        const int k0 = ks * 16;
        uint32_t kh[4];
        const uint32_t boff = bS_row * 272 + (k0 + b_koff) * 2;
        ldm_x4(kh, sb + CK + boff);
#pragma unroll
        for (int mi = 0; mi < 2; mi++) {
            uint32_t qh[4];
            const uint32_t aoff = (aQ_row + mi * 16) * 272 + (k0 + a_koff) * 2;
            ldm_x4(qh, sb + CQ + aoff);
#pragma unroll
            for (int ni = 0; ni < 2; ni++)
                mma_f16(accS[mi][ni], qh, kh + ni * 2);
        }
    }

    // mask + store S (single fp16)
#pragma unroll
    for (int mi = 0; mi < 2; mi++) {
#pragma unroll
        for (int ni = 0; ni < 2; ni++) {
#pragma unroll
            for (int q = 0; q < 4; q++) {
                const int il = wm * 32 + mi * 16 + qr + (q >> 1) * 8;
                const int jl = wn * 16 + ni * 8 + qc * 2 + (q & 1);
                float s = 0.f;
                if (jl > il)
                    s = accS[mi][ni][q] * exp2f(l2d * (float)(jl - il - 1));
                *(__half*)(sm + CS + il * 144 + jl * 2) = __float2half_rn(s);
            }
        }
    }
    cp_wait<0>();
    __syncthreads();

    // ---- O accumulators ----
    float acc[2][4][4], accI[2][4][4];
#pragma unroll
    for (int i = 0; i < 2; i++)
#pragma unroll
        for (int j = 0; j < 4; j++)
#pragma unroll
            for (int q = 0; q < 4; q++) { acc[i][j][q] = 0.f; accI[i][j][q] = 0.f; }

    // intra SV: single x single (1 pass), K=64
#pragma unroll
    for (int ks = 0; ks < 4; ks++) {
        const int k0 = ks * 16;
        uint32_t vh[8];
#pragma unroll
        for (int nf = 0; nf < 2; nf++) {
            const uint32_t boff = (bO_row + nf * 16) * 144 + (k0 + b_koff) * 2;
            ldm_x4(vh + nf * 4, sb + CV + boff);
        }
#pragma unroll
        for (int mi = 0; mi < 2; mi++) {
            uint32_t sh[4];
            const uint32_t aoff = (aQ_row + mi * 16) * 144 + (k0 + a_koff) * 2;
            ldm_x4(sh, sb + CS + aoff);
#pragma unroll
            for (int ni = 0; ni < 4; ni++)
                mma_f16(acc[mi][ni], sh, vh + ni * 2);
        }
    }

    // inter: O_i += Q @ T^T (single x single), K=128
    if (c < NCH - 1) {
#pragma unroll
        for (int ks = 0; ks < 8; ks++) {
            const int k0 = ks * 16;
            uint32_t th[8];
#pragma unroll
            for (int nf = 0; nf < 2; nf++) {
                const uint32_t boff =
                    (bO_row + nf * 16) * 272 + (k0 + b_koff) * 2;
                ldm_x4(th + nf * 4, sb + CT + boff);
            }
#pragma unroll
            for (int mi = 0; mi < 2; mi++) {
                uint32_t qh[4];
                const uint32_t aoff =
                    (aQ_row + mi * 16) * 272 + (k0 + a_koff) * 2;
                ldm_x4(qh, sb + CQ + aoff);
#pragma unroll
                for (int ni = 0; ni < 4; ni++)
                    mma_f16(accI[mi][ni], qh, th + ni * 2);
            }
        }
    }

    // epilogue: O = acc + f(row) * accI -> single fp16 write g_rh
#pragma unroll
    for (int mi = 0; mi < 2; mi++) {
        const int r0 = wm * 32 + mi * 16 + qr;
        const float f0 = exp2f(l2d * (float)(63 - r0));
        const float f1 = exp2f(l2d * (float)(63 - (r0 + 8)));
#pragma unroll
        for (int ni = 0; ni < 4; ni++) {
            const int col = wn * 32 + ni * 8 + qc * 2;
            const size_t a0 = gb + (size_t)r0 * Cc + col;
            const size_t a1 = gb + (size_t)(r0 + 8) * Cc + col;
            __half2 p;
            p.x = __float2half_rn(acc[mi][ni][0] + f0 * accI[mi][ni][0]);
            p.y = __float2half_rn(acc[mi][ni][1] + f0 * accI[mi][ni][1]);
            *(__half2*)(g_rh + a0) = p;
            p.x = __float2half_rn(acc[mi][ni][2] + f1 * accI[mi][ni][2]);
            p.y = __float2half_rn(acc[mi][ni][3] + f1 * accI[mi][ni][3]);
            *(__half2*)(g_rh + a1) = p;
        }
    }
}

extern "C" void kernel_launch(void* const* d_in, const int* in_sizes, int n_in,
                              void* d_out, int out_size)
{
    const float* x     = (const float*)d_in[0];
    const float* basis = (const float*)d_in[1];
    const float* wq    = (const float*)d_in[2];
    const float* wk    = (const float*)d_in[3];
    const float* vc    = (const float*)d_in[4];
    const float* oc    = (const float*)d_in[5];
    const float* dlog  = (const float*)d_in[6];
    const float* oscal = (const float*)d_in[7];
    float* out = (float*)d_out;

    (void)in_sizes; (void)n_in; (void)out_size;

    cudaFuncSetAttribute(k_state, cudaFuncAttributeMaxDynamicSharedMemorySize,
                         STATE_SMEM);
    cudaFuncSetAttribute(k_cattn, cudaFuncAttributeMaxDynamicSharedMemorySize,
                         CATTN_SMEM);
    cudaFuncSetAttribute(k_gemm_proj, cudaFuncAttributeMaxDynamicSharedMemorySize,
                         GS_BYTES);
    cudaFuncSetAttribute(k_gemm_out, cudaFuncAttributeMaxDynamicSharedMemorySize,
                         GS_BYTES);

    k_prep<<<PREP_BLKS, 256>>>(x, wq, wk, basis, vc, oc);

    k_gemm_proj<<<dim3(Cc / 128, MROWS / 128, 3), 256, GS_BYTES>>>();
    k_norm<<<MROWS, 256>>>();

    k_state<<<dim3(NCH - 1, Hc, Bc), 256, STATE_SMEM>>>(dlog);
    k_scan<<<dim3(16, 16), 256>>>(dlog);
    k_cattn<<<dim3(NCH, Hc, Bc), 256, CATTN_SMEM>>>(dlog);

    k_gemm_out<<<dim3(Vc / 128, MROWS / 128), 256, GS_BYTES>>>(out, oscal);
}

// round 15
// speedup vs baseline: 1.6040x; 1.0847x over previous
#include <cuda_runtime.h>
#include <cuda_fp16.h>
#include <cstdint>

// Problem constants
#define Bc 4
#define Tc 2048
#define Vc 512
#define Cc 512
#define Hc 4
#define Dc 128
#define NBc 128
#define MROWS (Bc*Tc)    // 8192
#define NCH 32
#define CHL 64

// fp32 scratch
__device__ float g_q[MROWS*Cc];
__device__ float g_k[MROWS*Cc];
__device__ float g_stA[(size_t)16*NCH*Dc*Dc];   // A^T per chunk

// fp16 scratch (ALL single precision operands)
__device__ __half g_xh[MROWS*Cc];
__device__ __half g_rh[MROWS*Cc];
__device__ __half g_qnh[MROWS*Cc];
__device__ __half g_knh[MROWS*Cc];
__device__ __half g_vsh[MROWS*Cc];
__device__ __half g_wqTh[Cc*Vc];
__device__ __half g_wkTh[Cc*Vc];
__device__ __half g_vwTh[Cc*Vc];
__device__ __half g_owh[Vc*Cc];
__device__ __half g_sTh[(size_t)16*NCH*Dc*Dc];  // T^T single fp16 [bh][c][e][d]

// ===========================================================================
// Helpers
// ===========================================================================
__device__ __forceinline__ uint32_t smem_u32(const void* p) {
    uint32_t a;
    asm("{ .reg .u64 t; cvta.to.shared.u64 t, %1; cvt.u32.u64 %0, t; }"
        : "=r"(a) : "l"(p));
    return a;
}
__device__ __forceinline__ void ldm_x4(uint32_t* r, uint32_t addr) {
    asm volatile("ldmatrix.sync.aligned.m8n8.x4.shared.b16 {%0,%1,%2,%3}, [%4];"
                 : "=r"(r[0]), "=r"(r[1]), "=r"(r[2]), "=r"(r[3]) : "r"(addr));
}
__device__ __forceinline__ void mma_f16(float* c, const uint32_t* a,
                                        const uint32_t* b) {
    asm volatile(
        "mma.sync.aligned.m16n8k16.row.col.f32.f16.f16.f32 "
        "{%0,%1,%2,%3}, {%4,%5,%6,%7}, {%8,%9}, {%0,%1,%2,%3};"
        : "+f"(c[0]), "+f"(c[1]), "+f"(c[2]), "+f"(c[3])
        : "r"(a[0]), "r"(a[1]), "r"(a[2]), "r"(a[3]), "r"(b[0]), "r"(b[1]));
}
__device__ __forceinline__ void cp16(uint32_t dst, const void* src) {
    asm volatile("cp.async.cg.shared.global [%0], [%1], 16;"
                 :: "r"(dst), "l"(src));
}
__device__ __forceinline__ void cp_commit() {
    asm volatile("cp.async.commit_group;");
}
template <int N>
__device__ __forceinline__ void cp_wait() {
    asm volatile("cp.async.wait_group %0;" :: "n"(N));
}

// ===========================================================================
// 1-pass single-fp16 warp-MMA GEMM. K-slab 64, 3-stage pipeline, one sync
// per iteration. C[128,128] = A[M,512]@B[N,512]^T.
// ===========================================================================
#define GSLAB 18432                 // 128 rows * 144B
#define GBUF  (2 * GSLAB)           // 36864 (A, B)
#define GS_BYTES (3 * GBUF)         // 110592 (3 stages)

__device__ __forceinline__ void gemm_mma_tile(
    const __half* __restrict__ Ah, const __half* __restrict__ Bh,
    float* __restrict__ Cp, __half* __restrict__ Oh,
    float alpha, int tm, int tn)
{
    extern __shared__ __align__(16) char smc[];
    const int tid = threadIdx.x, lane = tid & 31, wid = tid >> 5;
    const int wm = wid >> 2, wn = wid & 3;
    const uint32_t sb = smem_u32(smc);

    float acc[4][4][4];
#pragma unroll
    for (int i = 0; i < 4; i++)
#pragma unroll
        for (int j = 0; j < 4; j++)
#pragma unroll
            for (int q = 0; q < 4; q++) acc[i][j][q] = 0.f;

    const __half* bases[2];
    bases[0] = Ah + ((size_t)tm * 128) * 512;
    bases[1] = Bh + ((size_t)tn * 128) * 512;

    auto issue = [&](int c, int stage) {
        const uint32_t bb = sb + stage * GBUF;
#pragma unroll
        for (int s = 0; s < 2; s++) {
            const __half* src = bases[s] + c * 64;
#pragma unroll
            for (int i = 0; i < 4; i++) {
                const int idx = tid + 256 * i;
                const int row = idx >> 3, q = idx & 7;
                cp16(bb + s * GSLAB + row * 144 + q * 16,
                     src + (size_t)row * 512 + q * 8);
            }
        }
        cp_commit();
    };

    issue(0, 0);
    issue(1, 1);

    const uint32_t a_lrow = wm * 64 + (lane & 15);
    const uint32_t a_koff = (lane >> 4) * 8;
    const uint32_t b_lrow = wn * 32 + (lane & 7) + ((lane >> 4) << 3);
    const uint32_t b_koff = ((lane >> 3) & 1) * 8;

    int stage = 0;
    for (int c = 0; c < 8; c++) {
        if (c == 7) cp_wait<0>(); else cp_wait<1>();
        __syncthreads();
        const uint32_t bb = sb + stage * GBUF;

#pragma unroll
        for (int ks = 0; ks < 4; ks++) {
            const int k0 = ks * 16;
            uint32_t bh[8];
#pragma unroll
            for (int nf = 0; nf < 2; nf++) {
                const uint32_t boff =
                    (b_lrow + nf * 16) * 144 + (k0 + b_koff) * 2;
                ldm_x4(bh + nf * 4, bb + GSLAB + boff);
            }
#pragma unroll
            for (int mi = 0; mi < 4; mi++) {
                const uint32_t aoff =
                    (a_lrow + mi * 16) * 144 + (k0 + a_koff) * 2;
                uint32_t ah[4];
                ldm_x4(ah, bb + aoff);
#pragma unroll
                for (int ni = 0; ni < 4; ni++)
                    mma_f16(acc[mi][ni], ah, bh + ni * 2);
            }
        }
        if (c + 2 < 8) issue(c + 2, (c + 2) % 3);
        stage = (stage + 1) % 3;
    }

    const int qr = lane >> 2, qc = lane & 3;
#pragma unroll
    for (int mi = 0; mi < 4; mi++) {
#pragma unroll
        for (int ni = 0; ni < 4; ni++) {
            const int m = tm * 128 + wm * 64 + mi * 16 + qr;
            const int n = tn * 128 + wn * 32 + ni * 8 + qc * 2;
            float o0 = acc[mi][ni][0] * alpha, o1 = acc[mi][ni][1] * alpha;
            float o2 = acc[mi][ni][2] * alpha, o3 = acc[mi][ni][3] * alpha;
            if (Cp) {
                float2 v0, v1;
                v0.x = o0; v0.y = o1; v1.x = o2; v1.y = o3;
                *(float2*)(Cp + (size_t)m * 512 + n)       = v0;
                *(float2*)(Cp + (size_t)(m + 8) * 512 + n) = v1;
            } else {
                __half2 p;
                p.x = __float2half_rn(o0); p.y = __float2half_rn(o1);
                *(__half2*)(Oh + (size_t)m * 512 + n) = p;
                p.x = __float2half_rn(o2); p.y = __float2half_rn(o3);
                *(__half2*)(Oh + (size_t)(m + 8) * 512 + n) = p;
            }
        }
    }
}

__global__ void __launch_bounds__(256) k_gemm_proj()
{
    if (blockIdx.z == 0)
        gemm_mma_tile(g_xh, g_wqTh, g_q, nullptr, 1.f, blockIdx.y, blockIdx.x);
    else if (blockIdx.z == 1)
        gemm_mma_tile(g_xh, g_wkTh, g_k, nullptr, 1.f, blockIdx.y, blockIdx.x);
    else
        gemm_mma_tile(g_xh, g_vwTh, nullptr, g_vsh, 1.f, blockIdx.y, blockIdx.x);
}

__global__ void __launch_bounds__(256) k_gemm_out(float* __restrict__ out,
                                                  const float* __restrict__ os)
{
    gemm_mma_tile(g_rh, g_owh, out, nullptr, __ldg(os), blockIdx.y, blockIdx.x);
}

// ===========================================================================
// k_prep: fused prep, long pole (weights GEMMs) first.
// ===========================================================================
#define PREP_W_BLKS   32
#define PREP_TR_BLKS  512
#define PREP_SPLIT_BLKS 4096
#define PREP_BLKS (PREP_W_BLKS + PREP_TR_BLKS + PREP_SPLIT_BLKS)

__global__ void __launch_bounds__(256) k_prep(
    const float* __restrict__ x, const float* __restrict__ wq,
    const float* __restrict__ wk, const float* __restrict__ basis,
    const float* __restrict__ vc, const float* __restrict__ oc)
{
    __shared__ __align__(16) float shmem[2 * 8 * 132];
    const int blk = blockIdx.x;
    const int tid = threadIdx.x;

    if (blk < PREP_W_BLKS) {
        float (*As)[132] = (float(*)[132])shmem;
        float (*Bs)[132] = (float(*)[132])(shmem + 8 * 132);
        const int z = blk >> 4;
        const int bx = blk & 3, by = (blk >> 2) & 3;
        const float* A = z ? basis : vc;
        const float* B = z ? oc : basis;
        __half* Oh = z ? g_owh : g_vwTh;
        const int tx = tid & 15, ty = tid >> 4;

        float acc[8][8];
#pragma unroll
        for (int i = 0; i < 8; i++)
#pragma unroll
            for (int j = 0; j < 8; j++) acc[i][j] = 0.f;

        const float* Ab = A + (size_t)(by * 128) * NBc;

        for (int k0 = 0; k0 < NBc; k0 += 8) {
            {
                const int ar = tid >> 1, ac = (tid & 1) * 4;
                float4 v = *(const float4*)(Ab + (size_t)ar * NBc + k0 + ac);
                As[ac + 0][ar] = v.x; As[ac + 1][ar] = v.y;
                As[ac + 2][ar] = v.z; As[ac + 3][ar] = v.w;
            }
            {
                const int br = tid >> 1, bc = (tid & 1) * 4;
                float4 v = *(const float4*)(B + (size_t)(bx * 128 + br) * NBc + k0 + bc);
                Bs[bc + 0][br] = v.x; Bs[bc + 1][br] = v.y;
                Bs[bc + 2][br] = v.z; Bs[bc + 3][br] = v.w;
            }
            __syncthreads();

#pragma unroll
            for (int kk = 0; kk < 8; kk++) {
                float a[8], bf[8];
                *(float4*)(a)     = *(const float4*)&As[kk][ty * 8];
                *(float4*)(a + 4) = *(const float4*)&As[kk][ty * 8 + 4];
                *(float4*)(bf)     = *(const float4*)&Bs[kk][tx * 8];
                *(float4*)(bf + 4) = *(const float4*)&Bs[kk][tx * 8 + 4];
#pragma unroll
                for (int i = 0; i < 8; i++)
#pragma unroll
                    for (int j = 0; j < 8; j++) acc[i][j] += a[i] * bf[j];
            }
            __syncthreads();
        }

#pragma unroll
        for (int i = 0; i < 8; i++) {
            const size_t rowb =
                (size_t)(by * 128 + ty * 8 + i) * 512 + bx * 128 + tx * 8;
#pragma unroll
            for (int j = 0; j < 8; j += 2) {
                __half2 p;
                p.x = __float2half_rn(acc[i][j]);
                p.y = __float2half_rn(acc[i][j + 1]);
                *(__half2*)(Oh + rowb + j) = p;
            }
        }
        return;
    }

    if (blk < PREP_W_BLKS + PREP_TR_BLKS) {
        float (*t)[33] = (float(*)[33])shmem;
        const int tb = blk - PREP_W_BLKS;
        const int z = tb >> 8;
        const int tile = tb & 255;
        const int bx = tile & 15, by = tile >> 4;
        const float* in = z ? wk : wq;
        __half* oh = z ? g_wkTh : g_wqTh;
        const int i = tid & 31, ty = tid >> 5;
#pragma unroll
        for (int r = 0; r < 4; r++) {
            const int j = ty + 8 * r;
            t[j][i] = in[(size_t)(by * 32 + j) * 512 + bx * 32 + i];
        }
        __syncthreads();
#pragma unroll
        for (int r = 0; r < 4; r++) {
            const int a = ty + 8 * r;
            oh[(size_t)(bx * 32 + a) * 512 + by * 32 + i] =
                __float2half_rn(t[i][a]);
        }
        return;
    }

    {
        const int i = (blk - PREP_W_BLKS - PREP_TR_BLKS) * 256 + tid;
        float4 v = ((const float4*)x)[i];
        __half2 p;
        p.x = __float2half_rn(v.x); p.y = __float2half_rn(v.y);
        ((__half2*)g_xh)[2 * i]     = p;
        p.x = __float2half_rn(v.z); p.y = __float2half_rn(v.w);
        ((__half2*)g_xh)[2 * i + 1] = p;
    }
}

// L2-normalize rows of g_q/g_k; both -> single fp16
__global__ void __launch_bounds__(256) k_norm()
{
    const int row = blockIdx.x;
    const float* q = g_q + (size_t)row * Cc;
    const float* k = g_k + (size_t)row * Cc;
    const int t = threadIdx.x;
    float q0 = q[t], q1 = q[t + 256];
    float k0 = k[t], k1 = k[t + 256];
    float sq = q0 * q0 + q1 * q1;
    float sk = k0 * k0 + k1 * k1;
#pragma unroll
    for (int off = 16; off; off >>= 1) {
        sq += __shfl_xor_sync(0xffffffffu, sq, off);
        sk += __shfl_xor_sync(0xffffffffu, sk, off);
    }
    __shared__ float rq[8], rk[8];
    __shared__ float inv[2];
    const int w = t >> 5, l = t & 31;
    if (l == 0) { rq[w] = sq; rk[w] = sk; }
    __syncthreads();
    if (t == 0) {
        float a = 0.f, cc = 0.f;
#pragma unroll
        for (int i = 0; i < 8; i++) { a += rq[i]; cc += rk[i]; }
        inv[0] = 1.f / fmaxf(sqrtf(a), 1e-12f);
        inv[1] = 1.f / fmaxf(sqrtf(cc), 1e-12f);
    }
    __syncthreads();
    const float iq = inv[0], ik = inv[1];
    const size_t b = (size_t)row * Cc;
    g_qnh[b + t]       = __float2half_rn(q0 * iq);
    g_qnh[b + t + 256] = __float2half_rn(q1 * iq);
    g_knh[b + t]       = __float2half_rn(k0 * ik);
    g_knh[b + t + 256] = __float2half_rn(k1 * ik);
}

// ===========================================================================
// Phase A (MMA): A^T_c[e][d] = sum_j V[j][e] * (d^j K[j][d]) — single/single,
// 1-pass. smem 36.9 KB -> 3 CTAs/SM.
// ===========================================================================
#define ST_K  0
#define ST_V  18432
#define STATE_SMEM 36864

__global__ void __launch_bounds__(256) k_state(const float* __restrict__ dlog)
{
    extern __shared__ __align__(16) char sm[];
    const int c = blockIdx.x + 1, h = blockIdx.y, b = blockIdx.z;
    const int tid = threadIdx.x, lane = tid & 31, wid = tid >> 5;
    const float dec = 1.f / (1.f + expf(-dlog[h]));
    const float l2d = log2f(dec);
    const size_t gb = ((size_t)b * Tc + c * CHL) * Cc + h * Dc;

#pragma unroll
    for (int it = 0; it < 2; it++) {
        const int idx = tid + 256 * it;          // 0..511
        const int jp = idx & 31;                 // j-pair 0..31
        const int d0 = (idx >> 5) * 8;           // 0..120
        const int j0 = jp * 2;
        const size_t r0 = gb + (size_t)j0 * Cc + d0;
        const size_t r1 = r0 + Cc;
        uint4 k0q = *(const uint4*)(g_knh + r0);
        uint4 k1q = *(const uint4*)(g_knh + r1);
        uint4 v0q = *(const uint4*)(g_vsh + r0);
        uint4 v1q = *(const uint4*)(g_vsh + r1);
        const __half* pk0 = (const __half*)&k0q;
        const __half* pk1 = (const __half*)&k1q;
        const __half* pv0 = (const __half*)&v0q;
        const __half* pv1 = (const __half*)&v1q;
        const float e0 = exp2f(l2d * (float)j0);
        const float e1 = e0 * dec;
#pragma unroll
        for (int u = 0; u < 8; u++) {
            const uint32_t off = (d0 + u) * 144 + jp * 4;
            __half2 p;
            p.x = __float2half_rn(__half2float(pk0[u]) * e0);
            p.y = __float2half_rn(__half2float(pk1[u]) * e1);
            *(__half2*)(sm + ST_K + off) = p;
            p.x = pv0[u]; p.y = pv1[u];
            *(__half2*)(sm + ST_V + off) = p;
        }
    }
    __syncthreads();

    const int wm = wid >> 2, wn = wid & 3;
    const uint32_t sb = smem_u32(sm);
    const uint32_t a_lrow = wm * 64 + (lane & 15);
    const uint32_t a_koff = (lane >> 4) * 8;
    const uint32_t b_lrow = wn * 32 + (lane & 7) + ((lane >> 4) << 3);
    const uint32_t b_koff = ((lane >> 3) & 1) * 8;

    float acc[4][4][4];
#pragma unroll
    for (int i = 0; i < 4; i++)
#pragma unroll
        for (int j = 0; j < 4; j++)
#pragma unroll
            for (int q = 0; q < 4; q++) acc[i][j][q] = 0.f;

#pragma unroll
    for (int ks = 0; ks < 4; ks++) {
        const int k0 = ks * 16;
        uint32_t kh[8];
#pragma unroll
        for (int nf = 0; nf < 2; nf++) {
            const uint32_t boff = (b_lrow + nf * 16) * 144 + (k0 + b_koff) * 2;
            ldm_x4(kh + nf * 4, sb + ST_K + boff);
        }
#pragma unroll
        for (int mi = 0; mi < 4; mi++) {
            uint32_t vh[4];
            const uint32_t aoff = (a_lrow + mi * 16) * 144 + (k0 + a_koff) * 2;
            ldm_x4(vh, sb + ST_V + aoff);
#pragma unroll
            for (int ni = 0; ni < 4; ni++)
                mma_f16(acc[mi][ni], vh, kh + ni * 2);
        }
    }

    float* dst = g_stA + ((size_t)(b * Hc + h) * NCH + c) * (Dc * Dc);
    const int qr = lane >> 2, qc = lane & 3;
#pragma unroll
    for (int mi = 0; mi < 4; mi++) {
#pragma unroll
        for (int ni = 0; ni < 4; ni++) {
            const int m = wm * 64 + mi * 16 + qr;
            const int n = wn * 32 + ni * 8 + qc * 2;
            float2 v0, v1;
            v0.x = acc[mi][ni][0]; v0.y = acc[mi][ni][1];
            v1.x = acc[mi][ni][2]; v1.y = acc[mi][ni][3];
            *(float2*)(dst + (size_t)m * Dc + n)       = v0;
            *(float2*)(dst + (size_t)(m + 8) * Dc + n) = v1;
        }
    }
}

// ===========================================================================
// Phase B: backward scan on A^T, writes single-fp16 T^T.
// ===========================================================================
__global__ void __launch_bounds__(256) k_scan(const float* __restrict__ dlog)
{
    const int bh = blockIdx.x;
    const int h = bh & (Hc - 1);
    const int idx4 = blockIdx.y * 256 + threadIdx.x;   // 0..4095
    const float dec = 1.f / (1.f + expf(-dlog[h]));
    const float dL = exp2f(log2f(dec) * (float)CHL);

    float4 run = make_float4(0.f, 0.f, 0.f, 0.f);
    for (int c = NCH - 2; c >= 0; c--) {
        const float4* A =
            (const float4*)(g_stA + ((size_t)bh * NCH + c + 1) * (Dc * Dc));
        float4 a = A[idx4];
        run.x = a.x + dL * run.x;
        run.y = a.y + dL * run.y;
        run.z = a.z + dL * run.z;
        run.w = a.w + dL * run.w;
        const size_t o = ((size_t)bh * NCH + c) * (Dc * Dc) + (size_t)idx4 * 4;
        __half2 p;
        p.x = __float2half_rn(run.x); p.y = __float2half_rn(run.y);
        *(__half2*)(g_sTh + o) = p;
        p.x = __float2half_rn(run.z); p.y = __float2half_rn(run.w);
        *(__half2*)(g_sTh + o + 2) = p;
    }
}

// ===========================================================================
// Phase C (MMA): all-single operands, 1-pass MMAs.
// CQ 17408 | CK 17408 | CV 18432 | CS 9216 | CT 34816 => 97280, 2 CTAs/SM.
// ===========================================================================
#define CQ   0
#define CK   17408
#define CV   34816
#define CS   53248
#define CT   62464
#define CATTN_SMEM 97280

__global__ void __launch_bounds__(256) k_cattn(const float* __restrict__ dlog)
{
    extern __shared__ __align__(16) char sm[];
    const int c = blockIdx.x, h = blockIdx.y, b = blockIdx.z;
    const int tid = threadIdx.x, lane = tid & 31, wid = tid >> 5;
    const int wm = wid >> 2, wn = wid & 3;
    const float dec = 1.f / (1.f + expf(-dlog[h]));
    const float l2d = log2f(dec);
    const size_t gb = ((size_t)b * Tc + c * CHL) * Cc + h * Dc;
    const uint32_t sb = smem_u32(sm);

    // Prefetch full T^T (single fp16) with cp.async
    if (c < NCH - 1) {
        const __half* Th = g_sTh + ((size_t)(b * Hc + h) * NCH + c) * (Dc * Dc);
#pragma unroll
        for (int i = 0; i < 8; i++) {
            const int idx = tid + 256 * i;           // 0..2047
            const int e = idx >> 4, q = idx & 15;
            cp16(sb + CT + e * 272 + q * 16, Th + (size_t)e * 128 + q * 8);
        }
    }
    cp_commit();

    // Q single, K single tiles 64x128 pitch 272B
    {
        const uint4* s0 = (const uint4*)(g_qnh + gb);
        const uint4* s2 = (const uint4*)(g_knh + gb);
#pragma unroll
        for (int i = 0; i < 4; i++) {
            const int idx = tid + 256 * i;
            const int row = idx >> 4, q = idx & 15;
            const size_t so = (size_t)row * 64 + q;
            const uint32_t doff = row * 272 + q * 16;
            *(uint4*)(sm + CQ + doff) = s0[so];
            *(uint4*)(sm + CK + doff) = s2[so];
        }
    }
    // Transposed V (single): VT[d][j] pitch 144B — vectorized staging
#pragma unroll
    for (int it = 0; it < 2; it++) {
        const int idx = tid + 256 * it;
        const int jp = idx & 31;
        const int d0 = (idx >> 5) * 8;
        const int j0 = jp * 2;
        const size_t r0 = gb + (size_t)j0 * Cc + d0;
        uint4 a0 = *(const uint4*)(g_vsh + r0);
        uint4 a1 = *(const uint4*)(g_vsh + r0 + Cc);
        const __half* p0 = (const __half*)&a0;
        const __half* p1 = (const __half*)&a1;
#pragma unroll
        for (int u = 0; u < 8; u++) {
            __half2 p; p.x = p0[u]; p.y = p1[u];
            *(__half2*)(sm + CV + (d0 + u) * 144 + jp * 4) = p;
        }
    }
    __syncthreads();

    const uint32_t a_koff = (lane >> 4) * 8;
    const uint32_t b_koff = ((lane >> 3) & 1) * 8;
    const uint32_t aQ_row = wm * 32 + (lane & 15);
    const uint32_t bS_row = wn * 16 + (lane & 7) + ((lane >> 4) << 3);
    const uint32_t bO_row = wn * 32 + (lane & 7) + ((lane >> 4) << 3);
    const int qr = lane >> 2, qc = lane & 3;

    // ---- intra: S = Q K^T (1 pass) ----
    float accS[2][2][4];
#pragma unroll
    for (int i = 0; i < 2; i++)
#pragma unroll
        for (int j = 0; j < 2; j++)
#pragma unroll
            for (int q = 0; q < 4; q++) accS[i][j][q] = 0.f;

#pragma unroll
    for (int ks = 0; ks < 8; ks++) {
        const int k0 = ks * 16;
        uint32_t kh[4];
        const uint32_t boff = bS_row * 272 + (k0 + b_koff) * 2;
        ldm_x4(kh, sb + CK + boff);
#pragma unroll
        for (int mi = 0; mi < 2; mi++) {
            uint32_t qh[4];
            const uint32_t aoff = (aQ_row + mi * 16) * 272 + (k0 + a_koff) * 2;
            ldm_x4(qh, sb + CQ + aoff);
#pragma unroll
            for (int ni = 0; ni < 2; ni++)
                mma_f16(accS[mi][ni], qh, kh + ni * 2);
        }
    }

    // mask + store S (single fp16)
#pragma unroll
    for (int mi = 0; mi < 2; mi++) {
#pragma unroll
        for (int ni = 0; ni < 2; ni++) {
#pragma unroll
            for (int q = 0; q < 4; q++) {
                const int il = wm * 32 + mi * 16 + qr + (q >> 1) * 8;
                const int jl = wn * 16 + ni * 8 + qc * 2 + (q & 1);
                float s = 0.f;
                if (jl > il)
                    s = accS[mi][ni][q] * exp2f(l2d * (float)(jl - il - 1));
                *(__half*)(sm + CS + il * 144 + jl * 2) = __float2half_rn(s);
            }
        }
    }
    cp_wait<0>();
    __syncthreads();

    // ---- O accumulators ----
    float acc[2][4][4], accI[2][4][4];
#pragma unroll
    for (int i = 0; i < 2; i++)
#pragma unroll
        for (int j = 0; j < 4; j++)
#pragma unroll
            for (int q = 0; q < 4; q++) { acc[i][j][q] = 0.f; accI[i][j][q] = 0.f; }

    // intra SV: single x single (1 pass), K=64
#pragma unroll
    for (int ks = 0; ks < 4; ks++) {
        const int k0 = ks * 16;
        uint32_t vh[8];
#pragma unroll
        for (int nf = 0; nf < 2; nf++) {
            const uint32_t boff = (bO_row + nf * 16) * 144 + (k0 + b_koff) * 2;
            ldm_x4(vh + nf * 4, sb + CV + boff);
        }
#pragma unroll
        for (int mi = 0; mi < 2; mi++) {
            uint32_t sh[4];
            const uint32_t aoff = (aQ_row + mi * 16) * 144 + (k0 + a_koff) * 2;
            ldm_x4(sh, sb + CS + aoff);
#pragma unroll
            for (int ni = 0; ni < 4; ni++)
                mma_f16(acc[mi][ni], sh, vh + ni * 2);
        }
    }

    // inter: O_i += Q @ T^T (single x single), K=128
    if (c < NCH - 1) {
#pragma unroll
        for (int ks = 0; ks < 8; ks++) {
            const int k0 = ks * 16;
            uint32_t th[8];
#pragma unroll
            for (int nf = 0; nf < 2; nf++) {
                const uint32_t boff =
                    (bO_row + nf * 16) * 272 + (k0 + b_koff) * 2;
                ldm_x4(th + nf * 4, sb + CT + boff);
            }
#pragma unroll
            for (int mi = 0; mi < 2; mi++) {
                uint32_t qh[4];
                const uint32_t aoff =
                    (aQ_row + mi * 16) * 272 + (k0 + a_koff) * 2;
                ldm_x4(qh, sb + CQ + aoff);
#pragma unroll
                for (int ni = 0; ni < 4; ni++)
                    mma_f16(accI[mi][ni], qh, th + ni * 2);
            }
        }
    }

    // epilogue: O = acc + f(row) * accI -> single fp16 write g_rh
#pragma unroll
    for (int mi = 0; mi < 2; mi++) {
        const int r0 = wm * 32 + mi * 16 + qr;
        const float f0 = exp2f(l2d * (float)(63 - r0));
        const float f1 = exp2f(l2d * (float)(63 - (r0 + 8)));
#pragma unroll
        for (int ni = 0; ni < 4; ni++) {
            const int col = wn * 32 + ni * 8 + qc * 2;
            const size_t a0 = gb + (size_t)r0 * Cc + col;
            const size_t a1 = gb + (size_t)(r0 + 8) * Cc + col;
            __half2 p;
            p.x = __float2half_rn(acc[mi][ni][0] + f0 * accI[mi][ni][0]);
            p.y = __float2half_rn(acc[mi][ni][1] + f0 * accI[mi][ni][1]);
            *(__half2*)(g_rh + a0) = p;
            p.x = __float2half_rn(acc[mi][ni][2] + f1 * accI[mi][ni][2]);
            p.y = __float2half_rn(acc[mi][ni][3] + f1 * accI[mi][ni][3]);
            *(__half2*)(g_rh + a1) = p;
        }
    }
}

extern "C" void kernel_launch(void* const* d_in, const int* in_sizes, int n_in,
                              void* d_out, int out_size)
{
    const float* x     = (const float*)d_in[0];
    const float* basis = (const float*)d_in[1];
    const float* wq    = (const float*)d_in[2];
    const float* wk    = (const float*)d_in[3];
    const float* vc    = (const float*)d_in[4];
    const float* oc    = (const float*)d_in[5];
    const float* dlog  = (const float*)d_in[6];
    const float* oscal = (const float*)d_in[7];
    float* out = (float*)d_out;

    (void)in_sizes; (void)n_in; (void)out_size;

    cudaFuncSetAttribute(k_state, cudaFuncAttributeMaxDynamicSharedMemorySize,
                         STATE_SMEM);
    cudaFuncSetAttribute(k_cattn, cudaFuncAttributeMaxDynamicSharedMemorySize,
                         CATTN_SMEM);
    cudaFuncSetAttribute(k_gemm_proj, cudaFuncAttributeMaxDynamicSharedMemorySize,
                         GS_BYTES);
    cudaFuncSetAttribute(k_gemm_out, cudaFuncAttributeMaxDynamicSharedMemorySize,
                         GS_BYTES);

    k_prep<<<PREP_BLKS, 256>>>(x, wq, wk, basis, vc, oc);

    k_gemm_proj<<<dim3(Cc / 128, MROWS / 128, 3), 256, GS_BYTES>>>();
    k_norm<<<MROWS, 256>>>();

    k_state<<<dim3(NCH - 1, Hc, Bc), 256, STATE_SMEM>>>(dlog);
    k_scan<<<dim3(16, 16), 256>>>(dlog);
    k_cattn<<<dim3(NCH, Hc, Bc), 256, CATTN_SMEM>>>(dlog);

    k_gemm_out<<<dim3(Vc / 128, MROWS / 128), 256, GS_BYTES>>>(out, oscal);
}

// round 16
// speedup vs baseline: 1.6547x; 1.0316x over previous
#include <cuda_runtime.h>
#include <cuda_fp16.h>
#include <cstdint>

// Problem constants
#define Bc 4
#define Tc 2048
#define Vc 512
#define Cc 512
#define Hc 4
#define Dc 128
#define NBc 128
#define MROWS (Bc*Tc)    // 8192
#define NCH 32
#define CHL 64

// fp32 scratch
__device__ float g_q[MROWS*Cc];
__device__ float g_k[MROWS*Cc];

// fp16 scratch (all single precision operands)
__device__ __half g_stA16[(size_t)16*NCH*Dc*Dc];   // A^T fp16 per chunk
__device__ __half g_xh[MROWS*Cc];
__device__ __half g_rh[MROWS*Cc];
__device__ __half g_qnh[MROWS*Cc];
__device__ __half g_knh[MROWS*Cc];
__device__ __half g_vsh[MROWS*Cc];
__device__ __half g_wqTh[Cc*Vc];
__device__ __half g_wkTh[Cc*Vc];
__device__ __half g_vwTh[Cc*Vc];
__device__ __half g_owh[Vc*Cc];
__device__ __half g_sTh[(size_t)16*NCH*Dc*Dc];  // T^T fp16 [bh][c][e][d]

// ===========================================================================
// Helpers
// ===========================================================================
__device__ __forceinline__ uint32_t smem_u32(const void* p) {
    uint32_t a;
    asm("{ .reg .u64 t; cvta.to.shared.u64 t, %1; cvt.u32.u64 %0, t; }"
        : "=r"(a) : "l"(p));
    return a;
}
__device__ __forceinline__ void ldm_x4(uint32_t* r, uint32_t addr) {
    asm volatile("ldmatrix.sync.aligned.m8n8.x4.shared.b16 {%0,%1,%2,%3}, [%4];"
                 : "=r"(r[0]), "=r"(r[1]), "=r"(r[2]), "=r"(r[3]) : "r"(addr));
}
__device__ __forceinline__ void ldm_x4_t(uint32_t* r, uint32_t addr) {
    asm volatile(
        "ldmatrix.sync.aligned.m8n8.x4.trans.shared.b16 {%0,%1,%2,%3}, [%4];"
        : "=r"(r[0]), "=r"(r[1]), "=r"(r[2]), "=r"(r[3]) : "r"(addr));
}
__device__ __forceinline__ void mma_f16(float* c, const uint32_t* a,
                                        const uint32_t* b) {
    asm volatile(
        "mma.sync.aligned.m16n8k16.row.col.f32.f16.f16.f32 "
        "{%0,%1,%2,%3}, {%4,%5,%6,%7}, {%8,%9}, {%0,%1,%2,%3};"
        : "+f"(c[0]), "+f"(c[1]), "+f"(c[2]), "+f"(c[3])
        : "r"(a[0]), "r"(a[1]), "r"(a[2]), "r"(a[3]), "r"(b[0]), "r"(b[1]));
}
__device__ __forceinline__ void cp16(uint32_t dst, const void* src) {
    asm volatile("cp.async.cg.shared.global [%0], [%1], 16;"
                 :: "r"(dst), "l"(src));
}
__device__ __forceinline__ void cp_commit() {
    asm volatile("cp.async.commit_group;");
}
template <int N>
__device__ __forceinline__ void cp_wait() {
    asm volatile("cp.async.wait_group %0;" :: "n"(N));
}

// ===========================================================================
// 1-pass single-fp16 warp-MMA GEMM. K-slab 64, 3-stage pipeline, one sync
// per iteration. C[128,128] = A[M,512]@B[N,512]^T.
// ===========================================================================
#define GSLAB 18432                 // 128 rows * 144B
#define GBUF  (2 * GSLAB)           // 36864 (A, B)
#define GS_BYTES (3 * GBUF)         // 110592

__device__ __forceinline__ void gemm_mma_tile(
    const __half* __restrict__ Ah, const __half* __restrict__ Bh,
    float* __restrict__ Cp, __half* __restrict__ Oh,
    float alpha, int tm, int tn)
{
    extern __shared__ __align__(16) char smc[];
    const int tid = threadIdx.x, lane = tid & 31, wid = tid >> 5;
    const int wm = wid >> 2, wn = wid & 3;
    const uint32_t sb = smem_u32(smc);

    float acc[4][4][4];
#pragma unroll
    for (int i = 0; i < 4; i++)
#pragma unroll
        for (int j = 0; j < 4; j++)
#pragma unroll
            for (int q = 0; q < 4; q++) acc[i][j][q] = 0.f;

    const __half* bases[2];
    bases[0] = Ah + ((size_t)tm * 128) * 512;
    bases[1] = Bh + ((size_t)tn * 128) * 512;

    auto issue = [&](int c, int stage) {
        const uint32_t bb = sb + stage * GBUF;
#pragma unroll
        for (int s = 0; s < 2; s++) {
            const __half* src = bases[s] + c * 64;
#pragma unroll
            for (int i = 0; i < 4; i++) {
                const int idx = tid + 256 * i;
                const int row = idx >> 3, q = idx & 7;
                cp16(bb + s * GSLAB + row * 144 + q * 16,
                     src + (size_t)row * 512 + q * 8);
            }
        }
        cp_commit();
    };

    issue(0, 0);
    issue(1, 1);

    const uint32_t a_lrow = wm * 64 + (lane & 15);
    const uint32_t a_koff = (lane >> 4) * 8;
    const uint32_t b_lrow = wn * 32 + (lane & 7) + ((lane >> 4) << 3);
    const uint32_t b_koff = ((lane >> 3) & 1) * 8;

    int stage = 0;
    for (int c = 0; c < 8; c++) {
        if (c == 7) cp_wait<0>(); else cp_wait<1>();
        __syncthreads();
        const uint32_t bb = sb + stage * GBUF;

#pragma unroll
        for (int ks = 0; ks < 4; ks++) {
            const int k0 = ks * 16;
            uint32_t bh[8];
#pragma unroll
            for (int nf = 0; nf < 2; nf++) {
                const uint32_t boff =
                    (b_lrow + nf * 16) * 144 + (k0 + b_koff) * 2;
                ldm_x4(bh + nf * 4, bb + GSLAB + boff);
            }
#pragma unroll
            for (int mi = 0; mi < 4; mi++) {
                const uint32_t aoff =
                    (a_lrow + mi * 16) * 144 + (k0 + a_koff) * 2;
                uint32_t ah[4];
                ldm_x4(ah, bb + aoff);
#pragma unroll
                for (int ni = 0; ni < 4; ni++)
                    mma_f16(acc[mi][ni], ah, bh + ni * 2);
            }
        }
        if (c + 2 < 8) issue(c + 2, (c + 2) % 3);
        stage = (stage + 1) % 3;
    }

    const int qr = lane >> 2, qc = lane & 3;
#pragma unroll
    for (int mi = 0; mi < 4; mi++) {
#pragma unroll
        for (int ni = 0; ni < 4; ni++) {
            const int m = tm * 128 + wm * 64 + mi * 16 + qr;
            const int n = tn * 128 + wn * 32 + ni * 8 + qc * 2;
            float o0 = acc[mi][ni][0] * alpha, o1 = acc[mi][ni][1] * alpha;
            float o2 = acc[mi][ni][2] * alpha, o3 = acc[mi][ni][3] * alpha;
            if (Cp) {
                float2 v0, v1;
                v0.x = o0; v0.y = o1; v1.x = o2; v1.y = o3;
                *(float2*)(Cp + (size_t)m * 512 + n)       = v0;
                *(float2*)(Cp + (size_t)(m + 8) * 512 + n) = v1;
            } else {
                __half2 p;
                p.x = __float2half_rn(o0); p.y = __float2half_rn(o1);
                *(__half2*)(Oh + (size_t)m * 512 + n) = p;
                p.x = __float2half_rn(o2); p.y = __float2half_rn(o3);
                *(__half2*)(Oh + (size_t)(m + 8) * 512 + n) = p;
            }
        }
    }
}

__global__ void __launch_bounds__(256) k_gemm_proj()
{
    if (blockIdx.z == 0)
        gemm_mma_tile(g_xh, g_wqTh, g_q, nullptr, 1.f, blockIdx.y, blockIdx.x);
    else if (blockIdx.z == 1)
        gemm_mma_tile(g_xh, g_wkTh, g_k, nullptr, 1.f, blockIdx.y, blockIdx.x);
    else
        gemm_mma_tile(g_xh, g_vwTh, nullptr, g_vsh, 1.f, blockIdx.y, blockIdx.x);
}

__global__ void __launch_bounds__(256) k_gemm_out(float* __restrict__ out,
                                                  const float* __restrict__ os)
{
    gemm_mma_tile(g_rh, g_owh, out, nullptr, __ldg(os), blockIdx.y, blockIdx.x);
}

// ===========================================================================
// k_prep: fused prep, long pole (weights GEMMs) first.
// ===========================================================================
#define PREP_W_BLKS   32
#define PREP_TR_BLKS  512
#define PREP_SPLIT_BLKS 4096
#define PREP_BLKS (PREP_W_BLKS + PREP_TR_BLKS + PREP_SPLIT_BLKS)

__global__ void __launch_bounds__(256) k_prep(
    const float* __restrict__ x, const float* __restrict__ wq,
    const float* __restrict__ wk, const float* __restrict__ basis,
    const float* __restrict__ vc, const float* __restrict__ oc)
{
    __shared__ __align__(16) float shmem[2 * 8 * 132];
    const int blk = blockIdx.x;
    const int tid = threadIdx.x;

    if (blk < PREP_W_BLKS) {
        float (*As)[132] = (float(*)[132])shmem;
        float (*Bs)[132] = (float(*)[132])(shmem + 8 * 132);
        const int z = blk >> 4;
        const int bx = blk & 3, by = (blk >> 2) & 3;
        const float* A = z ? basis : vc;
        const float* B = z ? oc : basis;
        __half* Oh = z ? g_owh : g_vwTh;
        const int tx = tid & 15, ty = tid >> 4;

        float acc[8][8];
#pragma unroll
        for (int i = 0; i < 8; i++)
#pragma unroll
            for (int j = 0; j < 8; j++) acc[i][j] = 0.f;

        const float* Ab = A + (size_t)(by * 128) * NBc;

        for (int k0 = 0; k0 < NBc; k0 += 8) {
            {
                const int ar = tid >> 1, ac = (tid & 1) * 4;
                float4 v = *(const float4*)(Ab + (size_t)ar * NBc + k0 + ac);
                As[ac + 0][ar] = v.x; As[ac + 1][ar] = v.y;
                As[ac + 2][ar] = v.z; As[ac + 3][ar] = v.w;
            }
            {
                const int br = tid >> 1, bc = (tid & 1) * 4;
                float4 v = *(const float4*)(B + (size_t)(bx * 128 + br) * NBc + k0 + bc);
                Bs[bc + 0][br] = v.x; Bs[bc + 1][br] = v.y;
                Bs[bc + 2][br] = v.z; Bs[bc + 3][br] = v.w;
            }
            __syncthreads();

#pragma unroll
            for (int kk = 0; kk < 8; kk++) {
                float a[8], bf[8];
                *(float4*)(a)     = *(const float4*)&As[kk][ty * 8];
                *(float4*)(a + 4) = *(const float4*)&As[kk][ty * 8 + 4];
                *(float4*)(bf)     = *(const float4*)&Bs[kk][tx * 8];
                *(float4*)(bf + 4) = *(const float4*)&Bs[kk][tx * 8 + 4];
#pragma unroll
                for (int i = 0; i < 8; i++)
#pragma unroll
                    for (int j = 0; j < 8; j++) acc[i][j] += a[i] * bf[j];
            }
            __syncthreads();
        }

#pragma unroll
        for (int i = 0; i < 8; i++) {
            const size_t rowb =
                (size_t)(by * 128 + ty * 8 + i) * 512 + bx * 128 + tx * 8;
#pragma unroll
            for (int j = 0; j < 8; j += 2) {
                __half2 p;
                p.x = __float2half_rn(acc[i][j]);
                p.y = __float2half_rn(acc[i][j + 1]);
                *(__half2*)(Oh + rowb + j) = p;
            }
        }
        return;
    }

    if (blk < PREP_W_BLKS + PREP_TR_BLKS) {
        float (*t)[33] = (float(*)[33])shmem;
        const int tb = blk - PREP_W_BLKS;
        const int z = tb >> 8;
        const int tile = tb & 255;
        const int bx = tile & 15, by = tile >> 4;
        const float* in = z ? wk : wq;
        __half* oh = z ? g_wkTh : g_wqTh;
        const int i = tid & 31, ty = tid >> 5;
#pragma unroll
        for (int r = 0; r < 4; r++) {
            const int j = ty + 8 * r;
            t[j][i] = in[(size_t)(by * 32 + j) * 512 + bx * 32 + i];
        }
        __syncthreads();
#pragma unroll
        for (int r = 0; r < 4; r++) {
            const int a = ty + 8 * r;
            oh[(size_t)(bx * 32 + a) * 512 + by * 32 + i] =
                __float2half_rn(t[i][a]);
        }
        return;
    }

    {
        const int i = (blk - PREP_W_BLKS - PREP_TR_BLKS) * 256 + tid;
        float4 v = ((const float4*)x)[i];
        __half2 p;
        p.x = __float2half_rn(v.x); p.y = __float2half_rn(v.y);
        ((__half2*)g_xh)[2 * i]     = p;
        p.x = __float2half_rn(v.z); p.y = __float2half_rn(v.w);
        ((__half2*)g_xh)[2 * i + 1] = p;
    }
}

// L2-normalize rows of g_q/g_k; both -> single fp16
__global__ void __launch_bounds__(256) k_norm()
{
    const int row = blockIdx.x;
    const float* q = g_q + (size_t)row * Cc;
    const float* k = g_k + (size_t)row * Cc;
    const int t = threadIdx.x;
    float q0 = q[t], q1 = q[t + 256];
    float k0 = k[t], k1 = k[t + 256];
    float sq = q0 * q0 + q1 * q1;
    float sk = k0 * k0 + k1 * k1;
#pragma unroll
    for (int off = 16; off; off >>= 1) {
        sq += __shfl_xor_sync(0xffffffffu, sq, off);
        sk += __shfl_xor_sync(0xffffffffu, sk, off);
    }
    __shared__ float rq[8], rk[8];
    __shared__ float inv[2];
    const int w = t >> 5, l = t & 31;
    if (l == 0) { rq[w] = sq; rk[w] = sk; }
    __syncthreads();
    if (t == 0) {
        float a = 0.f, cc = 0.f;
#pragma unroll
        for (int i = 0; i < 8; i++) { a += rq[i]; cc += rk[i]; }
        inv[0] = 1.f / fmaxf(sqrtf(a), 1e-12f);
        inv[1] = 1.f / fmaxf(sqrtf(cc), 1e-12f);
    }
    __syncthreads();
    const float iq = inv[0], ik = inv[1];
    const size_t b = (size_t)row * Cc;
    g_qnh[b + t]       = __float2half_rn(q0 * iq);
    g_qnh[b + t + 256] = __float2half_rn(q1 * iq);
    g_knh[b + t]       = __float2half_rn(k0 * ik);
    g_knh[b + t + 256] = __float2half_rn(k1 * ik);
}

// ===========================================================================
// Phase A: A^T_c[e][d] = sum_j V[j][e] * (d^j K[j][d]).
// Row-major staging (coalesced) + ldmatrix.trans fragments. fp16 output.
// ===========================================================================
#define ST_K  0
#define ST_V  17408
#define STATE_SMEM 34816

__global__ void __launch_bounds__(256) k_state(const float* __restrict__ dlog)
{
    extern __shared__ __align__(16) char sm[];
    const int c = blockIdx.x + 1, h = blockIdx.y, b = blockIdx.z;
    const int tid = threadIdx.x, lane = tid & 31, wid = tid >> 5;
    const float dec = 1.f / (1.f + expf(-dlog[h]));
    const float l2d = log2f(dec);
    const size_t gb = ((size_t)b * Tc + c * CHL) * Cc + h * Dc;

    // Row-major staging: K (decayed) and V, [j=64][128 halfs] pitch 272B.
#pragma unroll
    for (int i = 0; i < 4; i++) {
        const int idx = tid + 256 * i;        // 0..1023
        const int row = idx >> 4, q = idx & 15;
        const size_t src = gb + (size_t)row * Cc + q * 8;
        uint4 kq = *(const uint4*)(g_knh + src);
        uint4 vq = *(const uint4*)(g_vsh + src);
        const float e = exp2f(l2d * (float)row);
        const __half* pk = (const __half*)&kq;
        __half ko[8];
#pragma unroll
        for (int u = 0; u < 8; u++)
            ko[u] = __float2half_rn(__half2float(pk[u]) * e);
        *(uint4*)(sm + ST_K + row * 272 + q * 16) = *(uint4*)ko;
        *(uint4*)(sm + ST_V + row * 272 + q * 16) = vq;
    }
    __syncthreads();

    const int wm = wid >> 2, wn = wid & 3;
    const uint32_t sb = smem_u32(sm);
    // trans-ldmatrix lane terms
    const uint32_t aT_row = (lane & 7) + ((lane >> 4) << 3);        // j for A
    const uint32_t aT_col = ((lane >> 3) & 1) << 3;                 // e
    const uint32_t bT_row = (lane & 7) + (((lane >> 3) & 1) << 3);  // j for B
    const uint32_t bT_col = (lane >> 4) << 3;                       // d

    float acc[4][4][4];
#pragma unroll
    for (int i = 0; i < 4; i++)
#pragma unroll
        for (int j = 0; j < 4; j++)
#pragma unroll
            for (int q = 0; q < 4; q++) acc[i][j][q] = 0.f;

#pragma unroll
    for (int ks = 0; ks < 4; ks++) {
        const int j0 = ks * 16;
        uint32_t kh[8];
#pragma unroll
        for (int nf = 0; nf < 2; nf++) {
            const uint32_t d0 = wn * 32 + nf * 16;
            ldm_x4_t(kh + nf * 4,
                     sb + ST_K + (j0 + bT_row) * 272 + (d0 + bT_col) * 2);
        }
#pragma unroll
        for (int mi = 0; mi < 4; mi++) {
            const uint32_t e0 = wm * 64 + mi * 16;
            uint32_t vh[4];
            ldm_x4_t(vh, sb + ST_V + (j0 + aT_row) * 272 + (e0 + aT_col) * 2);
#pragma unroll
            for (int ni = 0; ni < 4; ni++)
                mma_f16(acc[mi][ni], vh, kh + ni * 2);
        }
    }

    __half* dst = g_stA16 + ((size_t)(b * Hc + h) * NCH + c) * (Dc * Dc);
    const int qr = lane >> 2, qc = lane & 3;
#pragma unroll
    for (int mi = 0; mi < 4; mi++) {
#pragma unroll
        for (int ni = 0; ni < 4; ni++) {
            const int m = wm * 64 + mi * 16 + qr;
            const int n = wn * 32 + ni * 8 + qc * 2;
            __half2 p;
            p.x = __float2half_rn(acc[mi][ni][0]);
            p.y = __float2half_rn(acc[mi][ni][1]);
            *(__half2*)(dst + (size_t)m * Dc + n) = p;
            p.x = __float2half_rn(acc[mi][ni][2]);
            p.y = __float2half_rn(acc[mi][ni][3]);
            *(__half2*)(dst + (size_t)(m + 8) * Dc + n) = p;
        }
    }
}

// ===========================================================================
// Phase B: backward scan on fp16 A^T, writes fp16 T^T. 8 halfs / thread.
// ===========================================================================
__global__ void __launch_bounds__(256) k_scan(const float* __restrict__ dlog)
{
    const int bh = blockIdx.x;
    const int h = bh & (Hc - 1);
    const int idx = blockIdx.y * 256 + threadIdx.x;   // 0..2047
    const float dec = 1.f / (1.f + expf(-dlog[h]));
    const float dL = exp2f(log2f(dec) * (float)CHL);

    float run[8];
#pragma unroll
    for (int u = 0; u < 8; u++) run[u] = 0.f;

    for (int c = NCH - 2; c >= 0; c--) {
        const uint4 av = *(const uint4*)(
            g_stA16 + ((size_t)bh * NCH + c + 1) * (Dc * Dc) + (size_t)idx * 8);
        const __half* pa = (const __half*)&av;
        __half ov[8];
#pragma unroll
        for (int u = 0; u < 8; u++) {
            run[u] = __half2float(pa[u]) + dL * run[u];
            ov[u] = __float2half_rn(run[u]);
        }
        *(uint4*)(g_sTh + ((size_t)bh * NCH + c) * (Dc * Dc) +
                  (size_t)idx * 8) = *(uint4*)ov;
    }
}

// ===========================================================================
// Phase C (MMA): all-single operands. V staged ROW-MAJOR + trans-ldmatrix.
// CQ 17408 | CK 17408 | CV(row-major 64x272) 17408 | CS 9216 | CT 34816
// => 96256 bytes, 2 CTAs/SM.
// ===========================================================================
#define CQ   0
#define CK   17408
#define CV   34816
#define CS   52224
#define CT   61440
#define CATTN_SMEM 96256

__global__ void __launch_bounds__(256) k_cattn(const float* __restrict__ dlog)
{
    extern __shared__ __align__(16) char sm[];
    const int c = blockIdx.x, h = blockIdx.y, b = blockIdx.z;
    const int tid = threadIdx.x, lane = tid & 31, wid = tid >> 5;
    const int wm = wid >> 2, wn = wid & 3;
    const float dec = 1.f / (1.f + expf(-dlog[h]));
    const float l2d = log2f(dec);
    const size_t gb = ((size_t)b * Tc + c * CHL) * Cc + h * Dc;
    const uint32_t sb = smem_u32(sm);

    // Prefetch full T^T (fp16) with cp.async
    if (c < NCH - 1) {
        const __half* Th = g_sTh + ((size_t)(b * Hc + h) * NCH + c) * (Dc * Dc);
#pragma unroll
        for (int i = 0; i < 8; i++) {
            const int idx = tid + 256 * i;           // 0..2047
            const int e = idx >> 4, q = idx & 15;
            cp16(sb + CT + e * 272 + q * 16, Th + (size_t)e * 128 + q * 8);
        }
    }
    cp_commit();

    // Q, K, V tiles 64x128 row-major, pitch 272B (all coalesced uint4)
    {
        const uint4* s0 = (const uint4*)(g_qnh + gb);
        const uint4* s2 = (const uint4*)(g_knh + gb);
        const uint4* s3 = (const uint4*)(g_vsh + gb);
#pragma unroll
        for (int i = 0; i < 4; i++) {
            const int idx = tid + 256 * i;
            const int row = idx >> 4, q = idx & 15;
            const size_t so = (size_t)row * 64 + q;
            const uint32_t doff = row * 272 + q * 16;
            *(uint4*)(sm + CQ + doff) = s0[so];
            *(uint4*)(sm + CK + doff) = s2[so];
            *(uint4*)(sm + CV + doff) = s3[so];
        }
    }
    __syncthreads();

    const uint32_t a_koff = (lane >> 4) * 8;
    const uint32_t b_koff = ((lane >> 3) & 1) * 8;
    const uint32_t aQ_row = wm * 32 + (lane & 15);
    const uint32_t bS_row = wn * 16 + (lane & 7) + ((lane >> 4) << 3);
    const uint32_t bT_row = (lane & 7) + (((lane >> 3) & 1) << 3);  // trans B
    const uint32_t bT_col = (lane >> 4) << 3;
    const uint32_t bO_row = wn * 32 + (lane & 7) + ((lane >> 4) << 3);
    const int qr = lane >> 2, qc = lane & 3;

    // ---- intra: S = Q K^T (K row-major [j][d]: B rows = j, non-trans) ----
    float accS[2][2][4];
#pragma unroll
    for (int i = 0; i < 2; i++)
#pragma unroll
        for (int j = 0; j < 2; j++)
#pragma unroll
            for (int q = 0; q < 4; q++) accS[i][j][q] = 0.f;

#pragma unroll
    for (int ks = 0; ks < 8; ks++) {
        const int k0 = ks * 16;
        uint32_t kh[4];
        const uint32_t boff = bS_row * 272 + (k0 + b_koff) * 2;
        ldm_x4(kh, sb + CK + boff);
#pragma unroll
        for (int mi = 0; mi < 2; mi++) {
            uint32_t qh[4];
            const uint32_t aoff = (aQ_row + mi * 16) * 272 + (k0 + a_koff) * 2;
            ldm_x4(qh, sb + CQ + aoff);
#pragma unroll
            for (int ni = 0; ni < 2; ni++)
                mma_f16(accS[mi][ni], qh, kh + ni * 2);
        }
    }

    // mask + store S (fp16, pitch 144B)
#pragma unroll
    for (int mi = 0; mi < 2; mi++) {
#pragma unroll
        for (int ni = 0; ni < 2; ni++) {
#pragma unroll
            for (int q = 0; q < 4; q++) {
                const int il = wm * 32 + mi * 16 + qr + (q >> 1) * 8;
                const int jl = wn * 16 + ni * 8 + qc * 2 + (q & 1);
                float s = 0.f;
                if (jl > il)
                    s = accS[mi][ni][q] * exp2f(l2d * (float)(jl - il - 1));
                *(__half*)(sm + CS + il * 144 + jl * 2) = __float2half_rn(s);
            }
        }
    }
    cp_wait<0>();
    __syncthreads();

    // ---- O accumulators ----
    float acc[2][4][4], accI[2][4][4];
#pragma unroll
    for (int i = 0; i < 2; i++)
#pragma unroll
        for (int j = 0; j < 4; j++)
#pragma unroll
            for (int q = 0; q < 4; q++) { acc[i][j][q] = 0.f; accI[i][j][q] = 0.f; }

    // intra SV: S (A, non-trans, pitch 144) x V^T (B via trans from [j][d])
#pragma unroll
    for (int ks = 0; ks < 4; ks++) {
        const int j0 = ks * 16;
        uint32_t vh[8];
#pragma unroll
        for (int nf = 0; nf < 2; nf++) {
            const uint32_t d0 = wn * 32 + nf * 16;
            ldm_x4_t(vh + nf * 4,
                     sb + CV + (j0 + bT_row) * 272 + (d0 + bT_col) * 2);
        }
#pragma unroll
        for (int mi = 0; mi < 2; mi++) {
            uint32_t sh[4];
            const uint32_t aoff = (aQ_row + mi * 16) * 144 + (j0 + a_koff) * 2;
            ldm_x4(sh, sb + CS + aoff);
#pragma unroll
            for (int ni = 0; ni < 4; ni++)
                mma_f16(acc[mi][ni], sh, vh + ni * 2);
        }
    }

    // inter: O_i += Q @ T^T (T^T row-major [e][d]: B rows = e, non-trans)
    if (c < NCH - 1) {
#pragma unroll
        for (int ks = 0; ks < 8; ks++) {
            const int k0 = ks * 16;
            uint32_t th[8];
#pragma unroll
            for (int nf = 0; nf < 2; nf++) {
                const uint32_t boff =
                    (bO_row + nf * 16) * 272 + (k0 + b_koff) * 2;
                ldm_x4(th + nf * 4, sb + CT + boff);
            }
#pragma unroll
            for (int mi = 0; mi < 2; mi++) {
                uint32_t qh[4];
                const uint32_t aoff =
                    (aQ_row + mi * 16) * 272 + (k0 + a_koff) * 2;
                ldm_x4(qh, sb + CQ + aoff);
#pragma unroll
                for (int ni = 0; ni < 4; ni++)
                    mma_f16(accI[mi][ni], qh, th + ni * 2);
            }
        }
    }

    // epilogue: O = acc + f(row) * accI -> fp16 write g_rh
#pragma unroll
    for (int mi = 0; mi < 2; mi++) {
        const int r0 = wm * 32 + mi * 16 + qr;
        const float f0 = exp2f(l2d * (float)(63 - r0));
        const float f1 = exp2f(l2d * (float)(63 - (r0 + 8)));
#pragma unroll
        for (int ni = 0; ni < 4; ni++) {
            const int col = wn * 32 + ni * 8 + qc * 2;
            const size_t a0 = gb + (size_t)r0 * Cc + col;
            const size_t a1 = gb + (size_t)(r0 + 8) * Cc + col;
            __half2 p;
            p.x = __float2half_rn(acc[mi][ni][0] + f0 * accI[mi][ni][0]);
            p.y = __float2half_rn(acc[mi][ni][1] + f0 * accI[mi][ni][1]);
            *(__half2*)(g_rh + a0) = p;
            p.x = __float2half_rn(acc[mi][ni][2] + f1 * accI[mi][ni][2]);
            p.y = __float2half_rn(acc[mi][ni][3] + f1 * accI[mi][ni][3]);
            *(__half2*)(g_rh + a1) = p;
        }
    }
}

extern "C" void kernel_launch(void* const* d_in, const int* in_sizes, int n_in,
                              void* d_out, int out_size)
{
    const float* x     = (const float*)d_in[0];
    const float* basis = (const float*)d_in[1];
    const float* wq    = (const float*)d_in[2];
    const float* wk    = (const float*)d_in[3];
    const float* vc    = (const float*)d_in[4];
    const float* oc    = (const float*)d_in[5];
    const float* dlog  = (const float*)d_in[6];
    const float* oscal = (const float*)d_in[7];
    float* out = (float*)d_out;

    (void)in_sizes; (void)n_in; (void)out_size;

    cudaFuncSetAttribute(k_state, cudaFuncAttributeMaxDynamicSharedMemorySize,
                         STATE_SMEM);
    cudaFuncSetAttribute(k_cattn, cudaFuncAttributeMaxDynamicSharedMemorySize,
                         CATTN_SMEM);
    cudaFuncSetAttribute(k_gemm_proj, cudaFuncAttributeMaxDynamicSharedMemorySize,
                         GS_BYTES);
    cudaFuncSetAttribute(k_gemm_out, cudaFuncAttributeMaxDynamicSharedMemorySize,
                         GS_BYTES);

    k_prep<<<PREP_BLKS, 256>>>(x, wq, wk, basis, vc, oc);

    k_gemm_proj<<<dim3(Cc / 128, MROWS / 128, 3), 256, GS_BYTES>>>();
    k_norm<<<MROWS, 256>>>();

    k_state<<<dim3(NCH - 1, Hc, Bc), 256, STATE_SMEM>>>(dlog);
    k_scan<<<dim3(16, 8), 256>>>(dlog);
    k_cattn<<<dim3(NCH, Hc, Bc), 256, CATTN_SMEM>>>(dlog);

    k_gemm_out<<<dim3(Vc / 128, MROWS / 128), 256, GS_BYTES>>>(out, oscal);
}

// round 17
// speedup vs baseline: 1.8537x; 1.1203x over previous
#include <cuda_runtime.h>
#include <cuda_fp16.h>
#include <cstdint>

// Problem constants
#define Bc 4
#define Tc 2048
#define Vc 512
#define Cc 512
#define Hc 4
#define Dc 128
#define NBc 128
#define MROWS (Bc*Tc)    // 8192
#define NCH 32
#define CHL 64

// fp16 scratch (all single precision operands)
__device__ __half g_stA16[(size_t)16*NCH*Dc*Dc];   // A^T fp16 per chunk
__device__ __half g_xh[MROWS*Cc];
__device__ __half g_rh[MROWS*Cc];
__device__ __half g_qnh[MROWS*Cc];
__device__ __half g_knh[MROWS*Cc];
__device__ __half g_vsh[MROWS*Cc];
__device__ __half g_wqTh[Cc*Vc];
__device__ __half g_wkTh[Cc*Vc];
__device__ __half g_vwTh[Cc*Vc];
__device__ __half g_owh[Vc*Cc];
__device__ __half g_sTh[(size_t)16*NCH*Dc*Dc];  // T^T fp16 [bh][c][e][d]

// ===========================================================================
// Helpers
// ===========================================================================
__device__ __forceinline__ uint32_t smem_u32(const void* p) {
    uint32_t a;
    asm("{ .reg .u64 t; cvta.to.shared.u64 t, %1; cvt.u32.u64 %0, t; }"
        : "=r"(a) : "l"(p));
    return a;
}
__device__ __forceinline__ void ldm_x4(uint32_t* r, uint32_t addr) {
    asm volatile("ldmatrix.sync.aligned.m8n8.x4.shared.b16 {%0,%1,%2,%3}, [%4];"
                 : "=r"(r[0]), "=r"(r[1]), "=r"(r[2]), "=r"(r[3]) : "r"(addr));
}
__device__ __forceinline__ void ldm_x4_t(uint32_t* r, uint32_t addr) {
    asm volatile(
        "ldmatrix.sync.aligned.m8n8.x4.trans.shared.b16 {%0,%1,%2,%3}, [%4];"
        : "=r"(r[0]), "=r"(r[1]), "=r"(r[2]), "=r"(r[3]) : "r"(addr));
}
__device__ __forceinline__ void mma_f16(float* c, const uint32_t* a,
                                        const uint32_t* b) {
    asm volatile(
        "mma.sync.aligned.m16n8k16.row.col.f32.f16.f16.f32 "
        "{%0,%1,%2,%3}, {%4,%5,%6,%7}, {%8,%9}, {%0,%1,%2,%3};"
        : "+f"(c[0]), "+f"(c[1]), "+f"(c[2]), "+f"(c[3])
        : "r"(a[0]), "r"(a[1]), "r"(a[2]), "r"(a[3]), "r"(b[0]), "r"(b[1]));
}
__device__ __forceinline__ void cp16(uint32_t dst, const void* src) {
    asm volatile("cp.async.cg.shared.global [%0], [%1], 16;"
                 :: "r"(dst), "l"(src));
}
__device__ __forceinline__ void cp_commit() {
    asm volatile("cp.async.commit_group;");
}
template <int N>
__device__ __forceinline__ void cp_wait() {
    asm volatile("cp.async.wait_group %0;" :: "n"(N));
}

// ===========================================================================
// 1-pass single-fp16 warp-MMA GEMM. K-slab 64, 3-stage pipeline, one sync
// per iteration. C[128,128] = A[M,512]@B[N,512]^T.
// ===========================================================================
#define GSLAB 18432                 // 128 rows * 144B
#define GBUF  (2 * GSLAB)           // 36864 (A, B)
#define GS_BYTES (3 * GBUF)         // 110592

__device__ __forceinline__ void gemm_mma_tile(
    const __half* __restrict__ Ah, const __half* __restrict__ Bh,
    float* __restrict__ Cp, __half* __restrict__ Oh,
    float alpha, int tm, int tn)
{
    extern __shared__ __align__(16) char smc[];
    const int tid = threadIdx.x, lane = tid & 31, wid = tid >> 5;
    const int wm = wid >> 2, wn = wid & 3;
    const uint32_t sb = smem_u32(smc);

    float acc[4][4][4];
#pragma unroll
    for (int i = 0; i < 4; i++)
#pragma unroll
        for (int j = 0; j < 4; j++)
#pragma unroll
            for (int q = 0; q < 4; q++) acc[i][j][q] = 0.f;

    const __half* bases[2];
    bases[0] = Ah + ((size_t)tm * 128) * 512;
    bases[1] = Bh + ((size_t)tn * 128) * 512;

    auto issue = [&](int c, int stage) {
        const uint32_t bb = sb + stage * GBUF;
#pragma unroll
        for (int s = 0; s < 2; s++) {
            const __half* src = bases[s] + c * 64;
#pragma unroll
            for (int i = 0; i < 4; i++) {
                const int idx = tid + 256 * i;
                const int row = idx >> 3, q = idx & 7;
                cp16(bb + s * GSLAB + row * 144 + q * 16,
                     src + (size_t)row * 512 + q * 8);
            }
        }
        cp_commit();
    };

    issue(0, 0);
    issue(1, 1);

    const uint32_t a_lrow = wm * 64 + (lane & 15);
    const uint32_t a_koff = (lane >> 4) * 8;
    const uint32_t b_lrow = wn * 32 + (lane & 7) + ((lane >> 4) << 3);
    const uint32_t b_koff = ((lane >> 3) & 1) * 8;

    int stage = 0;
    for (int c = 0; c < 8; c++) {
        if (c == 7) cp_wait<0>(); else cp_wait<1>();
        __syncthreads();
        const uint32_t bb = sb + stage * GBUF;

#pragma unroll
        for (int ks = 0; ks < 4; ks++) {
            const int k0 = ks * 16;
            uint32_t bh[8];
#pragma unroll
            for (int nf = 0; nf < 2; nf++) {
                const uint32_t boff =
                    (b_lrow + nf * 16) * 144 + (k0 + b_koff) * 2;
                ldm_x4(bh + nf * 4, bb + GSLAB + boff);
            }
#pragma unroll
            for (int mi = 0; mi < 4; mi++) {
                const uint32_t aoff =
                    (a_lrow + mi * 16) * 144 + (k0 + a_koff) * 2;
                uint32_t ah[4];
                ldm_x4(ah, bb + aoff);
#pragma unroll
                for (int ni = 0; ni < 4; ni++)
                    mma_f16(acc[mi][ni], ah, bh + ni * 2);
            }
        }
        if (c + 2 < 8) issue(c + 2, (c + 2) % 3);
        stage = (stage + 1) % 3;
    }

    const int qr = lane >> 2, qc = lane & 3;
#pragma unroll
    for (int mi = 0; mi < 4; mi++) {
#pragma unroll
        for (int ni = 0; ni < 4; ni++) {
            const int m = tm * 128 + wm * 64 + mi * 16 + qr;
            const int n = tn * 128 + wn * 32 + ni * 8 + qc * 2;
            float o0 = acc[mi][ni][0] * alpha, o1 = acc[mi][ni][1] * alpha;
            float o2 = acc[mi][ni][2] * alpha, o3 = acc[mi][ni][3] * alpha;
            if (Cp) {
                float2 v0, v1;
                v0.x = o0; v0.y = o1; v1.x = o2; v1.y = o3;
                *(float2*)(Cp + (size_t)m * 512 + n)       = v0;
                *(float2*)(Cp + (size_t)(m + 8) * 512 + n) = v1;
            } else {
                __half2 p;
                p.x = __float2half_rn(o0); p.y = __float2half_rn(o1);
                *(__half2*)(Oh + (size_t)m * 512 + n) = p;
                p.x = __float2half_rn(o2); p.y = __float2half_rn(o3);
                *(__half2*)(Oh + (size_t)(m + 8) * 512 + n) = p;
            }
        }
    }
}

__global__ void __launch_bounds__(256) k_gemm_proj()
{
    if (blockIdx.z == 0)
        gemm_mma_tile(g_xh, g_wqTh, nullptr, g_qnh, 1.f, blockIdx.y, blockIdx.x);
    else if (blockIdx.z == 1)
        gemm_mma_tile(g_xh, g_wkTh, nullptr, g_knh, 1.f, blockIdx.y, blockIdx.x);
    else
        gemm_mma_tile(g_xh, g_vwTh, nullptr, g_vsh, 1.f, blockIdx.y, blockIdx.x);
}

__global__ void __launch_bounds__(256) k_gemm_out(float* __restrict__ out,
                                                  const float* __restrict__ os)
{
    gemm_mma_tile(g_rh, g_owh, out, nullptr, __ldg(os), blockIdx.y, blockIdx.x);
}

// ===========================================================================
// k_prep: fused prep, long pole (weights GEMMs, now 64x64 tiles) first.
//  [0,128)      : weights GEMMs -> g_vwTh, g_owh   (64x64 tiles, fp32)
//  [128,640)    : transpose wq/wk -> fp16
//  [640,4736)   : x -> fp16
// ===========================================================================
#define PREP_W_BLKS   128
#define PREP_TR_BLKS  512
#define PREP_SPLIT_BLKS 4096
#define PREP_BLKS (PREP_W_BLKS + PREP_TR_BLKS + PREP_SPLIT_BLKS)

__global__ void __launch_bounds__(256) k_prep(
    const float* __restrict__ x, const float* __restrict__ wq,
    const float* __restrict__ wk, const float* __restrict__ basis,
    const float* __restrict__ vc, const float* __restrict__ oc)
{
    __shared__ __align__(16) float shmem[2 * 16 * 68];   // 8704B
    const int blk = blockIdx.x;
    const int tid = threadIdx.x;

    if (blk < PREP_W_BLKS) {
        // ---- weights GEMMs, 64x64 tile, K=128, k-slab 16 ----
        float (*As)[68] = (float(*)[68])shmem;
        float (*Bs)[68] = (float(*)[68])(shmem + 16 * 68);
        const int z = blk >> 6;                // 0: vwT, 1: ow
        const int t = blk & 63;
        const int bx = t & 7, by = t >> 3;
        const float* A = z ? basis : vc;
        const float* B = z ? oc : basis;
        __half* Oh = z ? g_owh : g_vwTh;
        const int tx = tid & 15, ty = tid >> 4;

        float acc[4][4];
#pragma unroll
        for (int i = 0; i < 4; i++)
#pragma unroll
            for (int j = 0; j < 4; j++) acc[i][j] = 0.f;

        const float* Ab = A + (size_t)(by * 64) * NBc;
        const float* Bb = B + (size_t)(bx * 64) * NBc;
        const int lrow = tid >> 2, kq = (tid & 3) * 4;

        for (int k0 = 0; k0 < NBc; k0 += 16) {
            float4 va = *(const float4*)(Ab + (size_t)lrow * NBc + k0 + kq);
            float4 vb = *(const float4*)(Bb + (size_t)lrow * NBc + k0 + kq);
            As[kq + 0][lrow] = va.x; As[kq + 1][lrow] = va.y;
            As[kq + 2][lrow] = va.z; As[kq + 3][lrow] = va.w;
            Bs[kq + 0][lrow] = vb.x; Bs[kq + 1][lrow] = vb.y;
            Bs[kq + 2][lrow] = vb.z; Bs[kq + 3][lrow] = vb.w;
            __syncthreads();
#pragma unroll
            for (int kk = 0; kk < 16; kk++) {
                float a[4], bf[4];
                *(float4*)a  = *(const float4*)&As[kk][ty * 4];
                *(float4*)bf = *(const float4*)&Bs[kk][tx * 4];
#pragma unroll
                for (int i = 0; i < 4; i++)
#pragma unroll
                    for (int j = 0; j < 4; j++) acc[i][j] += a[i] * bf[j];
            }
            __syncthreads();
        }

#pragma unroll
        for (int i = 0; i < 4; i++) {
            const size_t rowb =
                (size_t)(by * 64 + ty * 4 + i) * 512 + bx * 64 + tx * 4;
#pragma unroll
            for (int j = 0; j < 4; j += 2) {
                __half2 p;
                p.x = __float2half_rn(acc[i][j]);
                p.y = __float2half_rn(acc[i][j + 1]);
                *(__half2*)(Oh + rowb + j) = p;
            }
        }
        return;
    }

    if (blk < PREP_W_BLKS + PREP_TR_BLKS) {
        float (*tmat)[33] = (float(*)[33])shmem;
        const int tb = blk - PREP_W_BLKS;
        const int z = tb >> 8;
        const int tile = tb & 255;
        const int bx = tile & 15, by = tile >> 4;
        const float* in = z ? wk : wq;
        __half* oh = z ? g_wkTh : g_wqTh;
        const int i = tid & 31, ty = tid >> 5;
#pragma unroll
        for (int r = 0; r < 4; r++) {
            const int j = ty + 8 * r;
            tmat[j][i] = in[(size_t)(by * 32 + j) * 512 + bx * 32 + i];
        }
        __syncthreads();
#pragma unroll
        for (int r = 0; r < 4; r++) {
            const int a = ty + 8 * r;
            oh[(size_t)(bx * 32 + a) * 512 + by * 32 + i] =
                __float2half_rn(tmat[i][a]);
        }
        return;
    }

    {
        const int i = (blk - PREP_W_BLKS - PREP_TR_BLKS) * 256 + tid;
        float4 v = ((const float4*)x)[i];
        __half2 p;
        p.x = __float2half_rn(v.x); p.y = __float2half_rn(v.y);
        ((__half2*)g_xh)[2 * i]     = p;
        p.x = __float2half_rn(v.z); p.y = __float2half_rn(v.w);
        ((__half2*)g_xh)[2 * i + 1] = p;
    }
}

// L2-normalize rows of fp16 q/k IN PLACE (sumsq recomputed from fp16).
__global__ void __launch_bounds__(256) k_norm()
{
    const int row = blockIdx.x;
    const int t = threadIdx.x;
    __half2* qp = (__half2*)(g_qnh + (size_t)row * Cc);
    __half2* kp = (__half2*)(g_knh + (size_t)row * Cc);
    const __half2 qv = qp[t], kv = kp[t];
    const float2 qf = __half22float2(qv);
    const float2 kf = __half22float2(kv);
    float sq = qf.x * qf.x + qf.y * qf.y;
    float sk = kf.x * kf.x + kf.y * kf.y;
#pragma unroll
    for (int off = 16; off; off >>= 1) {
        sq += __shfl_xor_sync(0xffffffffu, sq, off);
        sk += __shfl_xor_sync(0xffffffffu, sk, off);
    }
    __shared__ float rq[8], rk[8];
    __shared__ float inv[2];
    const int w = t >> 5, l = t & 31;
    if (l == 0) { rq[w] = sq; rk[w] = sk; }
    __syncthreads();
    if (t == 0) {
        float a = 0.f, cc = 0.f;
#pragma unroll
        for (int i = 0; i < 8; i++) { a += rq[i]; cc += rk[i]; }
        inv[0] = 1.f / fmaxf(sqrtf(a), 1e-12f);
        inv[1] = 1.f / fmaxf(sqrtf(cc), 1e-12f);
    }
    __syncthreads();
    const float iq = inv[0], ik = inv[1];
    __half2 o;
    o.x = __float2half_rn(qf.x * iq); o.y = __float2half_rn(qf.y * iq);
    qp[t] = o;
    o.x = __float2half_rn(kf.x * ik); o.y = __float2half_rn(kf.y * ik);
    kp[t] = o;
}

// ===========================================================================
// Phase A: A^T_c[e][d] = sum_j V[j][e] * (d^j K[j][d]).
// V via cp.async; K decayed in ALU. Row-major staging + trans-ldmatrix.
// ===========================================================================
#define ST_K  0
#define ST_V  17408
#define STATE_SMEM 34816

__global__ void __launch_bounds__(256) k_state(const float* __restrict__ dlog)
{
    extern __shared__ __align__(16) char sm[];
    const int c = blockIdx.x + 1, h = blockIdx.y, b = blockIdx.z;
    const int tid = threadIdx.x, lane = tid & 31, wid = tid >> 5;
    const float dec = 1.f / (1.f + expf(-dlog[h]));
    const float l2d = log2f(dec);
    const size_t gb = ((size_t)b * Tc + c * CHL) * Cc + h * Dc;
    const uint32_t sb = smem_u32(sm);

    // V async
#pragma unroll
    for (int i = 0; i < 4; i++) {
        const int idx = tid + 256 * i;
        const int row = idx >> 4, q = idx & 15;
        cp16(sb + ST_V + row * 272 + q * 16, g_vsh + gb + (size_t)row * Cc + q * 8);
    }
    cp_commit();

    // K with decay (ALU overlaps V transfer)
#pragma unroll
    for (int i = 0; i < 4; i++) {
        const int idx = tid + 256 * i;
        const int row = idx >> 4, q = idx & 15;
        uint4 kq = *(const uint4*)(g_knh + gb + (size_t)row * Cc + q * 8);
        const float e = exp2f(l2d * (float)row);
        const __half* pk = (const __half*)&kq;
        __half ko[8];
#pragma unroll
        for (int u = 0; u < 8; u++)
            ko[u] = __float2half_rn(__half2float(pk[u]) * e);
        *(uint4*)(sm + ST_K + row * 272 + q * 16) = *(uint4*)ko;
    }
    cp_wait<0>();
    __syncthreads();

    const int wm = wid >> 2, wn = wid & 3;
    const uint32_t aT_row = (lane & 7) + ((lane >> 4) << 3);
    const uint32_t aT_col = ((lane >> 3) & 1) << 3;
    const uint32_t bT_row = (lane & 7) + (((lane >> 3) & 1) << 3);
    const uint32_t bT_col = (lane >> 4) << 3;

    float acc[4][4][4];
#pragma unroll
    for (int i = 0; i < 4; i++)
#pragma unroll
        for (int j = 0; j < 4; j++)
#pragma unroll
            for (int q = 0; q < 4; q++) acc[i][j][q] = 0.f;

#pragma unroll
    for (int ks = 0; ks < 4; ks++) {
        const int j0 = ks * 16;
        uint32_t kh[8];
#pragma unroll
        for (int nf = 0; nf < 2; nf++) {
            const uint32_t d0 = wn * 32 + nf * 16;
            ldm_x4_t(kh + nf * 4,
                     sb + ST_K + (j0 + bT_row) * 272 + (d0 + bT_col) * 2);
        }
#pragma unroll
        for (int mi = 0; mi < 4; mi++) {
            const uint32_t e0 = wm * 64 + mi * 16;
            uint32_t vh[4];
            ldm_x4_t(vh, sb + ST_V + (j0 + aT_row) * 272 + (e0 + aT_col) * 2);
#pragma unroll
            for (int ni = 0; ni < 4; ni++)
                mma_f16(acc[mi][ni], vh, kh + ni * 2);
        }
    }

    __half* dst = g_stA16 + ((size_t)(b * Hc + h) * NCH + c) * (Dc * Dc);
    const int qr = lane >> 2, qc = lane & 3;
#pragma unroll
    for (int mi = 0; mi < 4; mi++) {
#pragma unroll
        for (int ni = 0; ni < 4; ni++) {
            const int m = wm * 64 + mi * 16 + qr;
            const int n = wn * 32 + ni * 8 + qc * 2;
            __half2 p;
            p.x = __float2half_rn(acc[mi][ni][0]);
            p.y = __float2half_rn(acc[mi][ni][1]);
            *(__half2*)(dst + (size_t)m * Dc + n) = p;
            p.x = __float2half_rn(acc[mi][ni][2]);
            p.y = __float2half_rn(acc[mi][ni][3]);
            *(__half2*)(dst + (size_t)(m + 8) * Dc + n) = p;
        }
    }
}

// ===========================================================================
// Phase B: backward scan on fp16 A^T, writes fp16 T^T.
// ===========================================================================
__global__ void __launch_bounds__(256) k_scan(const float* __restrict__ dlog)
{
    const int bh = blockIdx.x;
    const int h = bh & (Hc - 1);
    const int idx = blockIdx.y * 256 + threadIdx.x;   // 0..2047
    const float dec = 1.f / (1.f + expf(-dlog[h]));
    const float dL = exp2f(log2f(dec) * (float)CHL);

    float run[8];
#pragma unroll
    for (int u = 0; u < 8; u++) run[u] = 0.f;

    for (int c = NCH - 2; c >= 0; c--) {
        const uint4 av = *(const uint4*)(
            g_stA16 + ((size_t)bh * NCH + c + 1) * (Dc * Dc) + (size_t)idx * 8);
        const __half* pa = (const __half*)&av;
        __half ov[8];
#pragma unroll
        for (int u = 0; u < 8; u++) {
            run[u] = __half2float(pa[u]) + dL * run[u];
            ov[u] = __float2half_rn(run[u]);
        }
        *(uint4*)(g_sTh + ((size_t)bh * NCH + c) * (Dc * Dc) +
                  (size_t)idx * 8) = *(uint4*)ov;
    }
}

// ===========================================================================
// Phase C (MMA): all cp.async staging. V row-major + trans-ldmatrix.
// CQ 17408 | CK 17408 | CV 17408 | CS 9216 | CT 34816 => 96256, 2 CTAs/SM.
// ===========================================================================
#define CQ   0
#define CK   17408
#define CV   34816
#define CS   52224
#define CT   61440
#define CATTN_SMEM 96256

__global__ void __launch_bounds__(256) k_cattn(const float* __restrict__ dlog)
{
    extern __shared__ __align__(16) char sm[];
    const int c = blockIdx.x, h = blockIdx.y, b = blockIdx.z;
    const int tid = threadIdx.x, lane = tid & 31, wid = tid >> 5;
    const int wm = wid >> 2, wn = wid & 3;
    const float dec = 1.f / (1.f + expf(-dlog[h]));
    const float l2d = log2f(dec);
    const size_t gb = ((size_t)b * Tc + c * CHL) * Cc + h * Dc;
    const uint32_t sb = smem_u32(sm);

    // Group 1: Q, K, V (all row-major pitch 272B)
#pragma unroll
    for (int i = 0; i < 4; i++) {
        const int idx = tid + 256 * i;
        const int row = idx >> 4, q = idx & 15;
        const size_t so = gb + (size_t)row * Cc + q * 8;
        const uint32_t doff = row * 272 + q * 16;
        cp16(sb + CQ + doff, g_qnh + so);
        cp16(sb + CK + doff, g_knh + so);
        cp16(sb + CV + doff, g_vsh + so);
    }
    cp_commit();

    // Group 2: T^T
    if (c < NCH - 1) {
        const __half* Th = g_sTh + ((size_t)(b * Hc + h) * NCH + c) * (Dc * Dc);
#pragma unroll
        for (int i = 0; i < 8; i++) {
            const int idx = tid + 256 * i;
            const int e = idx >> 4, q = idx & 15;
            cp16(sb + CT + e * 272 + q * 16, Th + (size_t)e * 128 + q * 8);
        }
    }
    cp_commit();

    cp_wait<1>();    // Q/K/V ready (T may still be in flight)
    __syncthreads();

    const uint32_t a_koff = (lane >> 4) * 8;
    const uint32_t b_koff = ((lane >> 3) & 1) * 8;
    const uint32_t aQ_row = wm * 32 + (lane & 15);
    const uint32_t bS_row = wn * 16 + (lane & 7) + ((lane >> 4) << 3);
    const uint32_t bT_row = (lane & 7) + (((lane >> 3) & 1) << 3);
    const uint32_t bT_col = (lane >> 4) << 3;
    const uint32_t bO_row = wn * 32 + (lane & 7) + ((lane >> 4) << 3);
    const int qr = lane >> 2, qc = lane & 3;

    // ---- intra: S = Q K^T ----
    float accS[2][2][4];
#pragma unroll
    for (int i = 0; i < 2; i++)
#pragma unroll
        for (int j = 0; j < 2; j++)
#pragma unroll
            for (int q = 0; q < 4; q++) accS[i][j][q] = 0.f;

#pragma unroll
    for (int ks = 0; ks < 8; ks++) {
        const int k0 = ks * 16;
        uint32_t kh[4];
        const uint32_t boff = bS_row * 272 + (k0 + b_koff) * 2;
        ldm_x4(kh, sb + CK + boff);
#pragma unroll
        for (int mi = 0; mi < 2; mi++) {
            uint32_t qh[4];
            const uint32_t aoff = (aQ_row + mi * 16) * 272 + (k0 + a_koff) * 2;
            ldm_x4(qh, sb + CQ + aoff);
#pragma unroll
            for (int ni = 0; ni < 2; ni++)
                mma_f16(accS[mi][ni], qh, kh + ni * 2);
        }
    }

    // mask + store S (fp16, pitch 144B)
#pragma unroll
    for (int mi = 0; mi < 2; mi++) {
#pragma unroll
        for (int ni = 0; ni < 2; ni++) {
#pragma unroll
            for (int q = 0; q < 4; q++) {
                const int il = wm * 32 + mi * 16 + qr + (q >> 1) * 8;
                const int jl = wn * 16 + ni * 8 + qc * 2 + (q & 1);
                float s = 0.f;
                if (jl > il)
                    s = accS[mi][ni][q] * exp2f(l2d * (float)(jl - il - 1));
                *(__half*)(sm + CS + il * 144 + jl * 2) = __float2half_rn(s);
            }
        }
    }
    cp_wait<0>();
    __syncthreads();

    // ---- O accumulators ----
    float acc[2][4][4], accI[2][4][4];
#pragma unroll
    for (int i = 0; i < 2; i++)
#pragma unroll
        for (int j = 0; j < 4; j++)
#pragma unroll
            for (int q = 0; q < 4; q++) { acc[i][j][q] = 0.f; accI[i][j][q] = 0.f; }

    // intra SV: S (A, pitch 144) x V^T (trans-B from [j][d])
#pragma unroll
    for (int ks = 0; ks < 4; ks++) {
        const int j0 = ks * 16;
        uint32_t vh[8];
#pragma unroll
        for (int nf = 0; nf < 2; nf++) {
            const uint32_t d0 = wn * 32 + nf * 16;
            ldm_x4_t(vh + nf * 4,
                     sb + CV + (j0 + bT_row) * 272 + (d0 + bT_col) * 2);
        }
#pragma unroll
        for (int mi = 0; mi < 2; mi++) {
            uint32_t sh[4];
            const uint32_t aoff = (aQ_row + mi * 16) * 144 + (j0 + a_koff) * 2;
            ldm_x4(sh, sb + CS + aoff);
#pragma unroll
            for (int ni = 0; ni < 4; ni++)
                mma_f16(acc[mi][ni], sh, vh + ni * 2);
        }
    }

    // inter: O_i += Q @ T^T (T^T row-major [e][d], non-trans B)
    if (c < NCH - 1) {
#pragma unroll
        for (int ks = 0; ks < 8; ks++) {
            const int k0 = ks * 16;
            uint32_t th[8];
#pragma unroll
            for (int nf = 0; nf < 2; nf++) {
                const uint32_t boff =
                    (bO_row + nf * 16) * 272 + (k0 + b_koff) * 2;
                ldm_x4(th + nf * 4, sb + CT + boff);
            }
#pragma unroll
            for (int mi = 0; mi < 2; mi++) {
                uint32_t qh[4];
                const uint32_t aoff =
                    (aQ_row + mi * 16) * 272 + (k0 + a_koff) * 2;
                ldm_x4(qh, sb + CQ + aoff);
#pragma unroll
                for (int ni = 0; ni < 4; ni++)
                    mma_f16(accI[mi][ni], qh, th + ni * 2);
            }
        }
    }

    // epilogue: O = acc + f(row) * accI -> fp16 write g_rh
#pragma unroll
    for (int mi = 0; mi < 2; mi++) {
        const int r0 = wm * 32 + mi * 16 + qr;
        const float f0 = exp2f(l2d * (float)(63 - r0));
        const float f1 = exp2f(l2d * (float)(63 - (r0 + 8)));
#pragma unroll
        for (int ni = 0; ni < 4; ni++) {
            const int col = wn * 32 + ni * 8 + qc * 2;
            const size_t a0 = gb + (size_t)r0 * Cc + col;
            const size_t a1 = gb + (size_t)(r0 + 8) * Cc + col;
            __half2 p;
            p.x = __float2half_rn(acc[mi][ni][0] + f0 * accI[mi][ni][0]);
            p.y = __float2half_rn(acc[mi][ni][1] + f0 * accI[mi][ni][1]);
            *(__half2*)(g_rh + a0) = p;
            p.x = __float2half_rn(acc[mi][ni][2] + f1 * accI[mi][ni][2]);
            p.y = __float2half_rn(acc[mi][ni][3] + f1 * accI[mi][ni][3]);
            *(__half2*)(g_rh + a1) = p;
        }
    }
}

extern "C" void kernel_launch(void* const* d_in, const int* in_sizes, int n_in,
                              void* d_out, int out_size)
{
    const float* x     = (const float*)d_in[0];
    const float* basis = (const float*)d_in[1];
    const float* wq    = (const float*)d_in[2];
    const float* wk    = (const float*)d_in[3];
    const float* vc    = (const float*)d_in[4];
    const float* oc    = (const float*)d_in[5];
    const float* dlog  = (const float*)d_in[6];
    const float* oscal = (const float*)d_in[7];
    float* out = (float*)d_out;

    (void)in_sizes; (void)n_in; (void)out_size;

    cudaFuncSetAttribute(k_state, cudaFuncAttributeMaxDynamicSharedMemorySize,
                         STATE_SMEM);
    cudaFuncSetAttribute(k_cattn, cudaFuncAttributeMaxDynamicSharedMemorySize,
                         CATTN_SMEM);
    cudaFuncSetAttribute(k_gemm_proj, cudaFuncAttributeMaxDynamicSharedMemorySize,
                         GS_BYTES);
    cudaFuncSetAttribute(k_gemm_out, cudaFuncAttributeMaxDynamicSharedMemorySize,
                         GS_BYTES);

    k_prep<<<PREP_BLKS, 256>>>(x, wq, wk, basis, vc, oc);

    k_gemm_proj<<<dim3(Cc / 128, MROWS / 128, 3), 256, GS_BYTES>>>();
    k_norm<<<MROWS, 256>>>();

    k_state<<<dim3(NCH - 1, Hc, Bc), 256, STATE_SMEM>>>(dlog);
    k_scan<<<dim3(16, 8), 256>>>(dlog);
    k_cattn<<<dim3(NCH, Hc, Bc), 256, CATTN_SMEM>>>(dlog);

    k_gemm_out<<<dim3(Vc / 128, MROWS / 128), 256, GS_BYTES>>>(out, oscal);
}